// round 6
// baseline (speedup 1.0000x reference)
#include <cuda_runtime.h>
#include <math.h>

#define En 8
#define Bn 16
#define Cn 128
#define Hn 64
#define Wn 64
#define HWn 4096
#define HCn 512
#define OHWn 1024

// ---------------- scratch (device globals; no allocation) ----------------
__device__ float g_y[(size_t)En * Bn * Cn * HWn];      // 268 MB expert conv raw
__device__ unsigned g_combt[(size_t)Bn * Cn * HWn];    // combined, tf32 bits
__device__ float g_h1[(size_t)Bn * HCn * HWn];         // 134 MB pw1 raw
__device__ float g_h2[(size_t)Bn * HCn * HWn];         // 134 MB dw raw
__device__ float g_o[(size_t)Bn * Cn * OHWn];          // 8.4 MB pw2 raw
__device__ unsigned g_wt[(size_t)En * 16 * 9 * 8 * 128];   // expert W tf32, staging order
__device__ unsigned g_w1t[(size_t)4 * 16 * 8 * 128];       // pw1 W tf32, staging order
__device__ unsigned g_xt[(size_t)Bn * Cn * HWn];           // x as tf32 bits
__device__ float g_estats[En * Bn * 8 * 2];
__device__ float g_eca[En * Bn * Cn];
__device__ float g_ecb[En * Bn * Cn];
__device__ float g_wts[16][En];
__device__ float g_s1[Bn * 8 * 2];
__device__ float g_c1a[Bn * HCn];
__device__ float g_c1b[Bn * HCn];
__device__ float g_s2[Bn * 8 * 2];
__device__ float g_c2a[Bn * HCn];
__device__ float g_c2b[Bn * HCn];
__device__ float g_s3[Bn * 8 * 2];
__device__ float g_c3a[Bn * Cn];
__device__ float g_c3b[Bn * Cn];

__device__ __forceinline__ float silu_f(float v) { return v / (1.f + __expf(-v)); }

__device__ __forceinline__ unsigned to_tf32(float f) {
    unsigned r;
    asm("cvt.rna.tf32.f32 %0, %1;" : "=r"(r) : "f"(f));
    return r;
}

__device__ __forceinline__ void mma_tf32(float& c0, float& c1, float& c2, float& c3,
                                         unsigned a0, unsigned a1, unsigned a2, unsigned a3,
                                         unsigned b0, unsigned b1) {
    asm volatile(
        "mma.sync.aligned.m16n8k8.row.col.f32.tf32.tf32.f32 "
        "{%0,%1,%2,%3}, {%4,%5,%6,%7}, {%8,%9}, {%0,%1,%2,%3};"
        : "+f"(c0), "+f"(c1), "+f"(c2), "+f"(c3)
        : "r"(a0), "r"(a1), "r"(a2), "r"(a3), "r"(b0), "r"(b1));
}

// ---------------- K0: zero the stats accumulators ----------------
__global__ void k_zero() {
    int i = blockIdx.x * 256 + threadIdx.x;
    if (i < En * Bn * 8 * 2) g_estats[i] = 0.f;
    if (i < Bn * 8 * 2) { g_s1[i] = 0.f; g_s2[i] = 0.f; g_s3[i] = 0.f; }
}

// ---------------- W prep (expert): [e][cc][tap][ci][co] tf32 bits ----------------
__global__ void k_wprep(const float* __restrict__ w_exp) {
    int i = blockIdx.x * 256 + threadIdx.x;
    if (i >= En * 16 * 9 * 8 * 128) return;
    int co = i & 127;
    int r = i >> 7;
    int ci = r & 7; r >>= 3;
    int tap = r % 9; r /= 9;
    int cc = r & 15;
    int e = r >> 4;
    g_wt[i] = to_tf32(w_exp[((size_t)(e * 128 + co) * 128 + cc * 8 + ci) * 9 + tap]);
}

// ---------------- W prep (pw1): [hcblk][cc][ci][hc128] tf32 bits ----------------
__global__ void k_w1prep(const float* __restrict__ w_pw1) {
    int i = blockIdx.x * 256 + threadIdx.x;
    if (i >= 4 * 16 * 8 * 128) return;
    int hcl = i & 127;
    int ci = (i >> 7) & 7;
    int cc = (i >> 10) & 15;
    int blk = i >> 14;
    int hc = blk * 128 + hcl;
    g_w1t[i] = to_tf32(w_pw1[(size_t)hc * 128 + cc * 8 + ci]);
}

// ---------------- X prep: tf32 bits, same NCHW layout ----------------
__global__ void k_xprep(const float* __restrict__ x) {
    int i = blockIdx.x * 256 + threadIdx.x;
    g_xt[i] = to_tf32(x[i]);
}

// ---------------- K1: expert 3x3 conv via tf32 mma + GN stats ----------------
// block: one (e,b), 128 co, 4 image rows (256 px). 16 warps = 4 co-groups x 4 rows.
// warp: 32 co x 64 px (one image row). Dynamic smem 51840 B.
__global__ __launch_bounds__(512, 1) void k_expert() {
    extern __shared__ unsigned sm[];
    unsigned* ws = sm;                       // [9][8][136] = 9792 words
    unsigned* xs = sm + 9792;                // [8][6][66]  = 3168 words

    const int ty0 = blockIdx.x * 4;          // 16 tiles of 4 rows
    const int e = blockIdx.z >> 4;
    const int b = blockIdx.z & 15;

    const int tid = threadIdx.x;
    const int warp = tid >> 5;
    const int lane = tid & 31;
    const int wc = warp >> 2;                // co group (32 co)
    const int wp = warp & 3;                 // image row within 4-row strip
    const int grp = lane >> 2;
    const int tig = lane & 3;

    float acc[2][8][4];
    #pragma unroll
    for (int mt = 0; mt < 2; mt++)
        #pragma unroll
        for (int nt = 0; nt < 8; nt++)
            #pragma unroll
            for (int q = 0; q < 4; q++) acc[mt][nt][q] = 0.f;

    const unsigned* wt = g_wt + (size_t)e * 147456;
    const unsigned* xt = g_xt + (size_t)b * Cn * HWn;

    for (int cc = 0; cc < 16; cc++) {
        // stage W: 9216 contiguous words -> padded smem
        {
            const uint4* src = (const uint4*)(wt + cc * 9216);
            for (int idx = tid; idx < 2304; idx += 512) {
                int tc = idx >> 5, w4 = idx & 31;
                *(uint4*)(ws + tc * 136 + w4 * 4) = src[idx];
            }
        }
        // stage X halo: 8 ci x 6 rows x 66 cols
        for (int idx = tid; idx < 3168; idx += 512) {
            int ci = idx / 396;
            int rem = idx - ci * 396;
            int row = rem / 66;
            int cx = rem - row * 66;
            int gy = ty0 - 1 + row, gx = cx - 1;
            unsigned v = 0u;
            if ((unsigned)gy < 64u && (unsigned)gx < 64u)
                v = xt[(size_t)(cc * 8 + ci) * HWn + gy * 64 + gx];
            xs[(ci * 6 + row) * 66 + cx] = v;
        }
        __syncthreads();

        #pragma unroll
        for (int tap = 0; tap < 9; tap++) {
            const int kh = tap / 3, kw = tap % 3;
            unsigned a0[2], a1[2], a2[2], a3[2];
            #pragma unroll
            for (int mt = 0; mt < 2; mt++) {
                int co_r = wc * 32 + mt * 16 + grp;
                a0[mt] = ws[(tap * 8 + tig) * 136 + co_r];
                a1[mt] = ws[(tap * 8 + tig) * 136 + co_r + 8];
                a2[mt] = ws[(tap * 8 + tig + 4) * 136 + co_r];
                a3[mt] = ws[(tap * 8 + tig + 4) * 136 + co_r + 8];
            }
            #pragma unroll
            for (int nt = 0; nt < 8; nt++) {
                int col = nt * 8 + grp + kw;
                unsigned b0 = xs[(tig * 6 + wp + kh) * 66 + col];
                unsigned b1 = xs[((tig + 4) * 6 + wp + kh) * 66 + col];
                mma_tf32(acc[0][nt][0], acc[0][nt][1], acc[0][nt][2], acc[0][nt][3],
                         a0[0], a1[0], a2[0], a3[0], b0, b1);
                mma_tf32(acc[1][nt][0], acc[1][nt][1], acc[1][nt][2], acc[1][nt][3],
                         a0[1], a1[1], a2[1], a3[1], b0, b1);
            }
        }
        __syncthreads();
    }

    // epilogue: write y + per-warp GN group stats
    size_t ybase = (size_t)(e * Bn + b) * Cn * HWn;
    const int row = ty0 + wp;
    float ls[2] = {0.f, 0.f}, lq[2] = {0.f, 0.f};
    #pragma unroll
    for (int mt = 0; mt < 2; mt++) {
        int co = wc * 32 + mt * 16 + grp;
        #pragma unroll
        for (int nt = 0; nt < 8; nt++) {
            int colx = nt * 8 + 2 * tig;
            float2 v0 = make_float2(acc[mt][nt][0], acc[mt][nt][1]);
            float2 v1 = make_float2(acc[mt][nt][2], acc[mt][nt][3]);
            *(float2*)(g_y + ybase + (size_t)co * HWn + row * 64 + colx) = v0;
            *(float2*)(g_y + ybase + (size_t)(co + 8) * HWn + row * 64 + colx) = v1;
            ls[mt] += v0.x + v0.y + v1.x + v1.y;
            lq[mt] += v0.x * v0.x + v0.y * v0.y + v1.x * v1.x + v1.y * v1.y;
        }
    }
    #pragma unroll
    for (int mt = 0; mt < 2; mt++) {
        float s = ls[mt], q = lq[mt];
        #pragma unroll
        for (int off = 16; off > 0; off >>= 1) {
            s += __shfl_xor_sync(0xFFFFFFFFu, s, off);
            q += __shfl_xor_sync(0xFFFFFFFFu, q, off);
        }
        if (lane == 0) {
            int g = 2 * wc + mt;
            atomicAdd(&g_estats[((e * Bn + b) * 8 + g) * 2], s);
            atomicAdd(&g_estats[((e * Bn + b) * 8 + g) * 2 + 1], q);
        }
    }
}

// ---------------- K2: finalize expert GN coefs + router softmax ----------------
__global__ void k_router_fin(const float* __restrict__ gns, const float* __restrict__ gnb,
                             const float* __restrict__ w1, const float* __restrict__ b1,
                             const float* __restrict__ w2, const float* __restrict__ b2) {
    int tid = threadIdx.x;
    for (int i = tid; i < En * Bn * Cn; i += 256) {
        int e = i >> 11, b = (i >> 7) & 15, c = i & 127, g = c >> 4;
        float s = g_estats[((e * Bn + b) * 8 + g) * 2];
        float sq = g_estats[((e * Bn + b) * 8 + g) * 2 + 1];
        float mean = s * (1.f / 65536.f);
        float var = sq * (1.f / 65536.f) - mean * mean;
        float rstd = rsqrtf(var + 1e-5f);
        float a = rstd * gns[e * Cn + c];
        g_eca[i] = a;
        g_ecb[i] = gnb[e * Cn + c] - mean * a;
    }
    if (tid < 16) {
        int py = tid >> 2, px = tid & 3;
        float fe[32];
        float cy = (py + 0.5f) * 0.25f, cx = (px + 0.5f) * 0.25f;
        #pragma unroll
        for (int k = 0; k < 8; k++) {
            float fr = (float)(1 << k) * 3.14159265358979323846f;
            fe[k] = sinf(cy * fr);
            fe[8 + k] = cosf(cy * fr);
            fe[16 + k] = sinf(cx * fr);
            fe[24 + k] = cosf(cx * fr);
        }
        float hb[64];
        for (int j = 0; j < 64; j++) {
            float s = b1[j];
            for (int k = 0; k < 32; k++) s = fmaf(fe[k], w1[k * 64 + j], s);
            hb[j] = s / (1.f + expf(-s));
        }
        float lo[8];
        float mx = -1e30f;
        for (int ee = 0; ee < 8; ee++) {
            float s = b2[ee];
            for (int j = 0; j < 64; j++) s = fmaf(hb[j], w2[j * 8 + ee], s);
            lo[ee] = s;
            mx = fmaxf(mx, s);
        }
        float den = 0.f;
        for (int ee = 0; ee < 8; ee++) { lo[ee] = expf(lo[ee] - mx); den += lo[ee]; }
        float inv = 1.f / den;
        for (int ee = 0; ee < 8; ee++) g_wts[tid][ee] = lo[ee] * inv;
    }
}

// ---------------- K3: combine experts -> tf32 bits ----------------
__global__ void k_combine(const float* __restrict__ x) {
    size_t t = (size_t)blockIdx.x * 256 + threadIdx.x;
    size_t i = t * 4;
    int b = (int)(i >> 19);
    int c = (int)(i >> 12) & 127;
    int p = (int)(i & 4095);
    int patch = ((p >> 6) >> 4) * 4 + ((p & 63) >> 4);
    float4 outv = *(const float4*)(x + i);
    #pragma unroll
    for (int e = 0; e < 8; e++) {
        int ebc = (e * Bn + b) * Cn + c;
        float a = g_eca[ebc], bb = g_ecb[ebc];
        float wt = g_wts[patch][e];
        float4 y = *(const float4*)(g_y + (size_t)ebc * HWn + p);
        outv.x += wt * silu_f(fmaf(y.x, a, bb));
        outv.y += wt * silu_f(fmaf(y.y, a, bb));
        outv.z += wt * silu_f(fmaf(y.z, a, bb));
        outv.w += wt * silu_f(fmaf(y.w, a, bb));
    }
    uint4 o;
    o.x = to_tf32(outv.x);
    o.y = to_tf32(outv.y);
    o.z = to_tf32(outv.z);
    o.w = to_tf32(outv.w);
    *(uint4*)(g_combt + i) = o;
}

// ---------------- K4: pw1 1x1 conv (128->512) via tf32 mma + gn1 stats ----------------
// block: 128 hc x 128 px for one b. 8 warps = 4 hc-groups x 2 px-halves.
__global__ __launch_bounds__(256) void k_pw1m() {
    __shared__ unsigned As[8 * 136];
    __shared__ unsigned Bs[8 * 136];
    const int pxb = blockIdx.x * 128;
    const int hcb = blockIdx.y * 128;
    const int b = blockIdx.z;
    const int tid = threadIdx.x;
    const int warp = tid >> 5;
    const int lane = tid & 31;
    const int wc = warp >> 1;               // hc group (32)
    const int wpx = warp & 1;               // px half (64)
    const int grp = lane >> 2;
    const int tig = lane & 3;

    float acc[2][8][4];
    #pragma unroll
    for (int mt = 0; mt < 2; mt++)
        #pragma unroll
        for (int nt = 0; nt < 8; nt++)
            #pragma unroll
            for (int q = 0; q < 4; q++) acc[mt][nt][q] = 0.f;

    for (int cc = 0; cc < 16; cc++) {
        {
            const uint4* srcA = (const uint4*)(g_w1t + (size_t)((blockIdx.y * 16 + cc) * 8) * 128);
            uint4 v = srcA[tid];
            *(uint4*)(As + (tid >> 5) * 136 + (tid & 31) * 4) = v;
        }
        {
            int r = tid >> 5;
            const uint4* srcB = (const uint4*)(g_combt + (size_t)(b * Cn + cc * 8 + r) * HWn + pxb);
            uint4 v = srcB[tid & 31];
            *(uint4*)(Bs + r * 136 + (tid & 31) * 4) = v;
        }
        __syncthreads();

        unsigned a0[2], a1[2], a2[2], a3[2];
        #pragma unroll
        for (int mt = 0; mt < 2; mt++) {
            int hc_r = wc * 32 + mt * 16 + grp;
            a0[mt] = As[tig * 136 + hc_r];
            a1[mt] = As[tig * 136 + hc_r + 8];
            a2[mt] = As[(tig + 4) * 136 + hc_r];
            a3[mt] = As[(tig + 4) * 136 + hc_r + 8];
        }
        #pragma unroll
        for (int nt = 0; nt < 8; nt++) {
            int col = wpx * 64 + nt * 8 + grp;
            unsigned b0 = Bs[tig * 136 + col];
            unsigned b1 = Bs[(tig + 4) * 136 + col];
            mma_tf32(acc[0][nt][0], acc[0][nt][1], acc[0][nt][2], acc[0][nt][3],
                     a0[0], a1[0], a2[0], a3[0], b0, b1);
            mma_tf32(acc[1][nt][0], acc[1][nt][1], acc[1][nt][2], acc[1][nt][3],
                     a0[1], a1[1], a2[1], a3[1], b0, b1);
        }
        __syncthreads();
    }

    // epilogue: write h1 + gn1 stats (groups of 64 channels)
    #pragma unroll
    for (int mt = 0; mt < 2; mt++) {
        int hc0 = hcb + wc * 32 + mt * 16 + grp;
        float ls = 0.f, lq = 0.f;
        #pragma unroll
        for (int nt = 0; nt < 8; nt++) {
            int px = pxb + wpx * 64 + nt * 8 + 2 * tig;
            float2 v0 = make_float2(acc[mt][nt][0], acc[mt][nt][1]);
            float2 v1 = make_float2(acc[mt][nt][2], acc[mt][nt][3]);
            *(float2*)(g_h1 + (size_t)(b * HCn + hc0) * HWn + px) = v0;
            *(float2*)(g_h1 + (size_t)(b * HCn + hc0 + 8) * HWn + px) = v1;
            ls += v0.x + v0.y + v1.x + v1.y;
            lq += v0.x * v0.x + v0.y * v0.y + v1.x * v1.x + v1.y * v1.y;
        }
        #pragma unroll
        for (int off = 16; off > 0; off >>= 1) {
            ls += __shfl_xor_sync(0xFFFFFFFFu, ls, off);
            lq += __shfl_xor_sync(0xFFFFFFFFu, lq, off);
        }
        if (lane == 0) {
            int g = (hcb >> 6) + (wc >> 1);
            atomicAdd(&g_s1[(b * 8 + g) * 2], ls);
            atomicAdd(&g_s1[(b * 8 + g) * 2 + 1], lq);
        }
    }
}

// ---------------- finalize kernels ----------------
__global__ void k_fin1(const float* __restrict__ s, const float* __restrict__ bias) {
    int i = blockIdx.x * 256 + threadIdx.x;
    if (i >= Bn * HCn) return;
    int b = i / HCn, c = i % HCn, g = c >> 6;
    float su = g_s1[(b * 8 + g) * 2], sq = g_s1[(b * 8 + g) * 2 + 1];
    float mean = su * (1.f / 262144.f);
    float var = sq * (1.f / 262144.f) - mean * mean;
    float rstd = rsqrtf(var + 1e-5f);
    float a = rstd * s[c];
    g_c1a[i] = a;
    g_c1b[i] = bias[c] - mean * a;
}
__global__ void k_fin2(const float* __restrict__ s, const float* __restrict__ bias) {
    int i = blockIdx.x * 256 + threadIdx.x;
    if (i >= Bn * HCn) return;
    int b = i / HCn, c = i % HCn, g = c >> 6;
    float su = g_s2[(b * 8 + g) * 2], sq = g_s2[(b * 8 + g) * 2 + 1];
    float mean = su * (1.f / 262144.f);
    float var = sq * (1.f / 262144.f) - mean * mean;
    float rstd = rsqrtf(var + 1e-5f);
    float a = rstd * s[c];
    g_c2a[i] = a;
    g_c2b[i] = bias[c] - mean * a;
}
__global__ void k_fin3(const float* __restrict__ s, const float* __restrict__ bias) {
    int i = blockIdx.x * 256 + threadIdx.x;
    if (i >= Bn * Cn) return;
    int b = i / Cn, c = i % Cn, g = c >> 4;
    float su = g_s3[(b * 8 + g) * 2], sq = g_s3[(b * 8 + g) * 2 + 1];
    float mean = su * (1.f / 16384.f);
    float var = sq * (1.f / 16384.f) - mean * mean;
    float rstd = rsqrtf(var + 1e-5f);
    float a = rstd * s[c];
    g_c3a[i] = a;
    g_c3b[i] = bias[c] - mean * a;
}

// ---------------- K5: depthwise 3x3 on silu(gn1(h1)) + gn2 stats ----------------
__global__ __launch_bounds__(256) void k_dw(const float* __restrict__ w_dw) {
    int rt = blockIdx.x;
    int hc = blockIdx.y;
    int b = blockIdx.z;
    __shared__ float xs[18][66];
    __shared__ float sred[2];
    int tid = threadIdx.x;
    float a = g_c1a[b * HCn + hc], bb = g_c1b[b * HCn + hc];
    const float* src = g_h1 + (size_t)(b * HCn + hc) * HWn;
    int r0 = rt * 16;
    for (int idx = tid; idx < 18 * 66; idx += 256) {
        int rr = idx / 66, cx = idx % 66;
        int gy = r0 - 1 + rr, gx = cx - 1;
        float v = 0.f;
        if ((unsigned)gy < 64u && (unsigned)gx < 64u)
            v = silu_f(fmaf(src[gy * 64 + gx], a, bb));
        xs[rr][cx] = v;
    }
    float wd[9];
    #pragma unroll
    for (int t9 = 0; t9 < 9; t9++) wd[t9] = __ldg(&w_dw[hc * 9 + t9]);
    __syncthreads();
    float lsum = 0.f, lsq = 0.f;
    float* dst = g_h2 + (size_t)(b * HCn + hc) * HWn;
    #pragma unroll
    for (int k4 = 0; k4 < 4; k4++) {
        int idx = tid + k4 * 256;
        int row = idx >> 6, col = idx & 63;
        float sum = 0.f;
        #pragma unroll
        for (int kh = 0; kh < 3; kh++)
            #pragma unroll
            for (int kw = 0; kw < 3; kw++)
                sum = fmaf(wd[kh * 3 + kw], xs[row + kh][col + kw], sum);
        dst[(r0 + row) * 64 + col] = sum;
        lsum += sum;
        lsq += sum * sum;
    }
    if (tid < 2) sred[tid] = 0.f;
    __syncthreads();
    atomicAdd(&sred[0], lsum);
    atomicAdd(&sred[1], lsq);
    __syncthreads();
    if (tid == 0) {
        int g = hc >> 6;
        atomicAdd(&g_s2[(b * 8 + g) * 2], sred[0]);
        atomicAdd(&g_s2[(b * 8 + g) * 2 + 1], sred[1]);
    }
}

// ---------------- K6: pw2 1x1 stride-2 (512->128) + gn3 stats ----------------
__global__ __launch_bounds__(256) void k_pw2(const float* __restrict__ w_pw2) {
    int pxb = blockIdx.x * 128;
    int cob = blockIdx.y * 64;
    int b = blockIdx.z;
    __shared__ float As[16][64];
    __shared__ float Bs[16][128];
    __shared__ float sred[8];
    int tid = threadIdx.x;
    int pg = tid & 15, cgp = tid >> 4;
    float acc[8][4];
    #pragma unroll
    for (int j = 0; j < 8; j++)
        #pragma unroll
        for (int o = 0; o < 4; o++) acc[j][o] = 0.f;

    for (int kb = 0; kb < 512; kb += 16) {
        for (int idx = tid; idx < 1024; idx += 256) {
            int co = idx >> 4, kk = idx & 15;
            As[kk][co] = w_pw2[(size_t)(cob + co) * 512 + kb + kk];
        }
        for (int idx = tid; idx < 2048; idx += 256) {
            int kk = idx >> 7, ii = idx & 127;
            int p = pxb + ii;
            int oh = p >> 5, ow = p & 31;
            int ch = kb + kk;
            float a = g_c2a[b * HCn + ch], bb = g_c2b[b * HCn + ch];
            float v = g_h2[(size_t)(b * HCn + ch) * HWn + oh * 128 + ow * 2];
            Bs[kk][ii] = silu_f(fmaf(v, a, bb));
        }
        __syncthreads();
        #pragma unroll
        for (int kk = 0; kk < 16; kk++) {
            float4 xa = *(const float4*)&Bs[kk][pg * 8];
            float4 xb2 = *(const float4*)&Bs[kk][pg * 8 + 4];
            float xv[8] = {xa.x, xa.y, xa.z, xa.w, xb2.x, xb2.y, xb2.z, xb2.w};
            float4 wa = *(const float4*)&As[kk][cgp * 4];
            float wv[4] = {wa.x, wa.y, wa.z, wa.w};
            #pragma unroll
            for (int j = 0; j < 8; j++)
                #pragma unroll
                for (int o = 0; o < 4; o++)
                    acc[j][o] = fmaf(xv[j], wv[o], acc[j][o]);
        }
        __syncthreads();
    }
    float lsum = 0.f, lsq = 0.f;
    #pragma unroll
    for (int o = 0; o < 4; o++) {
        int co = cob + cgp * 4 + o;
        float* dst = g_o + (size_t)(b * Cn + co) * OHWn + pxb + pg * 8;
        float4 v0 = make_float4(acc[0][o], acc[1][o], acc[2][o], acc[3][o]);
        float4 v1 = make_float4(acc[4][o], acc[5][o], acc[6][o], acc[7][o]);
        lsum += v0.x + v0.y + v0.z + v0.w + v1.x + v1.y + v1.z + v1.w;
        lsq += v0.x * v0.x + v0.y * v0.y + v0.z * v0.z + v0.w * v0.w +
               v1.x * v1.x + v1.y * v1.y + v1.z * v1.z + v1.w * v1.w;
        *(float4*)dst = v0;
        *(float4*)(dst + 4) = v1;
    }
    if (tid < 8) sred[tid] = 0.f;
    __syncthreads();
    atomicAdd(&sred[(cgp >> 2) * 2], lsum);
    atomicAdd(&sred[(cgp >> 2) * 2 + 1], lsq);
    __syncthreads();
    if (tid < 4) {
        int g = (cob >> 4) + tid;
        atomicAdd(&g_s3[(b * 8 + g) * 2], sred[tid * 2]);
        atomicAdd(&g_s3[(b * 8 + g) * 2 + 1], sred[tid * 2 + 1]);
    }
}

// ---------------- K7: final gn3 + silu ----------------
__global__ void k_out(float* __restrict__ out) {
    int i = blockIdx.x * 256 + threadIdx.x;
    int b = i >> 17;
    int c = (i >> 10) & 127;
    out[i] = silu_f(fmaf(g_o[i], g_c3a[b * Cn + c], g_c3b[b * Cn + c]));
}

// ---------------- launch ----------------
extern "C" void kernel_launch(void* const* d_in, const int* in_sizes, int n_in,
                              void* d_out, int out_size) {
    const float* x      = (const float*)d_in[0];
    const float* w_exp  = (const float*)d_in[1];
    const float* gns    = (const float*)d_in[2];
    const float* gnb    = (const float*)d_in[3];
    const float* w1     = (const float*)d_in[4];
    const float* b1     = (const float*)d_in[5];
    const float* w2     = (const float*)d_in[6];
    const float* b2     = (const float*)d_in[7];
    const float* w_pw1  = (const float*)d_in[8];
    const float* gn1s   = (const float*)d_in[9];
    const float* gn1b   = (const float*)d_in[10];
    const float* w_dw   = (const float*)d_in[11];
    const float* gn2s   = (const float*)d_in[12];
    const float* gn2b   = (const float*)d_in[13];
    const float* w_pw2  = (const float*)d_in[14];
    const float* gn3s   = (const float*)d_in[15];
    const float* gn3b   = (const float*)d_in[16];
    float* out = (float*)d_out;

    const int expert_smem = (9792 + 3168) * 4;   // 51840 B
    cudaFuncSetAttribute(k_expert, cudaFuncAttributeMaxDynamicSharedMemorySize,
                         expert_smem);

    k_zero<<<8, 256>>>();
    k_wprep<<<(En * 16 * 9 * 8 * 128 + 255) / 256, 256>>>(w_exp);
    k_w1prep<<<(4 * 16 * 8 * 128 + 255) / 256, 256>>>(w_pw1);
    k_xprep<<<(Bn * Cn * HWn) / 256, 256>>>(x);
    {
        dim3 g(16, 1, En * Bn);
        k_expert<<<g, 512, expert_smem>>>();
    }
    k_router_fin<<<1, 256>>>(gns, gnb, w1, b1, w2, b2);
    k_combine<<<8192, 256>>>(x);
    {
        dim3 g(32, 4, Bn);
        k_pw1m<<<g, 256>>>();
    }
    k_fin1<<<(Bn * HCn + 255) / 256, 256>>>(gn1s, gn1b);
    {
        dim3 g(4, HCn, Bn);
        k_dw<<<g, 256>>>(w_dw);
    }
    k_fin2<<<(Bn * HCn + 255) / 256, 256>>>(gn2s, gn2b);
    {
        dim3 g(8, 2, Bn);
        k_pw2<<<g, 256>>>(w_pw2);
    }
    k_fin3<<<(Bn * Cn + 255) / 256, 256>>>(gn3s, gn3b);
    k_out<<<8192, 256>>>(out);
}

// round 7
// speedup vs baseline: 1.2120x; 1.2120x over previous
#include <cuda_runtime.h>
#include <math.h>

#define En 8
#define Bn 16
#define Cn 128
#define Hn 64
#define Wn 64
#define HWn 4096
#define HCn 512
#define OHWn 1024

// ---------------- scratch (device globals; no allocation) ----------------
__device__ float g_y[(size_t)En * Bn * Cn * HWn];
__device__ unsigned g_combt[(size_t)Bn * Cn * HWn];    // combined, tf32 bits
__device__ float g_h1[(size_t)Bn * HCn * HWn];
__device__ float g_h2[(size_t)Bn * HCn * HWn];
__device__ float g_o[(size_t)Bn * Cn * OHWn];
__device__ unsigned g_wt[(size_t)En * 16 * 9 * 8 * 128];   // expert W tf32 staging order
__device__ unsigned g_w1t[(size_t)4 * 16 * 8 * 128];       // pw1 W tf32 staging order
__device__ unsigned g_w2t[(size_t)64 * 8 * 128];           // pw2 W tf32 staging order
__device__ unsigned g_xt[(size_t)Bn * Cn * HWn];           // x as tf32 bits
__device__ float g_estats[En * Bn * 8 * 2];
__device__ float g_eca[En * Bn * Cn];
__device__ float g_ecb[En * Bn * Cn];
__device__ float g_wts[16][En];
__device__ float g_s1[Bn * 8 * 2];
__device__ float g_c1a[Bn * HCn];
__device__ float g_c1b[Bn * HCn];
__device__ float g_s2[Bn * 8 * 2];
__device__ float g_c2a[Bn * HCn];
__device__ float g_c2b[Bn * HCn];
__device__ float g_s3[Bn * 8 * 2];
__device__ float g_c3a[Bn * Cn];
__device__ float g_c3b[Bn * Cn];

__device__ __forceinline__ float silu_f(float v) { return v / (1.f + __expf(-v)); }

__device__ __forceinline__ unsigned to_tf32(float f) {
    unsigned r;
    asm("cvt.rna.tf32.f32 %0, %1;" : "=r"(r) : "f"(f));
    return r;
}

__device__ __forceinline__ void mma_tf32(float& c0, float& c1, float& c2, float& c3,
                                         unsigned a0, unsigned a1, unsigned a2, unsigned a3,
                                         unsigned b0, unsigned b1) {
    asm volatile(
        "mma.sync.aligned.m16n8k8.row.col.f32.tf32.tf32.f32 "
        "{%0,%1,%2,%3}, {%4,%5,%6,%7}, {%8,%9}, {%0,%1,%2,%3};"
        : "+f"(c0), "+f"(c1), "+f"(c2), "+f"(c3)
        : "r"(a0), "r"(a1), "r"(a2), "r"(a3), "r"(b0), "r"(b1));
}

// ---------------- K0: zero the stats accumulators ----------------
__global__ void k_zero() {
    int i = blockIdx.x * 256 + threadIdx.x;
    if (i < En * Bn * 8 * 2) g_estats[i] = 0.f;
    if (i < Bn * 8 * 2) { g_s1[i] = 0.f; g_s2[i] = 0.f; g_s3[i] = 0.f; }
}

// ---------------- W preps ----------------
__global__ void k_wprep(const float* __restrict__ w_exp) {
    int i = blockIdx.x * 256 + threadIdx.x;
    if (i >= En * 16 * 9 * 8 * 128) return;
    int co = i & 127;
    int r = i >> 7;
    int ci = r & 7; r >>= 3;
    int tap = r % 9; r /= 9;
    int cc = r & 15;
    int e = r >> 4;
    g_wt[i] = to_tf32(w_exp[((size_t)(e * 128 + co) * 128 + cc * 8 + ci) * 9 + tap]);
}
__global__ void k_w1prep(const float* __restrict__ w_pw1) {
    int i = blockIdx.x * 256 + threadIdx.x;
    if (i >= 4 * 16 * 8 * 128) return;
    int hcl = i & 127;
    int ci = (i >> 7) & 7;
    int cc = (i >> 10) & 15;
    int blk = i >> 14;
    g_w1t[i] = to_tf32(w_pw1[(size_t)(blk * 128 + hcl) * 128 + cc * 8 + ci]);
}
__global__ void k_w2prep(const float* __restrict__ w_pw2) {
    int i = blockIdx.x * 256 + threadIdx.x;
    if (i >= 64 * 8 * 128) return;
    int co = i & 127;
    int ci = (i >> 7) & 7;
    int cc = i >> 10;
    g_w2t[i] = to_tf32(w_pw2[(size_t)co * 512 + cc * 8 + ci]);
}
__global__ void k_xprep(const float* __restrict__ x) {
    int i = blockIdx.x * 256 + threadIdx.x;
    g_xt[i] = to_tf32(x[i]);
}

// ---------------- K1: expert 3x3 conv via tf32 mma + GN stats ----------------
// block: one (e,b), 64 co (half), 4 image rows (256 px). 8 warps = 2 co-groups x 4 rows.
// warp: 32 co x 64 px. smem 33408 B, occupancy 2.
__global__ __launch_bounds__(256, 2) void k_expert() {
    __shared__ unsigned ws[9 * 8 * 72];      // [tap][ci][co pad72]
    __shared__ unsigned xs[8 * 6 * 66];      // [ci][halo row][halo col]

    const int ty0 = blockIdx.x * 4;          // 16 tiles of 4 rows
    const int chb = blockIdx.y;              // co half: 0 or 1
    const int e = blockIdx.z >> 4;
    const int b = blockIdx.z & 15;

    const int tid = threadIdx.x;
    const int warp = tid >> 5;
    const int lane = tid & 31;
    const int wc = warp >> 2;                // co group within half (32 co)
    const int wp = warp & 3;                 // image row within strip
    const int grp = lane >> 2;
    const int tig = lane & 3;

    float acc[2][8][4];
    #pragma unroll
    for (int mt = 0; mt < 2; mt++)
        #pragma unroll
        for (int nt = 0; nt < 8; nt++)
            #pragma unroll
            for (int q = 0; q < 4; q++) acc[mt][nt][q] = 0.f;

    const unsigned* wt = g_wt + (size_t)e * 147456;
    const unsigned* xt = g_xt + (size_t)b * Cn * HWn;

    for (int cc = 0; cc < 16; cc++) {
        // stage W half: 72 rows (tap,ci) x 64 co
        for (int idx = tid; idx < 1152; idx += 256) {
            int rw = idx >> 4, w4 = idx & 15;
            const uint4* src = (const uint4*)(wt + cc * 9216 + rw * 128 + chb * 64);
            *(uint4*)(ws + rw * 72 + w4 * 4) = src[w4];
        }
        // stage X halo: 8 ci x 6 rows x 66 cols
        for (int idx = tid; idx < 3168; idx += 256) {
            int ci = idx / 396;
            int rem = idx - ci * 396;
            int row = rem / 66;
            int cx = rem - row * 66;
            int gy = ty0 - 1 + row, gx = cx - 1;
            unsigned v = 0u;
            if ((unsigned)gy < 64u && (unsigned)gx < 64u)
                v = xt[(size_t)(cc * 8 + ci) * HWn + gy * 64 + gx];
            xs[(ci * 6 + row) * 66 + cx] = v;
        }
        __syncthreads();

        #pragma unroll
        for (int tap = 0; tap < 9; tap++) {
            const int kh = tap / 3, kw = tap % 3;
            unsigned a0[2], a1[2], a2[2], a3[2];
            #pragma unroll
            for (int mt = 0; mt < 2; mt++) {
                int co_r = wc * 32 + mt * 16 + grp;
                a0[mt] = ws[(tap * 8 + tig) * 72 + co_r];
                a1[mt] = ws[(tap * 8 + tig) * 72 + co_r + 8];
                a2[mt] = ws[(tap * 8 + tig + 4) * 72 + co_r];
                a3[mt] = ws[(tap * 8 + tig + 4) * 72 + co_r + 8];
            }
            #pragma unroll
            for (int nt = 0; nt < 8; nt++) {
                int col = nt * 8 + grp + kw;
                unsigned b0 = xs[(tig * 6 + wp + kh) * 66 + col];
                unsigned b1 = xs[((tig + 4) * 6 + wp + kh) * 66 + col];
                mma_tf32(acc[0][nt][0], acc[0][nt][1], acc[0][nt][2], acc[0][nt][3],
                         a0[0], a1[0], a2[0], a3[0], b0, b1);
                mma_tf32(acc[1][nt][0], acc[1][nt][1], acc[1][nt][2], acc[1][nt][3],
                         a0[1], a1[1], a2[1], a3[1], b0, b1);
            }
        }
        __syncthreads();
    }

    // epilogue: write y + per-warp GN group stats
    size_t ybase = (size_t)(e * Bn + b) * Cn * HWn;
    const int row = ty0 + wp;
    float ls[2] = {0.f, 0.f}, lq[2] = {0.f, 0.f};
    #pragma unroll
    for (int mt = 0; mt < 2; mt++) {
        int co = chb * 64 + wc * 32 + mt * 16 + grp;
        #pragma unroll
        for (int nt = 0; nt < 8; nt++) {
            int colx = nt * 8 + 2 * tig;
            float2 v0 = make_float2(acc[mt][nt][0], acc[mt][nt][1]);
            float2 v1 = make_float2(acc[mt][nt][2], acc[mt][nt][3]);
            *(float2*)(g_y + ybase + (size_t)co * HWn + row * 64 + colx) = v0;
            *(float2*)(g_y + ybase + (size_t)(co + 8) * HWn + row * 64 + colx) = v1;
            ls[mt] += v0.x + v0.y + v1.x + v1.y;
            lq[mt] += v0.x * v0.x + v0.y * v0.y + v1.x * v1.x + v1.y * v1.y;
        }
    }
    #pragma unroll
    for (int mt = 0; mt < 2; mt++) {
        float s = ls[mt], q = lq[mt];
        #pragma unroll
        for (int off = 16; off > 0; off >>= 1) {
            s += __shfl_xor_sync(0xFFFFFFFFu, s, off);
            q += __shfl_xor_sync(0xFFFFFFFFu, q, off);
        }
        if (lane == 0) {
            int g = chb * 4 + wc * 2 + mt;
            atomicAdd(&g_estats[((e * Bn + b) * 8 + g) * 2], s);
            atomicAdd(&g_estats[((e * Bn + b) * 8 + g) * 2 + 1], q);
        }
    }
}

// ---------------- K2: finalize expert GN coefs + router softmax ----------------
__global__ void k_router_fin(const float* __restrict__ gns, const float* __restrict__ gnb,
                             const float* __restrict__ w1, const float* __restrict__ b1,
                             const float* __restrict__ w2, const float* __restrict__ b2) {
    int tid = threadIdx.x;
    for (int i = tid; i < En * Bn * Cn; i += 256) {
        int e = i >> 11, b = (i >> 7) & 15, c = i & 127, g = c >> 4;
        float s = g_estats[((e * Bn + b) * 8 + g) * 2];
        float sq = g_estats[((e * Bn + b) * 8 + g) * 2 + 1];
        float mean = s * (1.f / 65536.f);
        float var = sq * (1.f / 65536.f) - mean * mean;
        float rstd = rsqrtf(var + 1e-5f);
        float a = rstd * gns[e * Cn + c];
        g_eca[i] = a;
        g_ecb[i] = gnb[e * Cn + c] - mean * a;
    }
    if (tid < 16) {
        int py = tid >> 2, px = tid & 3;
        float fe[32];
        float cy = (py + 0.5f) * 0.25f, cx = (px + 0.5f) * 0.25f;
        #pragma unroll
        for (int k = 0; k < 8; k++) {
            float fr = (float)(1 << k) * 3.14159265358979323846f;
            fe[k] = sinf(cy * fr);
            fe[8 + k] = cosf(cy * fr);
            fe[16 + k] = sinf(cx * fr);
            fe[24 + k] = cosf(cx * fr);
        }
        float hb[64];
        for (int j = 0; j < 64; j++) {
            float s = b1[j];
            for (int k = 0; k < 32; k++) s = fmaf(fe[k], w1[k * 64 + j], s);
            hb[j] = s / (1.f + expf(-s));
        }
        float lo[8];
        float mx = -1e30f;
        for (int ee = 0; ee < 8; ee++) {
            float s = b2[ee];
            for (int j = 0; j < 64; j++) s = fmaf(hb[j], w2[j * 8 + ee], s);
            lo[ee] = s;
            mx = fmaxf(mx, s);
        }
        float den = 0.f;
        for (int ee = 0; ee < 8; ee++) { lo[ee] = expf(lo[ee] - mx); den += lo[ee]; }
        float inv = 1.f / den;
        for (int ee = 0; ee < 8; ee++) g_wts[tid][ee] = lo[ee] * inv;
    }
}

// ---------------- K3: combine experts -> tf32 bits ----------------
__global__ void k_combine(const float* __restrict__ x) {
    size_t t = (size_t)blockIdx.x * 256 + threadIdx.x;
    size_t i = t * 4;
    int b = (int)(i >> 19);
    int c = (int)(i >> 12) & 127;
    int p = (int)(i & 4095);
    int patch = ((p >> 6) >> 4) * 4 + ((p & 63) >> 4);
    float4 outv = *(const float4*)(x + i);
    #pragma unroll
    for (int e = 0; e < 8; e++) {
        int ebc = (e * Bn + b) * Cn + c;
        float a = g_eca[ebc], bb = g_ecb[ebc];
        float wt = g_wts[patch][e];
        float4 y = *(const float4*)(g_y + (size_t)ebc * HWn + p);
        outv.x += wt * silu_f(fmaf(y.x, a, bb));
        outv.y += wt * silu_f(fmaf(y.y, a, bb));
        outv.z += wt * silu_f(fmaf(y.z, a, bb));
        outv.w += wt * silu_f(fmaf(y.w, a, bb));
    }
    uint4 o;
    o.x = to_tf32(outv.x);
    o.y = to_tf32(outv.y);
    o.z = to_tf32(outv.z);
    o.w = to_tf32(outv.w);
    *(uint4*)(g_combt + i) = o;
}

// ---------------- K4: pw1 1x1 (128->512) via tf32 mma + gn1 stats ----------------
__global__ __launch_bounds__(256) void k_pw1m() {
    __shared__ unsigned As[8 * 136];
    __shared__ unsigned Bs[8 * 136];
    const int pxb = blockIdx.x * 128;
    const int hcb = blockIdx.y * 128;
    const int b = blockIdx.z;
    const int tid = threadIdx.x;
    const int warp = tid >> 5;
    const int lane = tid & 31;
    const int wc = warp >> 1;
    const int wpx = warp & 1;
    const int grp = lane >> 2;
    const int tig = lane & 3;

    float acc[2][8][4];
    #pragma unroll
    for (int mt = 0; mt < 2; mt++)
        #pragma unroll
        for (int nt = 0; nt < 8; nt++)
            #pragma unroll
            for (int q = 0; q < 4; q++) acc[mt][nt][q] = 0.f;

    for (int cc = 0; cc < 16; cc++) {
        {
            const uint4* srcA = (const uint4*)(g_w1t + (size_t)((blockIdx.y * 16 + cc) * 8) * 128);
            uint4 v = srcA[tid];
            *(uint4*)(As + (tid >> 5) * 136 + (tid & 31) * 4) = v;
        }
        {
            int r = tid >> 5;
            const uint4* srcB = (const uint4*)(g_combt + (size_t)(b * Cn + cc * 8 + r) * HWn + pxb);
            uint4 v = srcB[tid & 31];
            *(uint4*)(Bs + r * 136 + (tid & 31) * 4) = v;
        }
        __syncthreads();

        unsigned a0[2], a1[2], a2[2], a3[2];
        #pragma unroll
        for (int mt = 0; mt < 2; mt++) {
            int hc_r = wc * 32 + mt * 16 + grp;
            a0[mt] = As[tig * 136 + hc_r];
            a1[mt] = As[tig * 136 + hc_r + 8];
            a2[mt] = As[(tig + 4) * 136 + hc_r];
            a3[mt] = As[(tig + 4) * 136 + hc_r + 8];
        }
        #pragma unroll
        for (int nt = 0; nt < 8; nt++) {
            int col = wpx * 64 + nt * 8 + grp;
            unsigned b0 = Bs[tig * 136 + col];
            unsigned b1 = Bs[(tig + 4) * 136 + col];
            mma_tf32(acc[0][nt][0], acc[0][nt][1], acc[0][nt][2], acc[0][nt][3],
                     a0[0], a1[0], a2[0], a3[0], b0, b1);
            mma_tf32(acc[1][nt][0], acc[1][nt][1], acc[1][nt][2], acc[1][nt][3],
                     a0[1], a1[1], a2[1], a3[1], b0, b1);
        }
        __syncthreads();
    }

    #pragma unroll
    for (int mt = 0; mt < 2; mt++) {
        int hc0 = hcb + wc * 32 + mt * 16 + grp;
        float ls = 0.f, lq = 0.f;
        #pragma unroll
        for (int nt = 0; nt < 8; nt++) {
            int px = pxb + wpx * 64 + nt * 8 + 2 * tig;
            float2 v0 = make_float2(acc[mt][nt][0], acc[mt][nt][1]);
            float2 v1 = make_float2(acc[mt][nt][2], acc[mt][nt][3]);
            *(float2*)(g_h1 + (size_t)(b * HCn + hc0) * HWn + px) = v0;
            *(float2*)(g_h1 + (size_t)(b * HCn + hc0 + 8) * HWn + px) = v1;
            ls += v0.x + v0.y + v1.x + v1.y;
            lq += v0.x * v0.x + v0.y * v0.y + v1.x * v1.x + v1.y * v1.y;
        }
        #pragma unroll
        for (int off = 16; off > 0; off >>= 1) {
            ls += __shfl_xor_sync(0xFFFFFFFFu, ls, off);
            lq += __shfl_xor_sync(0xFFFFFFFFu, lq, off);
        }
        if (lane == 0) {
            int g = (hcb >> 6) + (wc >> 1);
            atomicAdd(&g_s1[(b * 8 + g) * 2], ls);
            atomicAdd(&g_s1[(b * 8 + g) * 2 + 1], lq);
        }
    }
}

// ---------------- finalize kernels ----------------
__global__ void k_fin1(const float* __restrict__ s, const float* __restrict__ bias) {
    int i = blockIdx.x * 256 + threadIdx.x;
    if (i >= Bn * HCn) return;
    int b = i / HCn, c = i % HCn, g = c >> 6;
    float su = g_s1[(b * 8 + g) * 2], sq = g_s1[(b * 8 + g) * 2 + 1];
    float mean = su * (1.f / 262144.f);
    float var = sq * (1.f / 262144.f) - mean * mean;
    float rstd = rsqrtf(var + 1e-5f);
    float a = rstd * s[c];
    g_c1a[i] = a;
    g_c1b[i] = bias[c] - mean * a;
}
__global__ void k_fin2(const float* __restrict__ s, const float* __restrict__ bias) {
    int i = blockIdx.x * 256 + threadIdx.x;
    if (i >= Bn * HCn) return;
    int b = i / HCn, c = i % HCn, g = c >> 6;
    float su = g_s2[(b * 8 + g) * 2], sq = g_s2[(b * 8 + g) * 2 + 1];
    float mean = su * (1.f / 262144.f);
    float var = sq * (1.f / 262144.f) - mean * mean;
    float rstd = rsqrtf(var + 1e-5f);
    float a = rstd * s[c];
    g_c2a[i] = a;
    g_c2b[i] = bias[c] - mean * a;
}
__global__ void k_fin3(const float* __restrict__ s, const float* __restrict__ bias) {
    int i = blockIdx.x * 256 + threadIdx.x;
    if (i >= Bn * Cn) return;
    int b = i / Cn, c = i % Cn, g = c >> 4;
    float su = g_s3[(b * 8 + g) * 2], sq = g_s3[(b * 8 + g) * 2 + 1];
    float mean = su * (1.f / 16384.f);
    float var = sq * (1.f / 16384.f) - mean * mean;
    float rstd = rsqrtf(var + 1e-5f);
    float a = rstd * s[c];
    g_c3a[i] = a;
    g_c3b[i] = bias[c] - mean * a;
}

// ---------------- K5: depthwise 3x3 on silu(gn1(h1)) + gn2 stats ----------------
__global__ __launch_bounds__(256) void k_dw(const float* __restrict__ w_dw) {
    int rt = blockIdx.x;
    int hc = blockIdx.y;
    int b = blockIdx.z;
    __shared__ float xs[18][66];
    __shared__ float sred[2];
    int tid = threadIdx.x;
    float a = g_c1a[b * HCn + hc], bb = g_c1b[b * HCn + hc];
    const float* src = g_h1 + (size_t)(b * HCn + hc) * HWn;
    int r0 = rt * 16;
    for (int idx = tid; idx < 18 * 66; idx += 256) {
        int rr = idx / 66, cx = idx % 66;
        int gy = r0 - 1 + rr, gx = cx - 1;
        float v = 0.f;
        if ((unsigned)gy < 64u && (unsigned)gx < 64u)
            v = silu_f(fmaf(src[gy * 64 + gx], a, bb));
        xs[rr][cx] = v;
    }
    float wd[9];
    #pragma unroll
    for (int t9 = 0; t9 < 9; t9++) wd[t9] = __ldg(&w_dw[hc * 9 + t9]);
    __syncthreads();
    float lsum = 0.f, lsq = 0.f;
    float* dst = g_h2 + (size_t)(b * HCn + hc) * HWn;
    #pragma unroll
    for (int k4 = 0; k4 < 4; k4++) {
        int idx = tid + k4 * 256;
        int row = idx >> 6, col = idx & 63;
        float sum = 0.f;
        #pragma unroll
        for (int kh = 0; kh < 3; kh++)
            #pragma unroll
            for (int kw = 0; kw < 3; kw++)
                sum = fmaf(wd[kh * 3 + kw], xs[row + kh][col + kw], sum);
        dst[(r0 + row) * 64 + col] = sum;
        lsum += sum;
        lsq += sum * sum;
    }
    if (tid < 2) sred[tid] = 0.f;
    __syncthreads();
    atomicAdd(&sred[0], lsum);
    atomicAdd(&sred[1], lsq);
    __syncthreads();
    if (tid == 0) {
        int g = hc >> 6;
        atomicAdd(&g_s2[(b * 8 + g) * 2], sred[0]);
        atomicAdd(&g_s2[(b * 8 + g) * 2 + 1], sred[1]);
    }
}

// ---------------- K6: pw2 1x1 stride-2 (512->128) via tf32 mma + gn3 stats ----------------
// block: 128 co x 128 out px for one b. 8 warps = 4 co-groups x 2 px halves.
__global__ __launch_bounds__(256) void k_pw2m() {
    __shared__ unsigned As[8 * 136];
    __shared__ unsigned Bs[8 * 136];
    const int pxb = blockIdx.x * 128;        // 8 tiles over 1024 out px
    const int b = blockIdx.z;
    const int tid = threadIdx.x;
    const int warp = tid >> 5;
    const int lane = tid & 31;
    const int wc = warp >> 1;
    const int wpx = warp & 1;
    const int grp = lane >> 2;
    const int tig = lane & 3;

    float acc[2][8][4];
    #pragma unroll
    for (int mt = 0; mt < 2; mt++)
        #pragma unroll
        for (int nt = 0; nt < 8; nt++)
            #pragma unroll
            for (int q = 0; q < 4; q++) acc[mt][nt][q] = 0.f;

    for (int cc = 0; cc < 64; cc++) {
        {
            const uint4* srcA = (const uint4*)(g_w2t + (size_t)cc * 1024);
            uint4 v = srcA[tid];
            *(uint4*)(As + (tid >> 5) * 136 + (tid & 31) * 4) = v;
        }
        {
            int r = tid >> 5;                 // k row 0..7
            int ch = cc * 8 + r;
            float a = g_c2a[b * HCn + ch], bb = g_c2b[b * HCn + ch];
            const float* src = g_h2 + (size_t)(b * HCn + ch) * HWn;
            int i0 = (lane) * 4;              // 4 px per thread
            #pragma unroll
            for (int j = 0; j < 4; j++) {
                int p = pxb + i0 + j;
                int oh = p >> 5, ow = p & 31;
                float v = silu_f(fmaf(src[oh * 128 + ow * 2], a, bb));
                Bs[r * 136 + i0 + j] = to_tf32(v);
            }
        }
        __syncthreads();

        unsigned a0[2], a1[2], a2[2], a3[2];
        #pragma unroll
        for (int mt = 0; mt < 2; mt++) {
            int co_r = wc * 32 + mt * 16 + grp;
            a0[mt] = As[tig * 136 + co_r];
            a1[mt] = As[tig * 136 + co_r + 8];
            a2[mt] = As[(tig + 4) * 136 + co_r];
            a3[mt] = As[(tig + 4) * 136 + co_r + 8];
        }
        #pragma unroll
        for (int nt = 0; nt < 8; nt++) {
            int col = wpx * 64 + nt * 8 + grp;
            unsigned b0 = Bs[tig * 136 + col];
            unsigned b1 = Bs[(tig + 4) * 136 + col];
            mma_tf32(acc[0][nt][0], acc[0][nt][1], acc[0][nt][2], acc[0][nt][3],
                     a0[0], a1[0], a2[0], a3[0], b0, b1);
            mma_tf32(acc[1][nt][0], acc[1][nt][1], acc[1][nt][2], acc[1][nt][3],
                     a0[1], a1[1], a2[1], a3[1], b0, b1);
        }
        __syncthreads();
    }

    #pragma unroll
    for (int mt = 0; mt < 2; mt++) {
        int co0 = wc * 32 + mt * 16 + grp;
        float ls = 0.f, lq = 0.f;
        #pragma unroll
        for (int nt = 0; nt < 8; nt++) {
            int px = pxb + wpx * 64 + nt * 8 + 2 * tig;
            float2 v0 = make_float2(acc[mt][nt][0], acc[mt][nt][1]);
            float2 v1 = make_float2(acc[mt][nt][2], acc[mt][nt][3]);
            *(float2*)(g_o + (size_t)(b * Cn + co0) * OHWn + px) = v0;
            *(float2*)(g_o + (size_t)(b * Cn + co0 + 8) * OHWn + px) = v1;
            ls += v0.x + v0.y + v1.x + v1.y;
            lq += v0.x * v0.x + v0.y * v0.y + v1.x * v1.x + v1.y * v1.y;
        }
        #pragma unroll
        for (int off = 16; off > 0; off >>= 1) {
            ls += __shfl_xor_sync(0xFFFFFFFFu, ls, off);
            lq += __shfl_xor_sync(0xFFFFFFFFu, lq, off);
        }
        if (lane == 0) {
            int g = wc * 2 + mt;
            atomicAdd(&g_s3[(b * 8 + g) * 2], ls);
            atomicAdd(&g_s3[(b * 8 + g) * 2 + 1], lq);
        }
    }
}

// ---------------- K7: final gn3 + silu ----------------
__global__ void k_out(float* __restrict__ out) {
    int i = blockIdx.x * 256 + threadIdx.x;
    int b = i >> 17;
    int c = (i >> 10) & 127;
    out[i] = silu_f(fmaf(g_o[i], g_c3a[b * Cn + c], g_c3b[b * Cn + c]));
}

// ---------------- launch ----------------
extern "C" void kernel_launch(void* const* d_in, const int* in_sizes, int n_in,
                              void* d_out, int out_size) {
    const float* x      = (const float*)d_in[0];
    const float* w_exp  = (const float*)d_in[1];
    const float* gns    = (const float*)d_in[2];
    const float* gnb    = (const float*)d_in[3];
    const float* w1     = (const float*)d_in[4];
    const float* b1     = (const float*)d_in[5];
    const float* w2     = (const float*)d_in[6];
    const float* b2     = (const float*)d_in[7];
    const float* w_pw1  = (const float*)d_in[8];
    const float* gn1s   = (const float*)d_in[9];
    const float* gn1b   = (const float*)d_in[10];
    const float* w_dw   = (const float*)d_in[11];
    const float* gn2s   = (const float*)d_in[12];
    const float* gn2b   = (const float*)d_in[13];
    const float* w_pw2  = (const float*)d_in[14];
    const float* gn3s   = (const float*)d_in[15];
    const float* gn3b   = (const float*)d_in[16];
    float* out = (float*)d_out;

    k_zero<<<8, 256>>>();
    k_wprep<<<(En * 16 * 9 * 8 * 128 + 255) / 256, 256>>>(w_exp);
    k_w1prep<<<(4 * 16 * 8 * 128 + 255) / 256, 256>>>(w_pw1);
    k_w2prep<<<(64 * 8 * 128 + 255) / 256, 256>>>(w_pw2);
    k_xprep<<<(Bn * Cn * HWn) / 256, 256>>>(x);
    {
        dim3 g(16, 2, En * Bn);
        k_expert<<<g, 256>>>();
    }
    k_router_fin<<<1, 256>>>(gns, gnb, w1, b1, w2, b2);
    k_combine<<<8192, 256>>>(x);
    {
        dim3 g(32, 4, Bn);
        k_pw1m<<<g, 256>>>();
    }
    k_fin1<<<(Bn * HCn + 255) / 256, 256>>>(gn1s, gn1b);
    {
        dim3 g(4, HCn, Bn);
        k_dw<<<g, 256>>>(w_dw);
    }
    k_fin2<<<(Bn * HCn + 255) / 256, 256>>>(gn2s, gn2b);
    {
        dim3 g(8, 1, Bn);
        k_pw2m<<<g, 256>>>();
    }
    k_fin3<<<(Bn * Cn + 255) / 256, 256>>>(gn3s, gn3b);
    k_out<<<8192, 256>>>(out);
}

// round 8
// speedup vs baseline: 1.2970x; 1.0702x over previous
#include <cuda_runtime.h>
#include <math.h>

#define En 8
#define Bn 16
#define Cn 128
#define Hn 64
#define Wn 64
#define HWn 4096
#define HCn 512
#define OHWn 1024

// ---------------- scratch (device globals; no allocation) ----------------
__device__ float g_y[(size_t)En * Bn * Cn * HWn];
__device__ unsigned g_combt[(size_t)Bn * Cn * HWn];    // combined, tf32 bits
__device__ float g_h1[(size_t)Bn * HCn * HWn];
__device__ float g_h2[(size_t)Bn * HCn * HWn];
__device__ float g_o[(size_t)Bn * Cn * OHWn];
__device__ unsigned g_wt[(size_t)En * 16 * 9 * 8 * 128];   // expert W tf32 staging order
__device__ unsigned g_w1t[(size_t)4 * 16 * 8 * 128];       // pw1 W tf32 staging order
__device__ unsigned g_w2t[(size_t)64 * 8 * 128];           // pw2 W tf32 staging order
__device__ unsigned g_xt[(size_t)Bn * Cn * HWn];           // x as tf32 bits
__device__ float g_estats[En * Bn * 8 * 2];
__device__ float g_eca[En * Bn * Cn];
__device__ float g_ecb[En * Bn * Cn];
__device__ float g_wts[16][En];
__device__ float g_s1[Bn * 8 * 2];
__device__ float g_c1a[Bn * HCn];
__device__ float g_c1b[Bn * HCn];
__device__ float g_s2[Bn * 8 * 2];
__device__ float g_c2a[Bn * HCn];
__device__ float g_c2b[Bn * HCn];
__device__ float g_s3[Bn * 8 * 2];
__device__ float g_c3a[Bn * Cn];
__device__ float g_c3b[Bn * Cn];

__device__ __forceinline__ float silu_f(float v) { return v / (1.f + __expf(-v)); }

__device__ __forceinline__ unsigned to_tf32(float f) {
    unsigned r;
    asm("cvt.rna.tf32.f32 %0, %1;" : "=r"(r) : "f"(f));
    return r;
}

__device__ __forceinline__ void mma_tf32(float& c0, float& c1, float& c2, float& c3,
                                         unsigned a0, unsigned a1, unsigned a2, unsigned a3,
                                         unsigned b0, unsigned b1) {
    asm volatile(
        "mma.sync.aligned.m16n8k8.row.col.f32.tf32.tf32.f32 "
        "{%0,%1,%2,%3}, {%4,%5,%6,%7}, {%8,%9}, {%0,%1,%2,%3};"
        : "+f"(c0), "+f"(c1), "+f"(c2), "+f"(c3)
        : "r"(a0), "r"(a1), "r"(a2), "r"(a3), "r"(b0), "r"(b1));
}

// ---- cp.async helpers ----
__device__ __forceinline__ void cpa16(unsigned dst, const void* src) {
    asm volatile("cp.async.cg.shared.global [%0], [%1], 16;" :: "r"(dst), "l"(src));
}
__device__ __forceinline__ void cpa4(unsigned dst, const void* src, int sz) {
    asm volatile("cp.async.ca.shared.global [%0], [%1], 4, %2;"
                 :: "r"(dst), "l"(src), "r"(sz));
}
__device__ __forceinline__ void cp_commit() {
    asm volatile("cp.async.commit_group;");
}

// ---------------- K0: zero the stats accumulators ----------------
__global__ void k_zero() {
    int i = blockIdx.x * 256 + threadIdx.x;
    if (i < En * Bn * 8 * 2) g_estats[i] = 0.f;
    if (i < Bn * 8 * 2) { g_s1[i] = 0.f; g_s2[i] = 0.f; g_s3[i] = 0.f; }
}

// ---------------- W preps ----------------
__global__ void k_wprep(const float* __restrict__ w_exp) {
    int i = blockIdx.x * 256 + threadIdx.x;
    if (i >= En * 16 * 9 * 8 * 128) return;
    int co = i & 127;
    int r = i >> 7;
    int ci = r & 7; r >>= 3;
    int tap = r % 9; r /= 9;
    int cc = r & 15;
    int e = r >> 4;
    g_wt[i] = to_tf32(w_exp[((size_t)(e * 128 + co) * 128 + cc * 8 + ci) * 9 + tap]);
}
__global__ void k_w1prep(const float* __restrict__ w_pw1) {
    int i = blockIdx.x * 256 + threadIdx.x;
    if (i >= 4 * 16 * 8 * 128) return;
    int hcl = i & 127;
    int ci = (i >> 7) & 7;
    int cc = (i >> 10) & 15;
    int blk = i >> 14;
    g_w1t[i] = to_tf32(w_pw1[(size_t)(blk * 128 + hcl) * 128 + cc * 8 + ci]);
}
__global__ void k_w2prep(const float* __restrict__ w_pw2) {
    int i = blockIdx.x * 256 + threadIdx.x;
    if (i >= 64 * 8 * 128) return;
    int co = i & 127;
    int ci = (i >> 7) & 7;
    int cc = i >> 10;
    g_w2t[i] = to_tf32(w_pw2[(size_t)co * 512 + cc * 8 + ci]);
}
__global__ void k_xprep(const float* __restrict__ x) {
    int i = blockIdx.x * 256 + threadIdx.x;
    g_xt[i] = to_tf32(x[i]);
}

// ---------------- K1: expert 3x3 conv via tf32 mma, cp.async double-buffered ----------------
// block: one (e,b), 64 co (half), 4 image rows (256 px). 8 warps = 2 co-groups x 4 rows.
// dynamic smem: 2 x (72*72 W + 3168 X) words = 66816 B. occupancy 2.
#define WS_STRIDE 72
#define WS_BUF (72 * WS_STRIDE)      // 5184 words
#define XS_BUF 3168                  // 8 ci * 6 rows * 66 cols
__global__ __launch_bounds__(256, 2) void k_expert() {
    extern __shared__ unsigned sm[];
    const int ty0 = blockIdx.x * 4;          // 16 tiles of 4 rows
    const int chb = blockIdx.y;              // co half: 0 or 1
    const int e = blockIdx.z >> 4;
    const int b = blockIdx.z & 15;

    const int tid = threadIdx.x;
    const int warp = tid >> 5;
    const int lane = tid & 31;
    const int wc = warp >> 2;                // co group within half (32 co)
    const int wp = warp & 3;                 // image row within strip
    const int grp = lane >> 2;
    const int tig = lane & 3;

    const unsigned smbase = (unsigned)__cvta_generic_to_shared(sm);

    float acc[2][8][4];
    #pragma unroll
    for (int mt = 0; mt < 2; mt++)
        #pragma unroll
        for (int nt = 0; nt < 8; nt++)
            #pragma unroll
            for (int q = 0; q < 4; q++) acc[mt][nt][q] = 0.f;

    const unsigned* wt = g_wt + (size_t)e * 147456 + chb * 64;
    const unsigned* xt = g_xt + (size_t)b * Cn * HWn;

    auto stage = [&](int cc, int buf) {
        // W half-chunk: 72 rows (tap,ci) x 64 co, 16B async copies
        const unsigned wsoff = buf * WS_BUF;
        for (int idx = tid; idx < 1152; idx += 256) {
            int rw = idx >> 4, q = idx & 15;
            cpa16(smbase + (wsoff + rw * WS_STRIDE + q * 4) * 4,
                  wt + (size_t)cc * 9216 + rw * 128 + q * 4);
        }
        // X halo: 8 ci x 6 rows x 66 cols, 4B async with zero-fill OOB
        const unsigned xsoff = 2 * WS_BUF + buf * XS_BUF;
        for (int idx = tid; idx < 3168; idx += 256) {
            int ci = idx / 396;
            int rem = idx - ci * 396;
            int row = rem / 66;
            int cx = rem - row * 66;
            int gy = ty0 - 1 + row, gx = cx - 1;
            bool ok = ((unsigned)gy < 64u) && ((unsigned)gx < 64u);
            const unsigned* g = ok ? (xt + (size_t)(cc * 8 + ci) * HWn + gy * 64 + gx)
                                   : xt;
            cpa4(smbase + (xsoff + (ci * 6 + row) * 66 + cx) * 4, g, ok ? 4 : 0);
        }
    };

    stage(0, 0);
    cp_commit();

    for (int cc = 0; cc < 16; cc++) {
        if (cc < 15) {
            stage(cc + 1, (cc + 1) & 1);
            cp_commit();
            asm volatile("cp.async.wait_group 1;");
        } else {
            asm volatile("cp.async.wait_group 0;");
        }
        __syncthreads();

        const unsigned* ws = sm + (cc & 1) * WS_BUF;
        const unsigned* xs = sm + 2 * WS_BUF + (cc & 1) * XS_BUF;

        #pragma unroll
        for (int tap = 0; tap < 9; tap++) {
            const int kh = tap / 3, kw = tap % 3;
            unsigned a0[2], a1[2], a2[2], a3[2];
            #pragma unroll
            for (int mt = 0; mt < 2; mt++) {
                int co_r = wc * 32 + mt * 16 + grp;
                a0[mt] = ws[(tap * 8 + tig) * WS_STRIDE + co_r];
                a1[mt] = ws[(tap * 8 + tig) * WS_STRIDE + co_r + 8];
                a2[mt] = ws[(tap * 8 + tig + 4) * WS_STRIDE + co_r];
                a3[mt] = ws[(tap * 8 + tig + 4) * WS_STRIDE + co_r + 8];
            }
            #pragma unroll
            for (int nt = 0; nt < 8; nt++) {
                int col = nt * 8 + grp + kw;
                unsigned b0 = xs[(tig * 6 + wp + kh) * 66 + col];
                unsigned b1 = xs[((tig + 4) * 6 + wp + kh) * 66 + col];
                mma_tf32(acc[0][nt][0], acc[0][nt][1], acc[0][nt][2], acc[0][nt][3],
                         a0[0], a1[0], a2[0], a3[0], b0, b1);
                mma_tf32(acc[1][nt][0], acc[1][nt][1], acc[1][nt][2], acc[1][nt][3],
                         a0[1], a1[1], a2[1], a3[1], b0, b1);
            }
        }
        __syncthreads();
    }

    // epilogue: write y + per-warp GN group stats
    size_t ybase = (size_t)(e * Bn + b) * Cn * HWn;
    const int row = ty0 + wp;
    float ls[2] = {0.f, 0.f}, lq[2] = {0.f, 0.f};
    #pragma unroll
    for (int mt = 0; mt < 2; mt++) {
        int co = chb * 64 + wc * 32 + mt * 16 + grp;
        #pragma unroll
        for (int nt = 0; nt < 8; nt++) {
            int colx = nt * 8 + 2 * tig;
            float2 v0 = make_float2(acc[mt][nt][0], acc[mt][nt][1]);
            float2 v1 = make_float2(acc[mt][nt][2], acc[mt][nt][3]);
            *(float2*)(g_y + ybase + (size_t)co * HWn + row * 64 + colx) = v0;
            *(float2*)(g_y + ybase + (size_t)(co + 8) * HWn + row * 64 + colx) = v1;
            ls[mt] += v0.x + v0.y + v1.x + v1.y;
            lq[mt] += v0.x * v0.x + v0.y * v0.y + v1.x * v1.x + v1.y * v1.y;
        }
    }
    #pragma unroll
    for (int mt = 0; mt < 2; mt++) {
        float s = ls[mt], q = lq[mt];
        #pragma unroll
        for (int off = 16; off > 0; off >>= 1) {
            s += __shfl_xor_sync(0xFFFFFFFFu, s, off);
            q += __shfl_xor_sync(0xFFFFFFFFu, q, off);
        }
        if (lane == 0) {
            int g = chb * 4 + wc * 2 + mt;
            atomicAdd(&g_estats[((e * Bn + b) * 8 + g) * 2], s);
            atomicAdd(&g_estats[((e * Bn + b) * 8 + g) * 2 + 1], q);
        }
    }
}

// ---------------- K2: finalize expert GN coefs + router softmax ----------------
__global__ void k_router_fin(const float* __restrict__ gns, const float* __restrict__ gnb,
                             const float* __restrict__ w1, const float* __restrict__ b1,
                             const float* __restrict__ w2, const float* __restrict__ b2) {
    int tid = threadIdx.x;
    for (int i = tid; i < En * Bn * Cn; i += 256) {
        int e = i >> 11, b = (i >> 7) & 15, c = i & 127, g = c >> 4;
        float s = g_estats[((e * Bn + b) * 8 + g) * 2];
        float sq = g_estats[((e * Bn + b) * 8 + g) * 2 + 1];
        float mean = s * (1.f / 65536.f);
        float var = sq * (1.f / 65536.f) - mean * mean;
        float rstd = rsqrtf(var + 1e-5f);
        float a = rstd * gns[e * Cn + c];
        g_eca[i] = a;
        g_ecb[i] = gnb[e * Cn + c] - mean * a;
    }
    if (tid < 16) {
        int py = tid >> 2, px = tid & 3;
        float fe[32];
        float cy = (py + 0.5f) * 0.25f, cx = (px + 0.5f) * 0.25f;
        #pragma unroll
        for (int k = 0; k < 8; k++) {
            float fr = (float)(1 << k) * 3.14159265358979323846f;
            fe[k] = sinf(cy * fr);
            fe[8 + k] = cosf(cy * fr);
            fe[16 + k] = sinf(cx * fr);
            fe[24 + k] = cosf(cx * fr);
        }
        float hb[64];
        for (int j = 0; j < 64; j++) {
            float s = b1[j];
            for (int k = 0; k < 32; k++) s = fmaf(fe[k], w1[k * 64 + j], s);
            hb[j] = s / (1.f + expf(-s));
        }
        float lo[8];
        float mx = -1e30f;
        for (int ee = 0; ee < 8; ee++) {
            float s = b2[ee];
            for (int j = 0; j < 64; j++) s = fmaf(hb[j], w2[j * 8 + ee], s);
            lo[ee] = s;
            mx = fmaxf(mx, s);
        }
        float den = 0.f;
        for (int ee = 0; ee < 8; ee++) { lo[ee] = expf(lo[ee] - mx); den += lo[ee]; }
        float inv = 1.f / den;
        for (int ee = 0; ee < 8; ee++) g_wts[tid][ee] = lo[ee] * inv;
    }
}

// ---------------- K3: combine experts -> tf32 bits ----------------
__global__ void k_combine(const float* __restrict__ x) {
    size_t t = (size_t)blockIdx.x * 256 + threadIdx.x;
    size_t i = t * 4;
    int b = (int)(i >> 19);
    int c = (int)(i >> 12) & 127;
    int p = (int)(i & 4095);
    int patch = ((p >> 6) >> 4) * 4 + ((p & 63) >> 4);
    float4 outv = *(const float4*)(x + i);
    #pragma unroll
    for (int e = 0; e < 8; e++) {
        int ebc = (e * Bn + b) * Cn + c;
        float a = g_eca[ebc], bb = g_ecb[ebc];
        float wt = g_wts[patch][e];
        float4 y = *(const float4*)(g_y + (size_t)ebc * HWn + p);
        outv.x += wt * silu_f(fmaf(y.x, a, bb));
        outv.y += wt * silu_f(fmaf(y.y, a, bb));
        outv.z += wt * silu_f(fmaf(y.z, a, bb));
        outv.w += wt * silu_f(fmaf(y.w, a, bb));
    }
    uint4 o;
    o.x = to_tf32(outv.x);
    o.y = to_tf32(outv.y);
    o.z = to_tf32(outv.z);
    o.w = to_tf32(outv.w);
    *(uint4*)(g_combt + i) = o;
}

// ---------------- K4: pw1 1x1 (128->512) via tf32 mma + gn1 stats ----------------
__global__ __launch_bounds__(256) void k_pw1m() {
    __shared__ unsigned As[8 * 136];
    __shared__ unsigned Bs[8 * 136];
    const int pxb = blockIdx.x * 128;
    const int hcb = blockIdx.y * 128;
    const int b = blockIdx.z;
    const int tid = threadIdx.x;
    const int warp = tid >> 5;
    const int lane = tid & 31;
    const int wc = warp >> 1;
    const int wpx = warp & 1;
    const int grp = lane >> 2;
    const int tig = lane & 3;

    float acc[2][8][4];
    #pragma unroll
    for (int mt = 0; mt < 2; mt++)
        #pragma unroll
        for (int nt = 0; nt < 8; nt++)
            #pragma unroll
            for (int q = 0; q < 4; q++) acc[mt][nt][q] = 0.f;

    for (int cc = 0; cc < 16; cc++) {
        {
            const uint4* srcA = (const uint4*)(g_w1t + (size_t)((blockIdx.y * 16 + cc) * 8) * 128);
            uint4 v = srcA[tid];
            *(uint4*)(As + (tid >> 5) * 136 + (tid & 31) * 4) = v;
        }
        {
            int r = tid >> 5;
            const uint4* srcB = (const uint4*)(g_combt + (size_t)(b * Cn + cc * 8 + r) * HWn + pxb);
            uint4 v = srcB[tid & 31];
            *(uint4*)(Bs + r * 136 + (tid & 31) * 4) = v;
        }
        __syncthreads();

        unsigned a0[2], a1[2], a2[2], a3[2];
        #pragma unroll
        for (int mt = 0; mt < 2; mt++) {
            int hc_r = wc * 32 + mt * 16 + grp;
            a0[mt] = As[tig * 136 + hc_r];
            a1[mt] = As[tig * 136 + hc_r + 8];
            a2[mt] = As[(tig + 4) * 136 + hc_r];
            a3[mt] = As[(tig + 4) * 136 + hc_r + 8];
        }
        #pragma unroll
        for (int nt = 0; nt < 8; nt++) {
            int col = wpx * 64 + nt * 8 + grp;
            unsigned b0 = Bs[tig * 136 + col];
            unsigned b1 = Bs[(tig + 4) * 136 + col];
            mma_tf32(acc[0][nt][0], acc[0][nt][1], acc[0][nt][2], acc[0][nt][3],
                     a0[0], a1[0], a2[0], a3[0], b0, b1);
            mma_tf32(acc[1][nt][0], acc[1][nt][1], acc[1][nt][2], acc[1][nt][3],
                     a0[1], a1[1], a2[1], a3[1], b0, b1);
        }
        __syncthreads();
    }

    #pragma unroll
    for (int mt = 0; mt < 2; mt++) {
        int hc0 = hcb + wc * 32 + mt * 16 + grp;
        float ls = 0.f, lq = 0.f;
        #pragma unroll
        for (int nt = 0; nt < 8; nt++) {
            int px = pxb + wpx * 64 + nt * 8 + 2 * tig;
            float2 v0 = make_float2(acc[mt][nt][0], acc[mt][nt][1]);
            float2 v1 = make_float2(acc[mt][nt][2], acc[mt][nt][3]);
            *(float2*)(g_h1 + (size_t)(b * HCn + hc0) * HWn + px) = v0;
            *(float2*)(g_h1 + (size_t)(b * HCn + hc0 + 8) * HWn + px) = v1;
            ls += v0.x + v0.y + v1.x + v1.y;
            lq += v0.x * v0.x + v0.y * v0.y + v1.x * v1.x + v1.y * v1.y;
        }
        #pragma unroll
        for (int off = 16; off > 0; off >>= 1) {
            ls += __shfl_xor_sync(0xFFFFFFFFu, ls, off);
            lq += __shfl_xor_sync(0xFFFFFFFFu, lq, off);
        }
        if (lane == 0) {
            int g = (hcb >> 6) + (wc >> 1);
            atomicAdd(&g_s1[(b * 8 + g) * 2], ls);
            atomicAdd(&g_s1[(b * 8 + g) * 2 + 1], lq);
        }
    }
}

// ---------------- finalize kernels ----------------
__global__ void k_fin1(const float* __restrict__ s, const float* __restrict__ bias) {
    int i = blockIdx.x * 256 + threadIdx.x;
    if (i >= Bn * HCn) return;
    int b = i / HCn, c = i % HCn, g = c >> 6;
    float su = g_s1[(b * 8 + g) * 2], sq = g_s1[(b * 8 + g) * 2 + 1];
    float mean = su * (1.f / 262144.f);
    float var = sq * (1.f / 262144.f) - mean * mean;
    float rstd = rsqrtf(var + 1e-5f);
    float a = rstd * s[c];
    g_c1a[i] = a;
    g_c1b[i] = bias[c] - mean * a;
}
__global__ void k_fin2(const float* __restrict__ s, const float* __restrict__ bias) {
    int i = blockIdx.x * 256 + threadIdx.x;
    if (i >= Bn * HCn) return;
    int b = i / HCn, c = i % HCn, g = c >> 6;
    float su = g_s2[(b * 8 + g) * 2], sq = g_s2[(b * 8 + g) * 2 + 1];
    float mean = su * (1.f / 262144.f);
    float var = sq * (1.f / 262144.f) - mean * mean;
    float rstd = rsqrtf(var + 1e-5f);
    float a = rstd * s[c];
    g_c2a[i] = a;
    g_c2b[i] = bias[c] - mean * a;
}
__global__ void k_fin3(const float* __restrict__ s, const float* __restrict__ bias) {
    int i = blockIdx.x * 256 + threadIdx.x;
    if (i >= Bn * Cn) return;
    int b = i / Cn, c = i % Cn, g = c >> 4;
    float su = g_s3[(b * 8 + g) * 2], sq = g_s3[(b * 8 + g) * 2 + 1];
    float mean = su * (1.f / 16384.f);
    float var = sq * (1.f / 16384.f) - mean * mean;
    float rstd = rsqrtf(var + 1e-5f);
    float a = rstd * s[c];
    g_c3a[i] = a;
    g_c3b[i] = bias[c] - mean * a;
}

// ---------------- K5: depthwise 3x3 on silu(gn1(h1)) + gn2 stats ----------------
__global__ __launch_bounds__(256) void k_dw(const float* __restrict__ w_dw) {
    int rt = blockIdx.x;
    int hc = blockIdx.y;
    int b = blockIdx.z;
    __shared__ float xs[18][66];
    __shared__ float sred[2];
    int tid = threadIdx.x;
    float a = g_c1a[b * HCn + hc], bb = g_c1b[b * HCn + hc];
    const float* src = g_h1 + (size_t)(b * HCn + hc) * HWn;
    int r0 = rt * 16;
    for (int idx = tid; idx < 18 * 66; idx += 256) {
        int rr = idx / 66, cx = idx % 66;
        int gy = r0 - 1 + rr, gx = cx - 1;
        float v = 0.f;
        if ((unsigned)gy < 64u && (unsigned)gx < 64u)
            v = silu_f(fmaf(src[gy * 64 + gx], a, bb));
        xs[rr][cx] = v;
    }
    float wd[9];
    #pragma unroll
    for (int t9 = 0; t9 < 9; t9++) wd[t9] = __ldg(&w_dw[hc * 9 + t9]);
    __syncthreads();
    float lsum = 0.f, lsq = 0.f;
    float* dst = g_h2 + (size_t)(b * HCn + hc) * HWn;
    #pragma unroll
    for (int k4 = 0; k4 < 4; k4++) {
        int idx = tid + k4 * 256;
        int row = idx >> 6, col = idx & 63;
        float sum = 0.f;
        #pragma unroll
        for (int kh = 0; kh < 3; kh++)
            #pragma unroll
            for (int kw = 0; kw < 3; kw++)
                sum = fmaf(wd[kh * 3 + kw], xs[row + kh][col + kw], sum);
        dst[(r0 + row) * 64 + col] = sum;
        lsum += sum;
        lsq += sum * sum;
    }
    if (tid < 2) sred[tid] = 0.f;
    __syncthreads();
    atomicAdd(&sred[0], lsum);
    atomicAdd(&sred[1], lsq);
    __syncthreads();
    if (tid == 0) {
        int g = hc >> 6;
        atomicAdd(&g_s2[(b * 8 + g) * 2], sred[0]);
        atomicAdd(&g_s2[(b * 8 + g) * 2 + 1], sred[1]);
    }
}

// ---------------- K6: pw2 1x1 stride-2 (512->128) via tf32 mma + gn3 stats ----------------
__global__ __launch_bounds__(256) void k_pw2m() {
    __shared__ unsigned As[8 * 136];
    __shared__ unsigned Bs[8 * 136];
    const int pxb = blockIdx.x * 128;
    const int b = blockIdx.z;
    const int tid = threadIdx.x;
    const int warp = tid >> 5;
    const int lane = tid & 31;
    const int wc = warp >> 1;
    const int wpx = warp & 1;
    const int grp = lane >> 2;
    const int tig = lane & 3;

    float acc[2][8][4];
    #pragma unroll
    for (int mt = 0; mt < 2; mt++)
        #pragma unroll
        for (int nt = 0; nt < 8; nt++)
            #pragma unroll
            for (int q = 0; q < 4; q++) acc[mt][nt][q] = 0.f;

    for (int cc = 0; cc < 64; cc++) {
        {
            const uint4* srcA = (const uint4*)(g_w2t + (size_t)cc * 1024);
            uint4 v = srcA[tid];
            *(uint4*)(As + (tid >> 5) * 136 + (tid & 31) * 4) = v;
        }
        {
            int r = tid >> 5;
            int ch = cc * 8 + r;
            float a = g_c2a[b * HCn + ch], bb = g_c2b[b * HCn + ch];
            const float* src = g_h2 + (size_t)(b * HCn + ch) * HWn;
            int i0 = (lane) * 4;
            #pragma unroll
            for (int j = 0; j < 4; j++) {
                int p = pxb + i0 + j;
                int oh = p >> 5, ow = p & 31;
                float v = silu_f(fmaf(src[oh * 128 + ow * 2], a, bb));
                Bs[r * 136 + i0 + j] = to_tf32(v);
            }
        }
        __syncthreads();

        unsigned a0[2], a1[2], a2[2], a3[2];
        #pragma unroll
        for (int mt = 0; mt < 2; mt++) {
            int co_r = wc * 32 + mt * 16 + grp;
            a0[mt] = As[tig * 136 + co_r];
            a1[mt] = As[tig * 136 + co_r + 8];
            a2[mt] = As[(tig + 4) * 136 + co_r];
            a3[mt] = As[(tig + 4) * 136 + co_r + 8];
        }
        #pragma unroll
        for (int nt = 0; nt < 8; nt++) {
            int col = wpx * 64 + nt * 8 + grp;
            unsigned b0 = Bs[tig * 136 + col];
            unsigned b1 = Bs[(tig + 4) * 136 + col];
            mma_tf32(acc[0][nt][0], acc[0][nt][1], acc[0][nt][2], acc[0][nt][3],
                     a0[0], a1[0], a2[0], a3[0], b0, b1);
            mma_tf32(acc[1][nt][0], acc[1][nt][1], acc[1][nt][2], acc[1][nt][3],
                     a0[1], a1[1], a2[1], a3[1], b0, b1);
        }
        __syncthreads();
    }

    #pragma unroll
    for (int mt = 0; mt < 2; mt++) {
        int co0 = wc * 32 + mt * 16 + grp;
        float ls = 0.f, lq = 0.f;
        #pragma unroll
        for (int nt = 0; nt < 8; nt++) {
            int px = pxb + wpx * 64 + nt * 8 + 2 * tig;
            float2 v0 = make_float2(acc[mt][nt][0], acc[mt][nt][1]);
            float2 v1 = make_float2(acc[mt][nt][2], acc[mt][nt][3]);
            *(float2*)(g_o + (size_t)(b * Cn + co0) * OHWn + px) = v0;
            *(float2*)(g_o + (size_t)(b * Cn + co0 + 8) * OHWn + px) = v1;
            ls += v0.x + v0.y + v1.x + v1.y;
            lq += v0.x * v0.x + v0.y * v0.y + v1.x * v1.x + v1.y * v1.y;
        }
        #pragma unroll
        for (int off = 16; off > 0; off >>= 1) {
            ls += __shfl_xor_sync(0xFFFFFFFFu, ls, off);
            lq += __shfl_xor_sync(0xFFFFFFFFu, lq, off);
        }
        if (lane == 0) {
            int g = wc * 2 + mt;
            atomicAdd(&g_s3[(b * 8 + g) * 2], ls);
            atomicAdd(&g_s3[(b * 8 + g) * 2 + 1], lq);
        }
    }
}

// ---------------- K7: final gn3 + silu ----------------
__global__ void k_out(float* __restrict__ out) {
    int i = blockIdx.x * 256 + threadIdx.x;
    int b = i >> 17;
    int c = (i >> 10) & 127;
    out[i] = silu_f(fmaf(g_o[i], g_c3a[b * Cn + c], g_c3b[b * Cn + c]));
}

// ---------------- launch ----------------
extern "C" void kernel_launch(void* const* d_in, const int* in_sizes, int n_in,
                              void* d_out, int out_size) {
    const float* x      = (const float*)d_in[0];
    const float* w_exp  = (const float*)d_in[1];
    const float* gns    = (const float*)d_in[2];
    const float* gnb    = (const float*)d_in[3];
    const float* w1     = (const float*)d_in[4];
    const float* b1     = (const float*)d_in[5];
    const float* w2     = (const float*)d_in[6];
    const float* b2     = (const float*)d_in[7];
    const float* w_pw1  = (const float*)d_in[8];
    const float* gn1s   = (const float*)d_in[9];
    const float* gn1b   = (const float*)d_in[10];
    const float* w_dw   = (const float*)d_in[11];
    const float* gn2s   = (const float*)d_in[12];
    const float* gn2b   = (const float*)d_in[13];
    const float* w_pw2  = (const float*)d_in[14];
    const float* gn3s   = (const float*)d_in[15];
    const float* gn3b   = (const float*)d_in[16];
    float* out = (float*)d_out;

    const int expert_smem = (2 * WS_BUF + 2 * XS_BUF) * 4;   // 66816 B
    cudaFuncSetAttribute(k_expert, cudaFuncAttributeMaxDynamicSharedMemorySize,
                         expert_smem);

    // order chosen so k_expert is the 4th launch (ncu window captures slot 4)
    k_zero<<<8, 256>>>();
    k_wprep<<<(En * 16 * 9 * 8 * 128 + 255) / 256, 256>>>(w_exp);
    k_xprep<<<(Bn * Cn * HWn) / 256, 256>>>(x);
    {
        dim3 g(16, 2, En * Bn);
        k_expert<<<g, 256, expert_smem>>>();
    }
    k_w1prep<<<(4 * 16 * 8 * 128 + 255) / 256, 256>>>(w_pw1);
    k_w2prep<<<(64 * 8 * 128 + 255) / 256, 256>>>(w_pw2);
    k_router_fin<<<1, 256>>>(gns, gnb, w1, b1, w2, b2);
    k_combine<<<8192, 256>>>(x);
    {
        dim3 g(32, 4, Bn);
        k_pw1m<<<g, 256>>>();
    }
    k_fin1<<<(Bn * HCn + 255) / 256, 256>>>(gn1s, gn1b);
    {
        dim3 g(4, HCn, Bn);
        k_dw<<<g, 256>>>(w_dw);
    }
    k_fin2<<<(Bn * HCn + 255) / 256, 256>>>(gn2s, gn2b);
    {
        dim3 g(8, 1, Bn);
        k_pw2m<<<g, 256>>>();
    }
    k_fin3<<<(Bn * Cn + 255) / 256, 256>>>(gn3s, gn3b);
    k_out<<<8192, 256>>>(out);
}

// round 10
// speedup vs baseline: 1.5071x; 1.1620x over previous
#include <cuda_runtime.h>
#include <math.h>

#define En 8
#define Bn 16
#define Cn 128
#define Hn 64
#define Wn 64
#define HWn 4096
#define HCn 512
#define OHWn 1024

// ---------------- scratch (device globals; no allocation) ----------------
__device__ float g_y[(size_t)En * Bn * Cn * HWn];
__device__ unsigned g_combt[(size_t)Bn * Cn * HWn];    // combined, tf32 bits
__device__ float g_h1[(size_t)Bn * HCn * HWn];
__device__ float g_h2[(size_t)Bn * HCn * HWn];
__device__ float g_o[(size_t)Bn * Cn * OHWn];
__device__ unsigned g_wt[(size_t)En * 16 * 9 * 8 * 128];   // expert W tf32 staging order
__device__ unsigned g_w1t[(size_t)4 * 16 * 8 * 128];       // pw1 W tf32 staging order
__device__ unsigned g_w2t[(size_t)64 * 8 * 128];           // pw2 W tf32 staging order
__device__ unsigned g_xt[(size_t)Bn * Cn * HWn];           // x as tf32 bits
__device__ float g_estats[En * Bn * 8 * 2];
__device__ float g_eca[En * Bn * Cn];
__device__ float g_ecb[En * Bn * Cn];
__device__ float g_wts[16][En];
__device__ float g_s1[Bn * 8 * 2];
__device__ float g_c1a[Bn * HCn];
__device__ float g_c1b[Bn * HCn];
__device__ float g_s2[Bn * 8 * 2];
__device__ float g_c2a[Bn * HCn];
__device__ float g_c2b[Bn * HCn];
__device__ float g_s3[Bn * 8 * 2];
__device__ float g_c3a[Bn * Cn];
__device__ float g_c3b[Bn * Cn];

__device__ __forceinline__ float silu_f(float v) { return v / (1.f + __expf(-v)); }

__device__ __forceinline__ unsigned to_tf32(float f) {
    unsigned r;
    asm("cvt.rna.tf32.f32 %0, %1;" : "=r"(r) : "f"(f));
    return r;
}

__device__ __forceinline__ void mma_tf32(float& c0, float& c1, float& c2, float& c3,
                                         unsigned a0, unsigned a1, unsigned a2, unsigned a3,
                                         unsigned b0, unsigned b1) {
    asm volatile(
        "mma.sync.aligned.m16n8k8.row.col.f32.tf32.tf32.f32 "
        "{%0,%1,%2,%3}, {%4,%5,%6,%7}, {%8,%9}, {%0,%1,%2,%3};"
        : "+f"(c0), "+f"(c1), "+f"(c2), "+f"(c3)
        : "r"(a0), "r"(a1), "r"(a2), "r"(a3), "r"(b0), "r"(b1));
}

// ---- cp.async helpers ----
__device__ __forceinline__ void cpa16(unsigned dst, const void* src) {
    asm volatile("cp.async.cg.shared.global [%0], [%1], 16;" :: "r"(dst), "l"(src));
}
__device__ __forceinline__ void cpa16z(unsigned dst, const void* src, int sz) {
    asm volatile("cp.async.cg.shared.global [%0], [%1], 16, %2;"
                 :: "r"(dst), "l"(src), "r"(sz));
}
__device__ __forceinline__ void cp_commit() {
    asm volatile("cp.async.commit_group;");
}

// ---------------- K0: zero the stats accumulators ----------------
__global__ void k_zero() {
    int i = blockIdx.x * 256 + threadIdx.x;
    if (i < En * Bn * 8 * 2) g_estats[i] = 0.f;
    if (i < Bn * 8 * 2) { g_s1[i] = 0.f; g_s2[i] = 0.f; g_s3[i] = 0.f; }
}

// ---------------- W preps ----------------
__global__ void k_wprep(const float* __restrict__ w_exp) {
    int i = blockIdx.x * 256 + threadIdx.x;
    if (i >= En * 16 * 9 * 8 * 128) return;
    int co = i & 127;
    int r = i >> 7;
    int ci = r & 7; r >>= 3;
    int tap = r % 9; r /= 9;
    int cc = r & 15;
    int e = r >> 4;
    g_wt[i] = to_tf32(w_exp[((size_t)(e * 128 + co) * 128 + cc * 8 + ci) * 9 + tap]);
}
__global__ void k_w1prep(const float* __restrict__ w_pw1) {
    int i = blockIdx.x * 256 + threadIdx.x;
    if (i >= 4 * 16 * 8 * 128) return;
    int hcl = i & 127;
    int ci = (i >> 7) & 7;
    int cc = (i >> 10) & 15;
    int blk = i >> 14;
    g_w1t[i] = to_tf32(w_pw1[(size_t)(blk * 128 + hcl) * 128 + cc * 8 + ci]);
}
__global__ void k_w2prep(const float* __restrict__ w_pw2) {
    int i = blockIdx.x * 256 + threadIdx.x;
    if (i >= 64 * 8 * 128) return;
    int co = i & 127;
    int ci = (i >> 7) & 7;
    int cc = i >> 10;
    g_w2t[i] = to_tf32(w_pw2[(size_t)co * 512 + cc * 8 + ci]);
}
__global__ void k_xprep(const float* __restrict__ x) {
    int i = blockIdx.x * 256 + threadIdx.x;
    g_xt[i] = to_tf32(x[i]);
}

// ---------------- K1: expert 3x3 conv via tf32 mma, cp.async double-buffered ----------------
// block: one (e,b), 64 co (half), 4 image rows (256 px). 8 warps = 2 co-groups x 4 rows.
// X smem row stride 76 words: core (gx 0..63) at words 4..67, halos at 3 and 68 (always 0).
// dynamic smem: 2*(5184 W + 3648 X) words = 70656 B. occupancy 2.
#define WS_STRIDE 72
#define WS_BUF (72 * WS_STRIDE)      // 5184 words
#define XR_STRIDE 76
#define XS_BUF (48 * XR_STRIDE)      // 3648 words (8 ci * 6 rows)
__global__ __launch_bounds__(256, 2) void k_expert() {
    extern __shared__ unsigned sm[];
    const int ty0 = blockIdx.x * 4;          // 16 tiles of 4 rows
    const int chb = blockIdx.y;              // co half: 0 or 1
    const int e = blockIdx.z >> 4;
    const int b = blockIdx.z & 15;

    const int tid = threadIdx.x;
    const int warp = tid >> 5;
    const int lane = tid & 31;
    const int wc = warp >> 2;                // co group within half (32 co)
    const int wp = warp & 3;                 // image row within strip
    const int grp = lane >> 2;
    const int tig = lane & 3;

    const unsigned smbase = (unsigned)__cvta_generic_to_shared(sm);

    float acc[2][8][4];
    #pragma unroll
    for (int mt = 0; mt < 2; mt++)
        #pragma unroll
        for (int nt = 0; nt < 8; nt++)
            #pragma unroll
            for (int q = 0; q < 4; q++) acc[mt][nt][q] = 0.f;

    const unsigned* wt = g_wt + (size_t)e * 147456 + chb * 64;
    const unsigned* xt = g_xt + (size_t)b * Cn * HWn;

    // zero the always-OOB halo columns (words 3 and 68 of each X row), both buffers.
    // 96 slots = 2 buffers x 48 rows; threads 0..95 each take one slot.
    if (tid < 96) {
        int buf = tid / 48;
        int r = tid - buf * 48;
        sm[2 * WS_BUF + buf * XS_BUF + r * XR_STRIDE + 3] = 0u;
        sm[2 * WS_BUF + buf * XS_BUF + r * XR_STRIDE + 68] = 0u;
    }
    __syncthreads();

    auto stage = [&](int cc, int buf) {
        // W half-chunk: 72 rows (tap,ci) x 64 co, 16B async copies
        const unsigned wsoff = buf * WS_BUF;
        #pragma unroll
        for (int it = 0; it < 5; it++) {
            int idx = tid + it * 256;
            if (idx < 1152) {
                int rw = idx >> 4, q = idx & 15;
                cpa16(smbase + (wsoff + rw * WS_STRIDE + q * 4) * 4,
                      wt + (size_t)cc * 9216 + rw * 128 + q * 4);
            }
        }
        // X: warp = ci, lanes 0..15 = 16B core chunks, 6 halo rows
        const unsigned xsoff = 2 * WS_BUF + buf * XS_BUF;
        if (lane < 16) {
            const unsigned* src = xt + (size_t)(cc * 8 + warp) * HWn + (ty0 - 1) * 64 + lane * 4;
            #pragma unroll
            for (int rr = 0; rr < 6; rr++) {
                int gy = ty0 - 1 + rr;
                bool ok = (unsigned)gy < 64u;
                cpa16z(smbase + (xsoff + (warp * 6 + rr) * XR_STRIDE + 4 + lane * 4) * 4,
                       ok ? (const void*)(src + rr * 64) : (const void*)xt, ok ? 16 : 0);
            }
        }
    };

    stage(0, 0);
    cp_commit();

    for (int cc = 0; cc < 16; cc++) {
        if (cc < 15) {
            stage(cc + 1, (cc + 1) & 1);
            cp_commit();
            asm volatile("cp.async.wait_group 1;");
        } else {
            asm volatile("cp.async.wait_group 0;");
        }
        __syncthreads();

        const unsigned* ws = sm + (cc & 1) * WS_BUF;
        const unsigned* xs = sm + 2 * WS_BUF + (cc & 1) * XS_BUF;

        #pragma unroll
        for (int tap = 0; tap < 9; tap++) {
            const int kh = tap / 3, kw = tap % 3;
            unsigned a0[2], a1[2], a2[2], a3[2];
            #pragma unroll
            for (int mt = 0; mt < 2; mt++) {
                int co_r = wc * 32 + mt * 16 + grp;
                a0[mt] = ws[(tap * 8 + tig) * WS_STRIDE + co_r];
                a1[mt] = ws[(tap * 8 + tig) * WS_STRIDE + co_r + 8];
                a2[mt] = ws[(tap * 8 + tig + 4) * WS_STRIDE + co_r];
                a3[mt] = ws[(tap * 8 + tig + 4) * WS_STRIDE + co_r + 8];
            }
            #pragma unroll
            for (int nt = 0; nt < 8; nt++) {
                int col = 3 + nt * 8 + grp + kw;
                unsigned b0 = xs[(tig * 6 + wp + kh) * XR_STRIDE + col];
                unsigned b1 = xs[((tig + 4) * 6 + wp + kh) * XR_STRIDE + col];
                mma_tf32(acc[0][nt][0], acc[0][nt][1], acc[0][nt][2], acc[0][nt][3],
                         a0[0], a1[0], a2[0], a3[0], b0, b1);
                mma_tf32(acc[1][nt][0], acc[1][nt][1], acc[1][nt][2], acc[1][nt][3],
                         a0[1], a1[1], a2[1], a3[1], b0, b1);
            }
        }
        __syncthreads();
    }

    // epilogue: write y + per-warp GN group stats
    size_t ybase = (size_t)(e * Bn + b) * Cn * HWn;
    const int row = ty0 + wp;
    float ls[2] = {0.f, 0.f}, lq[2] = {0.f, 0.f};
    #pragma unroll
    for (int mt = 0; mt < 2; mt++) {
        int co = chb * 64 + wc * 32 + mt * 16 + grp;
        #pragma unroll
        for (int nt = 0; nt < 8; nt++) {
            int colx = nt * 8 + 2 * tig;
            float2 v0 = make_float2(acc[mt][nt][0], acc[mt][nt][1]);
            float2 v1 = make_float2(acc[mt][nt][2], acc[mt][nt][3]);
            *(float2*)(g_y + ybase + (size_t)co * HWn + row * 64 + colx) = v0;
            *(float2*)(g_y + ybase + (size_t)(co + 8) * HWn + row * 64 + colx) = v1;
            ls[mt] += v0.x + v0.y + v1.x + v1.y;
            lq[mt] += v0.x * v0.x + v0.y * v0.y + v1.x * v1.x + v1.y * v1.y;
        }
    }
    #pragma unroll
    for (int mt = 0; mt < 2; mt++) {
        float s = ls[mt], q = lq[mt];
        #pragma unroll
        for (int off = 16; off > 0; off >>= 1) {
            s += __shfl_xor_sync(0xFFFFFFFFu, s, off);
            q += __shfl_xor_sync(0xFFFFFFFFu, q, off);
        }
        if (lane == 0) {
            int g = chb * 4 + wc * 2 + mt;
            atomicAdd(&g_estats[((e * Bn + b) * 8 + g) * 2], s);
            atomicAdd(&g_estats[((e * Bn + b) * 8 + g) * 2 + 1], q);
        }
    }
}

// ---------------- K2: finalize expert GN coefs + router softmax ----------------
__global__ void k_router_fin(const float* __restrict__ gns, const float* __restrict__ gnb,
                             const float* __restrict__ w1, const float* __restrict__ b1,
                             const float* __restrict__ w2, const float* __restrict__ b2) {
    int tid = threadIdx.x;
    for (int i = tid; i < En * Bn * Cn; i += 256) {
        int e = i >> 11, b = (i >> 7) & 15, c = i & 127, g = c >> 4;
        float s = g_estats[((e * Bn + b) * 8 + g) * 2];
        float sq = g_estats[((e * Bn + b) * 8 + g) * 2 + 1];
        float mean = s * (1.f / 65536.f);
        float var = sq * (1.f / 65536.f) - mean * mean;
        float rstd = rsqrtf(var + 1e-5f);
        float a = rstd * gns[e * Cn + c];
        g_eca[i] = a;
        g_ecb[i] = gnb[e * Cn + c] - mean * a;
    }
    if (tid < 16) {
        int py = tid >> 2, px = tid & 3;
        float fe[32];
        float cy = (py + 0.5f) * 0.25f, cx = (px + 0.5f) * 0.25f;
        #pragma unroll
        for (int k = 0; k < 8; k++) {
            float fr = (float)(1 << k) * 3.14159265358979323846f;
            fe[k] = sinf(cy * fr);
            fe[8 + k] = cosf(cy * fr);
            fe[16 + k] = sinf(cx * fr);
            fe[24 + k] = cosf(cx * fr);
        }
        float hb[64];
        for (int j = 0; j < 64; j++) {
            float s = b1[j];
            for (int k = 0; k < 32; k++) s = fmaf(fe[k], w1[k * 64 + j], s);
            hb[j] = s / (1.f + expf(-s));
        }
        float lo[8];
        float mx = -1e30f;
        for (int ee = 0; ee < 8; ee++) {
            float s = b2[ee];
            for (int j = 0; j < 64; j++) s = fmaf(hb[j], w2[j * 8 + ee], s);
            lo[ee] = s;
            mx = fmaxf(mx, s);
        }
        float den = 0.f;
        for (int ee = 0; ee < 8; ee++) { lo[ee] = expf(lo[ee] - mx); den += lo[ee]; }
        float inv = 1.f / den;
        for (int ee = 0; ee < 8; ee++) g_wts[tid][ee] = lo[ee] * inv;
    }
}

// ---------------- K3: combine experts -> tf32 bits ----------------
__global__ void k_combine(const float* __restrict__ x) {
    size_t t = (size_t)blockIdx.x * 256 + threadIdx.x;
    size_t i = t * 4;
    int b = (int)(i >> 19);
    int c = (int)(i >> 12) & 127;
    int p = (int)(i & 4095);
    int patch = ((p >> 6) >> 4) * 4 + ((p & 63) >> 4);
    float4 outv = *(const float4*)(x + i);
    #pragma unroll
    for (int e = 0; e < 8; e++) {
        int ebc = (e * Bn + b) * Cn + c;
        float a = g_eca[ebc], bb = g_ecb[ebc];
        float wt = g_wts[patch][e];
        float4 y = *(const float4*)(g_y + (size_t)ebc * HWn + p);
        outv.x += wt * silu_f(fmaf(y.x, a, bb));
        outv.y += wt * silu_f(fmaf(y.y, a, bb));
        outv.z += wt * silu_f(fmaf(y.z, a, bb));
        outv.w += wt * silu_f(fmaf(y.w, a, bb));
    }
    uint4 o;
    o.x = to_tf32(outv.x);
    o.y = to_tf32(outv.y);
    o.z = to_tf32(outv.z);
    o.w = to_tf32(outv.w);
    *(uint4*)(g_combt + i) = o;
}

// ---------------- K4: pw1 1x1 (128->512) via tf32 mma + gn1 stats ----------------
__global__ __launch_bounds__(256) void k_pw1m() {
    __shared__ unsigned As[8 * 136];
    __shared__ unsigned Bs[8 * 136];
    const int pxb = blockIdx.x * 128;
    const int hcb = blockIdx.y * 128;
    const int b = blockIdx.z;
    const int tid = threadIdx.x;
    const int warp = tid >> 5;
    const int lane = tid & 31;
    const int wc = warp >> 1;
    const int wpx = warp & 1;
    const int grp = lane >> 2;
    const int tig = lane & 3;

    float acc[2][8][4];
    #pragma unroll
    for (int mt = 0; mt < 2; mt++)
        #pragma unroll
        for (int nt = 0; nt < 8; nt++)
            #pragma unroll
            for (int q = 0; q < 4; q++) acc[mt][nt][q] = 0.f;

    for (int cc = 0; cc < 16; cc++) {
        {
            const uint4* srcA = (const uint4*)(g_w1t + (size_t)((blockIdx.y * 16 + cc) * 8) * 128);
            uint4 v = srcA[tid];
            *(uint4*)(As + (tid >> 5) * 136 + (tid & 31) * 4) = v;
        }
        {
            int r = tid >> 5;
            const uint4* srcB = (const uint4*)(g_combt + (size_t)(b * Cn + cc * 8 + r) * HWn + pxb);
            uint4 v = srcB[tid & 31];
            *(uint4*)(Bs + r * 136 + (tid & 31) * 4) = v;
        }
        __syncthreads();

        unsigned a0[2], a1[2], a2[2], a3[2];
        #pragma unroll
        for (int mt = 0; mt < 2; mt++) {
            int hc_r = wc * 32 + mt * 16 + grp;
            a0[mt] = As[tig * 136 + hc_r];
            a1[mt] = As[tig * 136 + hc_r + 8];
            a2[mt] = As[(tig + 4) * 136 + hc_r];
            a3[mt] = As[(tig + 4) * 136 + hc_r + 8];
        }
        #pragma unroll
        for (int nt = 0; nt < 8; nt++) {
            int col = wpx * 64 + nt * 8 + grp;
            unsigned b0 = Bs[tig * 136 + col];
            unsigned b1 = Bs[(tig + 4) * 136 + col];
            mma_tf32(acc[0][nt][0], acc[0][nt][1], acc[0][nt][2], acc[0][nt][3],
                     a0[0], a1[0], a2[0], a3[0], b0, b1);
            mma_tf32(acc[1][nt][0], acc[1][nt][1], acc[1][nt][2], acc[1][nt][3],
                     a0[1], a1[1], a2[1], a3[1], b0, b1);
        }
        __syncthreads();
    }

    #pragma unroll
    for (int mt = 0; mt < 2; mt++) {
        int hc0 = hcb + wc * 32 + mt * 16 + grp;
        float ls = 0.f, lq = 0.f;
        #pragma unroll
        for (int nt = 0; nt < 8; nt++) {
            int px = pxb + wpx * 64 + nt * 8 + 2 * tig;
            float2 v0 = make_float2(acc[mt][nt][0], acc[mt][nt][1]);
            float2 v1 = make_float2(acc[mt][nt][2], acc[mt][nt][3]);
            *(float2*)(g_h1 + (size_t)(b * HCn + hc0) * HWn + px) = v0;
            *(float2*)(g_h1 + (size_t)(b * HCn + hc0 + 8) * HWn + px) = v1;
            ls += v0.x + v0.y + v1.x + v1.y;
            lq += v0.x * v0.x + v0.y * v0.y + v1.x * v1.x + v1.y * v1.y;
        }
        #pragma unroll
        for (int off = 16; off > 0; off >>= 1) {
            ls += __shfl_xor_sync(0xFFFFFFFFu, ls, off);
            lq += __shfl_xor_sync(0xFFFFFFFFu, lq, off);
        }
        if (lane == 0) {
            int g = (hcb >> 6) + (wc >> 1);
            atomicAdd(&g_s1[(b * 8 + g) * 2], ls);
            atomicAdd(&g_s1[(b * 8 + g) * 2 + 1], lq);
        }
    }
}

// ---------------- finalize kernels ----------------
__global__ void k_fin1(const float* __restrict__ s, const float* __restrict__ bias) {
    int i = blockIdx.x * 256 + threadIdx.x;
    if (i >= Bn * HCn) return;
    int b = i / HCn, c = i % HCn, g = c >> 6;
    float su = g_s1[(b * 8 + g) * 2], sq = g_s1[(b * 8 + g) * 2 + 1];
    float mean = su * (1.f / 262144.f);
    float var = sq * (1.f / 262144.f) - mean * mean;
    float rstd = rsqrtf(var + 1e-5f);
    float a = rstd * s[c];
    g_c1a[i] = a;
    g_c1b[i] = bias[c] - mean * a;
}
__global__ void k_fin2(const float* __restrict__ s, const float* __restrict__ bias) {
    int i = blockIdx.x * 256 + threadIdx.x;
    if (i >= Bn * HCn) return;
    int b = i / HCn, c = i % HCn, g = c >> 6;
    float su = g_s2[(b * 8 + g) * 2], sq = g_s2[(b * 8 + g) * 2 + 1];
    float mean = su * (1.f / 262144.f);
    float var = sq * (1.f / 262144.f) - mean * mean;
    float rstd = rsqrtf(var + 1e-5f);
    float a = rstd * s[c];
    g_c2a[i] = a;
    g_c2b[i] = bias[c] - mean * a;
}
__global__ void k_fin3(const float* __restrict__ s, const float* __restrict__ bias) {
    int i = blockIdx.x * 256 + threadIdx.x;
    if (i >= Bn * Cn) return;
    int b = i / Cn, c = i % Cn, g = c >> 4;
    float su = g_s3[(b * 8 + g) * 2], sq = g_s3[(b * 8 + g) * 2 + 1];
    float mean = su * (1.f / 16384.f);
    float var = sq * (1.f / 16384.f) - mean * mean;
    float rstd = rsqrtf(var + 1e-5f);
    float a = rstd * s[c];
    g_c3a[i] = a;
    g_c3b[i] = bias[c] - mean * a;
}

// ---------------- K5: depthwise 3x3 on silu(gn1(h1)) + gn2 stats ----------------
__global__ __launch_bounds__(256) void k_dw(const float* __restrict__ w_dw) {
    int rt = blockIdx.x;
    int hc = blockIdx.y;
    int b = blockIdx.z;
    __shared__ float xs[18][66];
    __shared__ float sred[2];
    int tid = threadIdx.x;
    float a = g_c1a[b * HCn + hc], bb = g_c1b[b * HCn + hc];
    const float* src = g_h1 + (size_t)(b * HCn + hc) * HWn;
    int r0 = rt * 16;
    for (int idx = tid; idx < 18 * 66; idx += 256) {
        int rr = idx / 66, cx = idx % 66;
        int gy = r0 - 1 + rr, gx = cx - 1;
        float v = 0.f;
        if ((unsigned)gy < 64u && (unsigned)gx < 64u)
            v = silu_f(fmaf(src[gy * 64 + gx], a, bb));
        xs[rr][cx] = v;
    }
    float wd[9];
    #pragma unroll
    for (int t9 = 0; t9 < 9; t9++) wd[t9] = __ldg(&w_dw[hc * 9 + t9]);
    __syncthreads();
    float lsum = 0.f, lsq = 0.f;
    float* dst = g_h2 + (size_t)(b * HCn + hc) * HWn;
    #pragma unroll
    for (int k4 = 0; k4 < 4; k4++) {
        int idx = tid + k4 * 256;
        int row = idx >> 6, col = idx & 63;
        float sum = 0.f;
        #pragma unroll
        for (int kh = 0; kh < 3; kh++)
            #pragma unroll
            for (int kw = 0; kw < 3; kw++)
                sum = fmaf(wd[kh * 3 + kw], xs[row + kh][col + kw], sum);
        dst[(r0 + row) * 64 + col] = sum;
        lsum += sum;
        lsq += sum * sum;
    }
    if (tid < 2) sred[tid] = 0.f;
    __syncthreads();
    atomicAdd(&sred[0], lsum);
    atomicAdd(&sred[1], lsq);
    __syncthreads();
    if (tid == 0) {
        int g = hc >> 6;
        atomicAdd(&g_s2[(b * 8 + g) * 2], sred[0]);
        atomicAdd(&g_s2[(b * 8 + g) * 2 + 1], sred[1]);
    }
}

// ---------------- K6: pw2 1x1 stride-2 (512->128) via tf32 mma + gn3 stats ----------------
__global__ __launch_bounds__(256) void k_pw2m() {
    __shared__ unsigned As[8 * 136];
    __shared__ unsigned Bs[8 * 136];
    const int pxb = blockIdx.x * 128;
    const int b = blockIdx.z;
    const int tid = threadIdx.x;
    const int warp = tid >> 5;
    const int lane = tid & 31;
    const int wc = warp >> 1;
    const int wpx = warp & 1;
    const int grp = lane >> 2;
    const int tig = lane & 3;

    float acc[2][8][4];
    #pragma unroll
    for (int mt = 0; mt < 2; mt++)
        #pragma unroll
        for (int nt = 0; nt < 8; nt++)
            #pragma unroll
            for (int q = 0; q < 4; q++) acc[mt][nt][q] = 0.f;

    for (int cc = 0; cc < 64; cc++) {
        {
            const uint4* srcA = (const uint4*)(g_w2t + (size_t)cc * 1024);
            uint4 v = srcA[tid];
            *(uint4*)(As + (tid >> 5) * 136 + (tid & 31) * 4) = v;
        }
        {
            int r = tid >> 5;
            int ch = cc * 8 + r;
            float a = g_c2a[b * HCn + ch], bb = g_c2b[b * HCn + ch];
            const float* src = g_h2 + (size_t)(b * HCn + ch) * HWn;
            int i0 = (lane) * 4;
            #pragma unroll
            for (int j = 0; j < 4; j++) {
                int p = pxb + i0 + j;
                int oh = p >> 5, ow = p & 31;
                float v = silu_f(fmaf(src[oh * 128 + ow * 2], a, bb));
                Bs[r * 136 + i0 + j] = to_tf32(v);
            }
        }
        __syncthreads();

        unsigned a0[2], a1[2], a2[2], a3[2];
        #pragma unroll
        for (int mt = 0; mt < 2; mt++) {
            int co_r = wc * 32 + mt * 16 + grp;
            a0[mt] = As[tig * 136 + co_r];
            a1[mt] = As[tig * 136 + co_r + 8];
            a2[mt] = As[(tig + 4) * 136 + co_r];
            a3[mt] = As[(tig + 4) * 136 + co_r + 8];
        }
        #pragma unroll
        for (int nt = 0; nt < 8; nt++) {
            int col = wpx * 64 + nt * 8 + grp;
            unsigned b0 = Bs[tig * 136 + col];
            unsigned b1 = Bs[(tig + 4) * 136 + col];
            mma_tf32(acc[0][nt][0], acc[0][nt][1], acc[0][nt][2], acc[0][nt][3],
                     a0[0], a1[0], a2[0], a3[0], b0, b1);
            mma_tf32(acc[1][nt][0], acc[1][nt][1], acc[1][nt][2], acc[1][nt][3],
                     a0[1], a1[1], a2[1], a3[1], b0, b1);
        }
        __syncthreads();
    }

    #pragma unroll
    for (int mt = 0; mt < 2; mt++) {
        int co0 = wc * 32 + mt * 16 + grp;
        float ls = 0.f, lq = 0.f;
        #pragma unroll
        for (int nt = 0; nt < 8; nt++) {
            int px = pxb + wpx * 64 + nt * 8 + 2 * tig;
            float2 v0 = make_float2(acc[mt][nt][0], acc[mt][nt][1]);
            float2 v1 = make_float2(acc[mt][nt][2], acc[mt][nt][3]);
            *(float2*)(g_o + (size_t)(b * Cn + co0) * OHWn + px) = v0;
            *(float2*)(g_o + (size_t)(b * Cn + co0 + 8) * OHWn + px) = v1;
            ls += v0.x + v0.y + v1.x + v1.y;
            lq += v0.x * v0.x + v0.y * v0.y + v1.x * v1.x + v1.y * v1.y;
        }
        #pragma unroll
        for (int off = 16; off > 0; off >>= 1) {
            ls += __shfl_xor_sync(0xFFFFFFFFu, ls, off);
            lq += __shfl_xor_sync(0xFFFFFFFFu, lq, off);
        }
        if (lane == 0) {
            int g = wc * 2 + mt;
            atomicAdd(&g_s3[(b * 8 + g) * 2], ls);
            atomicAdd(&g_s3[(b * 8 + g) * 2 + 1], lq);
        }
    }
}

// ---------------- K7: final gn3 + silu ----------------
__global__ void k_out(float* __restrict__ out) {
    int i = blockIdx.x * 256 + threadIdx.x;
    int b = i >> 17;
    int c = (i >> 10) & 127;
    out[i] = silu_f(fmaf(g_o[i], g_c3a[b * Cn + c], g_c3b[b * Cn + c]));
}

// ---------------- launch ----------------
extern "C" void kernel_launch(void* const* d_in, const int* in_sizes, int n_in,
                              void* d_out, int out_size) {
    const float* x      = (const float*)d_in[0];
    const float* w_exp  = (const float*)d_in[1];
    const float* gns    = (const float*)d_in[2];
    const float* gnb    = (const float*)d_in[3];
    const float* w1     = (const float*)d_in[4];
    const float* b1     = (const float*)d_in[5];
    const float* w2     = (const float*)d_in[6];
    const float* b2     = (const float*)d_in[7];
    const float* w_pw1  = (const float*)d_in[8];
    const float* gn1s   = (const float*)d_in[9];
    const float* gn1b   = (const float*)d_in[10];
    const float* w_dw   = (const float*)d_in[11];
    const float* gn2s   = (const float*)d_in[12];
    const float* gn2b   = (const float*)d_in[13];
    const float* w_pw2  = (const float*)d_in[14];
    const float* gn3s   = (const float*)d_in[15];
    const float* gn3b   = (const float*)d_in[16];
    float* out = (float*)d_out;

    const int expert_smem = (2 * WS_BUF + 2 * XS_BUF) * 4;   // 70656 B
    cudaFuncSetAttribute(k_expert, cudaFuncAttributeMaxDynamicSharedMemorySize,
                         expert_smem);

    // order chosen so k_expert is the 4th launch (ncu window captures slot 4)
    k_zero<<<8, 256>>>();
    k_wprep<<<(En * 16 * 9 * 8 * 128 + 255) / 256, 256>>>(w_exp);
    k_xprep<<<(Bn * Cn * HWn) / 256, 256>>>(x);
    {
        dim3 g(16, 2, En * Bn);
        k_expert<<<g, 256, expert_smem>>>();
    }
    k_w1prep<<<(4 * 16 * 8 * 128 + 255) / 256, 256>>>(w_pw1);
    k_w2prep<<<(64 * 8 * 128 + 255) / 256, 256>>>(w_pw2);
    k_router_fin<<<1, 256>>>(gns, gnb, w1, b1, w2, b2);
    k_combine<<<8192, 256>>>(x);
    {
        dim3 g(32, 4, Bn);
        k_pw1m<<<g, 256>>>();
    }
    k_fin1<<<(Bn * HCn + 255) / 256, 256>>>(gn1s, gn1b);
    {
        dim3 g(4, HCn, Bn);
        k_dw<<<g, 256>>>(w_dw);
    }
    k_fin2<<<(Bn * HCn + 255) / 256, 256>>>(gn2s, gn2b);
    {
        dim3 g(8, 1, Bn);
        k_pw2m<<<g, 256>>>();
    }
    k_fin3<<<(Bn * Cn + 255) / 256, 256>>>(gn3s, gn3b);
    k_out<<<8192, 256>>>(out);
}

// round 11
// speedup vs baseline: 1.5432x; 1.0239x over previous
#include <cuda_runtime.h>
#include <math.h>

#define En 8
#define Bn 16
#define Cn 128
#define Hn 64
#define Wn 64
#define HWn 4096
#define HCn 512
#define OHWn 1024

// ---------------- scratch (device globals; no allocation) ----------------
__device__ float g_y[(size_t)En * Bn * Cn * HWn];
__device__ unsigned g_combt[(size_t)Bn * Cn * HWn];    // combined, tf32 bits
__device__ float g_h1[(size_t)Bn * HCn * HWn];
__device__ float g_h2[(size_t)Bn * HCn * HWn];
__device__ float g_o[(size_t)Bn * Cn * OHWn];
__device__ unsigned g_wt[(size_t)En * 16 * 9 * 8 * 128];   // expert W tf32 staging order
__device__ unsigned g_w1t[(size_t)4 * 16 * 8 * 128];       // pw1 W tf32 staging order
__device__ unsigned g_w2t[(size_t)64 * 8 * 128];           // pw2 W tf32 staging order
__device__ unsigned g_xt[(size_t)Bn * Cn * HWn];           // x as tf32 bits
__device__ float g_estats[En * Bn * 8 * 2];
__device__ float g_eca[En * Bn * Cn];
__device__ float g_ecb[En * Bn * Cn];
__device__ float g_wts[16][En];
__device__ float g_s1[Bn * 8 * 2];
__device__ float g_s2[Bn * 8 * 2];
__device__ float g_s3[Bn * 8 * 2];

__device__ __forceinline__ float silu_f(float v) { return v / (1.f + __expf(-v)); }

__device__ __forceinline__ unsigned to_tf32(float f) {
    unsigned r;
    asm("cvt.rna.tf32.f32 %0, %1;" : "=r"(r) : "f"(f));
    return r;
}

__device__ __forceinline__ void mma_tf32(float& c0, float& c1, float& c2, float& c3,
                                         unsigned a0, unsigned a1, unsigned a2, unsigned a3,
                                         unsigned b0, unsigned b1) {
    asm volatile(
        "mma.sync.aligned.m16n8k8.row.col.f32.tf32.tf32.f32 "
        "{%0,%1,%2,%3}, {%4,%5,%6,%7}, {%8,%9}, {%0,%1,%2,%3};"
        : "+f"(c0), "+f"(c1), "+f"(c2), "+f"(c3)
        : "r"(a0), "r"(a1), "r"(a2), "r"(a3), "r"(b0), "r"(b1));
}

// ---- cp.async helpers ----
__device__ __forceinline__ void cpa16(unsigned dst, const void* src) {
    asm volatile("cp.async.cg.shared.global [%0], [%1], 16;" :: "r"(dst), "l"(src));
}
__device__ __forceinline__ void cpa16z(unsigned dst, const void* src, int sz) {
    asm volatile("cp.async.cg.shared.global [%0], [%1], 16, %2;"
                 :: "r"(dst), "l"(src), "r"(sz));
}
__device__ __forceinline__ void cp_commit() {
    asm volatile("cp.async.commit_group;");
}

// ---------------- K0: zero the stats accumulators ----------------
__global__ void k_zero() {
    int i = blockIdx.x * 256 + threadIdx.x;
    if (i < En * Bn * 8 * 2) g_estats[i] = 0.f;
    if (i < Bn * 8 * 2) { g_s1[i] = 0.f; g_s2[i] = 0.f; g_s3[i] = 0.f; }
}

// ---------------- W preps ----------------
__global__ void k_wprep(const float* __restrict__ w_exp) {
    int i = blockIdx.x * 256 + threadIdx.x;
    if (i >= En * 16 * 9 * 8 * 128) return;
    int co = i & 127;
    int r = i >> 7;
    int ci = r & 7; r >>= 3;
    int tap = r % 9; r /= 9;
    int cc = r & 15;
    int e = r >> 4;
    g_wt[i] = to_tf32(w_exp[((size_t)(e * 128 + co) * 128 + cc * 8 + ci) * 9 + tap]);
}
__global__ void k_w1prep(const float* __restrict__ w_pw1) {
    int i = blockIdx.x * 256 + threadIdx.x;
    if (i >= 4 * 16 * 8 * 128) return;
    int hcl = i & 127;
    int ci = (i >> 7) & 7;
    int cc = (i >> 10) & 15;
    int blk = i >> 14;
    g_w1t[i] = to_tf32(w_pw1[(size_t)(blk * 128 + hcl) * 128 + cc * 8 + ci]);
}
__global__ void k_w2prep(const float* __restrict__ w_pw2) {
    int i = blockIdx.x * 256 + threadIdx.x;
    if (i >= 64 * 8 * 128) return;
    int co = i & 127;
    int ci = (i >> 7) & 7;
    int cc = i >> 10;
    g_w2t[i] = to_tf32(w_pw2[(size_t)co * 512 + cc * 8 + ci]);
}
__global__ void k_xprep(const float* __restrict__ x) {
    int i = blockIdx.x * 256 + threadIdx.x;
    g_xt[i] = to_tf32(x[i]);
}

// ---------------- K1: expert 3x3 conv via tf32 mma, cp.async double-buffered ----------------
#define WS_STRIDE 72
#define WS_BUF (72 * WS_STRIDE)      // 5184 words
#define XR_STRIDE 76
#define XS_BUF (48 * XR_STRIDE)      // 3648 words
__global__ __launch_bounds__(256, 2) void k_expert() {
    extern __shared__ unsigned sm[];
    const int ty0 = blockIdx.x * 4;
    const int chb = blockIdx.y;
    const int e = blockIdx.z >> 4;
    const int b = blockIdx.z & 15;

    const int tid = threadIdx.x;
    const int warp = tid >> 5;
    const int lane = tid & 31;
    const int wc = warp >> 2;
    const int wp = warp & 3;
    const int grp = lane >> 2;
    const int tig = lane & 3;

    const unsigned smbase = (unsigned)__cvta_generic_to_shared(sm);

    float acc[2][8][4];
    #pragma unroll
    for (int mt = 0; mt < 2; mt++)
        #pragma unroll
        for (int nt = 0; nt < 8; nt++)
            #pragma unroll
            for (int q = 0; q < 4; q++) acc[mt][nt][q] = 0.f;

    const unsigned* wt = g_wt + (size_t)e * 147456 + chb * 64;
    const unsigned* xt = g_xt + (size_t)b * Cn * HWn;

    if (tid < 96) {
        int buf = tid / 48;
        int r = tid - buf * 48;
        sm[2 * WS_BUF + buf * XS_BUF + r * XR_STRIDE + 3] = 0u;
        sm[2 * WS_BUF + buf * XS_BUF + r * XR_STRIDE + 68] = 0u;
    }
    __syncthreads();

    auto stage = [&](int cc, int buf) {
        const unsigned wsoff = buf * WS_BUF;
        #pragma unroll
        for (int it = 0; it < 5; it++) {
            int idx = tid + it * 256;
            if (idx < 1152) {
                int rw = idx >> 4, q = idx & 15;
                cpa16(smbase + (wsoff + rw * WS_STRIDE + q * 4) * 4,
                      wt + (size_t)cc * 9216 + rw * 128 + q * 4);
            }
        }
        const unsigned xsoff = 2 * WS_BUF + buf * XS_BUF;
        if (lane < 16) {
            const unsigned* src = xt + (size_t)(cc * 8 + warp) * HWn + (ty0 - 1) * 64 + lane * 4;
            #pragma unroll
            for (int rr = 0; rr < 6; rr++) {
                int gy = ty0 - 1 + rr;
                bool ok = (unsigned)gy < 64u;
                cpa16z(smbase + (xsoff + (warp * 6 + rr) * XR_STRIDE + 4 + lane * 4) * 4,
                       ok ? (const void*)(src + rr * 64) : (const void*)xt, ok ? 16 : 0);
            }
        }
    };

    stage(0, 0);
    cp_commit();

    for (int cc = 0; cc < 16; cc++) {
        if (cc < 15) {
            stage(cc + 1, (cc + 1) & 1);
            cp_commit();
            asm volatile("cp.async.wait_group 1;");
        } else {
            asm volatile("cp.async.wait_group 0;");
        }
        __syncthreads();

        const unsigned* ws = sm + (cc & 1) * WS_BUF;
        const unsigned* xs = sm + 2 * WS_BUF + (cc & 1) * XS_BUF;

        #pragma unroll
        for (int tap = 0; tap < 9; tap++) {
            const int kh = tap / 3, kw = tap % 3;
            unsigned a0[2], a1[2], a2[2], a3[2];
            #pragma unroll
            for (int mt = 0; mt < 2; mt++) {
                int co_r = wc * 32 + mt * 16 + grp;
                a0[mt] = ws[(tap * 8 + tig) * WS_STRIDE + co_r];
                a1[mt] = ws[(tap * 8 + tig) * WS_STRIDE + co_r + 8];
                a2[mt] = ws[(tap * 8 + tig + 4) * WS_STRIDE + co_r];
                a3[mt] = ws[(tap * 8 + tig + 4) * WS_STRIDE + co_r + 8];
            }
            #pragma unroll
            for (int nt = 0; nt < 8; nt++) {
                int col = 3 + nt * 8 + grp + kw;
                unsigned b0 = xs[(tig * 6 + wp + kh) * XR_STRIDE + col];
                unsigned b1 = xs[((tig + 4) * 6 + wp + kh) * XR_STRIDE + col];
                mma_tf32(acc[0][nt][0], acc[0][nt][1], acc[0][nt][2], acc[0][nt][3],
                         a0[0], a1[0], a2[0], a3[0], b0, b1);
                mma_tf32(acc[1][nt][0], acc[1][nt][1], acc[1][nt][2], acc[1][nt][3],
                         a0[1], a1[1], a2[1], a3[1], b0, b1);
            }
        }
        __syncthreads();
    }

    size_t ybase = (size_t)(e * Bn + b) * Cn * HWn;
    const int row = ty0 + wp;
    float ls[2] = {0.f, 0.f}, lq[2] = {0.f, 0.f};
    #pragma unroll
    for (int mt = 0; mt < 2; mt++) {
        int co = chb * 64 + wc * 32 + mt * 16 + grp;
        #pragma unroll
        for (int nt = 0; nt < 8; nt++) {
            int colx = nt * 8 + 2 * tig;
            float2 v0 = make_float2(acc[mt][nt][0], acc[mt][nt][1]);
            float2 v1 = make_float2(acc[mt][nt][2], acc[mt][nt][3]);
            *(float2*)(g_y + ybase + (size_t)co * HWn + row * 64 + colx) = v0;
            *(float2*)(g_y + ybase + (size_t)(co + 8) * HWn + row * 64 + colx) = v1;
            ls[mt] += v0.x + v0.y + v1.x + v1.y;
            lq[mt] += v0.x * v0.x + v0.y * v0.y + v1.x * v1.x + v1.y * v1.y;
        }
    }
    #pragma unroll
    for (int mt = 0; mt < 2; mt++) {
        float s = ls[mt], q = lq[mt];
        #pragma unroll
        for (int off = 16; off > 0; off >>= 1) {
            s += __shfl_xor_sync(0xFFFFFFFFu, s, off);
            q += __shfl_xor_sync(0xFFFFFFFFu, q, off);
        }
        if (lane == 0) {
            int g = chb * 4 + wc * 2 + mt;
            atomicAdd(&g_estats[((e * Bn + b) * 8 + g) * 2], s);
            atomicAdd(&g_estats[((e * Bn + b) * 8 + g) * 2 + 1], q);
        }
    }
}

// ---------------- K2: finalize expert GN coefs + router softmax ----------------
__global__ void k_router_fin(const float* __restrict__ gns, const float* __restrict__ gnb,
                             const float* __restrict__ w1, const float* __restrict__ b1,
                             const float* __restrict__ w2, const float* __restrict__ b2) {
    int tid = threadIdx.x;
    for (int i = tid; i < En * Bn * Cn; i += 256) {
        int e = i >> 11, b = (i >> 7) & 15, c = i & 127, g = c >> 4;
        float s = g_estats[((e * Bn + b) * 8 + g) * 2];
        float sq = g_estats[((e * Bn + b) * 8 + g) * 2 + 1];
        float mean = s * (1.f / 65536.f);
        float var = sq * (1.f / 65536.f) - mean * mean;
        float rstd = rsqrtf(var + 1e-5f);
        float a = rstd * gns[e * Cn + c];
        g_eca[i] = a;
        g_ecb[i] = gnb[e * Cn + c] - mean * a;
    }
    if (tid < 16) {
        int py = tid >> 2, px = tid & 3;
        float fe[32];
        float cy = (py + 0.5f) * 0.25f, cx = (px + 0.5f) * 0.25f;
        #pragma unroll
        for (int k = 0; k < 8; k++) {
            float fr = (float)(1 << k) * 3.14159265358979323846f;
            fe[k] = sinf(cy * fr);
            fe[8 + k] = cosf(cy * fr);
            fe[16 + k] = sinf(cx * fr);
            fe[24 + k] = cosf(cx * fr);
        }
        float hb[64];
        for (int j = 0; j < 64; j++) {
            float s = b1[j];
            for (int k = 0; k < 32; k++) s = fmaf(fe[k], w1[k * 64 + j], s);
            hb[j] = s / (1.f + expf(-s));
        }
        float lo[8];
        float mx = -1e30f;
        for (int ee = 0; ee < 8; ee++) {
            float s = b2[ee];
            for (int j = 0; j < 64; j++) s = fmaf(hb[j], w2[j * 8 + ee], s);
            lo[ee] = s;
            mx = fmaxf(mx, s);
        }
        float den = 0.f;
        for (int ee = 0; ee < 8; ee++) { lo[ee] = expf(lo[ee] - mx); den += lo[ee]; }
        float inv = 1.f / den;
        for (int ee = 0; ee < 8; ee++) g_wts[tid][ee] = lo[ee] * inv;
    }
}

// ---------------- K3: combine experts -> tf32 bits ----------------
__global__ void k_combine(const float* __restrict__ x) {
    size_t t = (size_t)blockIdx.x * 256 + threadIdx.x;
    size_t i = t * 4;
    int b = (int)(i >> 19);
    int c = (int)(i >> 12) & 127;
    int p = (int)(i & 4095);
    int patch = ((p >> 6) >> 4) * 4 + ((p & 63) >> 4);
    float4 outv = *(const float4*)(x + i);
    #pragma unroll
    for (int e = 0; e < 8; e++) {
        int ebc = (e * Bn + b) * Cn + c;
        float a = g_eca[ebc], bb = g_ecb[ebc];
        float wt = g_wts[patch][e];
        float4 y = *(const float4*)(g_y + (size_t)ebc * HWn + p);
        outv.x += wt * silu_f(fmaf(y.x, a, bb));
        outv.y += wt * silu_f(fmaf(y.y, a, bb));
        outv.z += wt * silu_f(fmaf(y.z, a, bb));
        outv.w += wt * silu_f(fmaf(y.w, a, bb));
    }
    uint4 o;
    o.x = to_tf32(outv.x);
    o.y = to_tf32(outv.y);
    o.z = to_tf32(outv.z);
    o.w = to_tf32(outv.w);
    *(uint4*)(g_combt + i) = o;
}

// ---------------- K4: pw1 1x1 (128->512) via tf32 mma, cp.async DB + gn1 stats ----------------
__global__ __launch_bounds__(256) void k_pw1m() {
    __shared__ unsigned As[2][8 * 136];
    __shared__ unsigned Bs[2][8 * 136];
    const int pxb = blockIdx.x * 128;
    const int hcb = blockIdx.y * 128;
    const int b = blockIdx.z;
    const int tid = threadIdx.x;
    const int warp = tid >> 5;
    const int lane = tid & 31;
    const int wc = warp >> 1;
    const int wpx = warp & 1;
    const int grp = lane >> 2;
    const int tig = lane & 3;

    const unsigned sa = (unsigned)__cvta_generic_to_shared(&As[0][0]);
    const unsigned sb = (unsigned)__cvta_generic_to_shared(&Bs[0][0]);

    float acc[2][8][4];
    #pragma unroll
    for (int mt = 0; mt < 2; mt++)
        #pragma unroll
        for (int nt = 0; nt < 8; nt++)
            #pragma unroll
            for (int q = 0; q < 4; q++) acc[mt][nt][q] = 0.f;

    auto stage = [&](int cc, int buf) {
        cpa16(sa + (buf * 1088 + (tid >> 5) * 136 + (tid & 31) * 4) * 4,
              g_w1t + (size_t)((blockIdx.y * 16 + cc) * 8) * 128 + (tid >> 5) * 128 + (tid & 31) * 4);
        cpa16(sb + (buf * 1088 + (tid >> 5) * 136 + (tid & 31) * 4) * 4,
              g_combt + (size_t)(b * Cn + cc * 8 + (tid >> 5)) * HWn + pxb + (tid & 31) * 4);
    };

    stage(0, 0);
    cp_commit();

    for (int cc = 0; cc < 16; cc++) {
        if (cc < 15) {
            stage(cc + 1, (cc + 1) & 1);
            cp_commit();
            asm volatile("cp.async.wait_group 1;");
        } else {
            asm volatile("cp.async.wait_group 0;");
        }
        __syncthreads();

        const unsigned* Ab = &As[cc & 1][0];
        const unsigned* Bb = &Bs[cc & 1][0];

        unsigned a0[2], a1[2], a2[2], a3[2];
        #pragma unroll
        for (int mt = 0; mt < 2; mt++) {
            int hc_r = wc * 32 + mt * 16 + grp;
            a0[mt] = Ab[tig * 136 + hc_r];
            a1[mt] = Ab[tig * 136 + hc_r + 8];
            a2[mt] = Ab[(tig + 4) * 136 + hc_r];
            a3[mt] = Ab[(tig + 4) * 136 + hc_r + 8];
        }
        #pragma unroll
        for (int nt = 0; nt < 8; nt++) {
            int col = wpx * 64 + nt * 8 + grp;
            unsigned b0 = Bb[tig * 136 + col];
            unsigned b1 = Bb[(tig + 4) * 136 + col];
            mma_tf32(acc[0][nt][0], acc[0][nt][1], acc[0][nt][2], acc[0][nt][3],
                     a0[0], a1[0], a2[0], a3[0], b0, b1);
            mma_tf32(acc[1][nt][0], acc[1][nt][1], acc[1][nt][2], acc[1][nt][3],
                     a0[1], a1[1], a2[1], a3[1], b0, b1);
        }
        __syncthreads();
    }

    #pragma unroll
    for (int mt = 0; mt < 2; mt++) {
        int hc0 = hcb + wc * 32 + mt * 16 + grp;
        float ls = 0.f, lq = 0.f;
        #pragma unroll
        for (int nt = 0; nt < 8; nt++) {
            int px = pxb + wpx * 64 + nt * 8 + 2 * tig;
            float2 v0 = make_float2(acc[mt][nt][0], acc[mt][nt][1]);
            float2 v1 = make_float2(acc[mt][nt][2], acc[mt][nt][3]);
            *(float2*)(g_h1 + (size_t)(b * HCn + hc0) * HWn + px) = v0;
            *(float2*)(g_h1 + (size_t)(b * HCn + hc0 + 8) * HWn + px) = v1;
            ls += v0.x + v0.y + v1.x + v1.y;
            lq += v0.x * v0.x + v0.y * v0.y + v1.x * v1.x + v1.y * v1.y;
        }
        #pragma unroll
        for (int off = 16; off > 0; off >>= 1) {
            ls += __shfl_xor_sync(0xFFFFFFFFu, ls, off);
            lq += __shfl_xor_sync(0xFFFFFFFFu, lq, off);
        }
        if (lane == 0) {
            int g = (hcb >> 6) + (wc >> 1);
            atomicAdd(&g_s1[(b * 8 + g) * 2], ls);
            atomicAdd(&g_s1[(b * 8 + g) * 2 + 1], lq);
        }
    }
}

// ---------------- K5: depthwise 3x3 (gn1 coefs inline) + gn2 stats ----------------
__global__ __launch_bounds__(256) void k_dw(const float* __restrict__ w_dw,
                                            const float* __restrict__ gn1s,
                                            const float* __restrict__ gn1b) {
    int rt = blockIdx.x;
    int hc = blockIdx.y;
    int b = blockIdx.z;
    __shared__ float xs[18][66];
    __shared__ float sred[2];
    int tid = threadIdx.x;
    // gn1 coefs inline (fin1 folded)
    int g1 = hc >> 6;
    float su = g_s1[(b * 8 + g1) * 2], sq = g_s1[(b * 8 + g1) * 2 + 1];
    float mean = su * (1.f / 262144.f);
    float var = sq * (1.f / 262144.f) - mean * mean;
    float rstd = rsqrtf(var + 1e-5f);
    float a = rstd * gn1s[hc];
    float bb = gn1b[hc] - mean * a;

    const float* src = g_h1 + (size_t)(b * HCn + hc) * HWn;
    int r0 = rt * 16;
    for (int idx = tid; idx < 18 * 66; idx += 256) {
        int rr = idx / 66, cx = idx % 66;
        int gy = r0 - 1 + rr, gx = cx - 1;
        float v = 0.f;
        if ((unsigned)gy < 64u && (unsigned)gx < 64u)
            v = silu_f(fmaf(src[gy * 64 + gx], a, bb));
        xs[rr][cx] = v;
    }
    float wd[9];
    #pragma unroll
    for (int t9 = 0; t9 < 9; t9++) wd[t9] = __ldg(&w_dw[hc * 9 + t9]);
    __syncthreads();
    float lsum = 0.f, lsq = 0.f;
    float* dst = g_h2 + (size_t)(b * HCn + hc) * HWn;
    #pragma unroll
    for (int k4 = 0; k4 < 4; k4++) {
        int idx = tid + k4 * 256;
        int row = idx >> 6, col = idx & 63;
        float sum = 0.f;
        #pragma unroll
        for (int kh = 0; kh < 3; kh++)
            #pragma unroll
            for (int kw = 0; kw < 3; kw++)
                sum = fmaf(wd[kh * 3 + kw], xs[row + kh][col + kw], sum);
        dst[(r0 + row) * 64 + col] = sum;
        lsum += sum;
        lsq += sum * sum;
    }
    if (tid < 2) sred[tid] = 0.f;
    __syncthreads();
    atomicAdd(&sred[0], lsum);
    atomicAdd(&sred[1], lsq);
    __syncthreads();
    if (tid == 0) {
        int g = hc >> 6;
        atomicAdd(&g_s2[(b * 8 + g) * 2], sred[0]);
        atomicAdd(&g_s2[(b * 8 + g) * 2 + 1], sred[1]);
    }
}

// ---------------- K6: pw2 1x1 stride-2 via tf32 mma, DB (gn2 coefs inline) + gn3 stats ----------------
__global__ __launch_bounds__(256) void k_pw2m(const float* __restrict__ gn2s,
                                              const float* __restrict__ gn2b) {
    __shared__ unsigned As[2][8 * 136];
    __shared__ unsigned Bs[2][8 * 136];
    const int pxb = blockIdx.x * 128;
    const int b = blockIdx.z;
    const int tid = threadIdx.x;
    const int warp = tid >> 5;
    const int lane = tid & 31;
    const int wc = warp >> 1;
    const int wpx = warp & 1;
    const int grp = lane >> 2;
    const int tig = lane & 3;
    const int r = warp;          // k-row 0..7 for B staging
    const unsigned sa = (unsigned)__cvta_generic_to_shared(&As[0][0]);

    float acc[2][8][4];
    #pragma unroll
    for (int mt = 0; mt < 2; mt++)
        #pragma unroll
        for (int nt = 0; nt < 8; nt++)
            #pragma unroll
            for (int q = 0; q < 4; q++) acc[mt][nt][q] = 0.f;

    auto loadB = [&](int cc, float* breg) {
        int ch = cc * 8 + r;
        const float* src = g_h2 + (size_t)(b * HCn + ch) * HWn;
        int i0 = lane * 4;
        #pragma unroll
        for (int j = 0; j < 4; j++) {
            int p = pxb + i0 + j;
            int oh = p >> 5, ow = p & 31;
            breg[j] = src[oh * 128 + ow * 2];
        }
    };
    auto coefs = [&](int cc, float& a, float& bb) {
        int ch = cc * 8 + r;
        int g2 = ch >> 6;
        float su = g_s2[(b * 8 + g2) * 2], sq = g_s2[(b * 8 + g2) * 2 + 1];
        float mean = su * (1.f / 262144.f);
        float var = sq * (1.f / 262144.f) - mean * mean;
        float rstd = rsqrtf(var + 1e-5f);
        a = rstd * gn2s[ch];
        bb = gn2b[ch] - mean * a;
    };
    auto stsB = [&](int buf, const float* breg, float a, float bb) {
        uint4 v;
        v.x = to_tf32(silu_f(fmaf(breg[0], a, bb)));
        v.y = to_tf32(silu_f(fmaf(breg[1], a, bb)));
        v.z = to_tf32(silu_f(fmaf(breg[2], a, bb)));
        v.w = to_tf32(silu_f(fmaf(breg[3], a, bb)));
        *(uint4*)(&Bs[buf][r * 136 + lane * 4]) = v;
    };
    auto stageA = [&](int cc, int buf) {
        cpa16(sa + (buf * 1088 + (tid >> 5) * 136 + (tid & 31) * 4) * 4,
              g_w2t + (size_t)cc * 1024 + (tid >> 5) * 128 + (tid & 31) * 4);
    };

    // prologue
    float breg[4], brega, bregb;
    loadB(0, breg);
    coefs(0, brega, bregb);
    stageA(0, 0);
    cp_commit();
    stsB(0, breg, brega, bregb);

    for (int cc = 0; cc < 64; cc++) {
        float nreg[4], na, nb2;
        if (cc < 63) {
            loadB(cc + 1, nreg);       // LDG issued early, hidden by mma
            coefs(cc + 1, na, nb2);
            stageA(cc + 1, (cc + 1) & 1);
            cp_commit();
            asm volatile("cp.async.wait_group 1;");
        } else {
            asm volatile("cp.async.wait_group 0;");
        }
        __syncthreads();

        const unsigned* Ab = &As[cc & 1][0];
        const unsigned* Bb = &Bs[cc & 1][0];

        unsigned a0[2], a1[2], a2[2], a3[2];
        #pragma unroll
        for (int mt = 0; mt < 2; mt++) {
            int co_r = wc * 32 + mt * 16 + grp;
            a0[mt] = Ab[tig * 136 + co_r];
            a1[mt] = Ab[tig * 136 + co_r + 8];
            a2[mt] = Ab[(tig + 4) * 136 + co_r];
            a3[mt] = Ab[(tig + 4) * 136 + co_r + 8];
        }
        #pragma unroll
        for (int nt = 0; nt < 8; nt++) {
            int col = wpx * 64 + nt * 8 + grp;
            unsigned b0 = Bb[tig * 136 + col];
            unsigned b1 = Bb[(tig + 4) * 136 + col];
            mma_tf32(acc[0][nt][0], acc[0][nt][1], acc[0][nt][2], acc[0][nt][3],
                     a0[0], a1[0], a2[0], a3[0], b0, b1);
            mma_tf32(acc[1][nt][0], acc[1][nt][1], acc[1][nt][2], acc[1][nt][3],
                     a0[1], a1[1], a2[1], a3[1], b0, b1);
        }
        __syncthreads();
        if (cc < 63) stsB((cc + 1) & 1, nreg, na, nb2);
    }

    #pragma unroll
    for (int mt = 0; mt < 2; mt++) {
        int co0 = wc * 32 + mt * 16 + grp;
        float ls = 0.f, lq = 0.f;
        #pragma unroll
        for (int nt = 0; nt < 8; nt++) {
            int px = pxb + wpx * 64 + nt * 8 + 2 * tig;
            float2 v0 = make_float2(acc[mt][nt][0], acc[mt][nt][1]);
            float2 v1 = make_float2(acc[mt][nt][2], acc[mt][nt][3]);
            *(float2*)(g_o + (size_t)(b * Cn + co0) * OHWn + px) = v0;
            *(float2*)(g_o + (size_t)(b * Cn + co0 + 8) * OHWn + px) = v1;
            ls += v0.x + v0.y + v1.x + v1.y;
            lq += v0.x * v0.x + v0.y * v0.y + v1.x * v1.x + v1.y * v1.y;
        }
        #pragma unroll
        for (int off = 16; off > 0; off >>= 1) {
            ls += __shfl_xor_sync(0xFFFFFFFFu, ls, off);
            lq += __shfl_xor_sync(0xFFFFFFFFu, lq, off);
        }
        if (lane == 0) {
            int g = wc * 2 + mt;
            atomicAdd(&g_s3[(b * 8 + g) * 2], ls);
            atomicAdd(&g_s3[(b * 8 + g) * 2 + 1], lq);
        }
    }
}

// ---------------- K7: final gn3 + silu (fin3 folded) ----------------
__global__ void k_out(float* __restrict__ out, const float* __restrict__ gn3s,
                      const float* __restrict__ gn3b) {
    int i = blockIdx.x * 256 + threadIdx.x;
    int b = i >> 17;
    int c = (i >> 10) & 127;
    int g = c >> 4;
    float su = g_s3[(b * 8 + g) * 2], sq = g_s3[(b * 8 + g) * 2 + 1];
    float mean = su * (1.f / 16384.f);
    float var = sq * (1.f / 16384.f) - mean * mean;
    float rstd = rsqrtf(var + 1e-5f);
    float a = rstd * gn3s[c];
    float bb = gn3b[c] - mean * a;
    out[i] = silu_f(fmaf(g_o[i], a, bb));
}

// ---------------- launch ----------------
extern "C" void kernel_launch(void* const* d_in, const int* in_sizes, int n_in,
                              void* d_out, int out_size) {
    const float* x      = (const float*)d_in[0];
    const float* w_exp  = (const float*)d_in[1];
    const float* gns    = (const float*)d_in[2];
    const float* gnb    = (const float*)d_in[3];
    const float* w1     = (const float*)d_in[4];
    const float* b1     = (const float*)d_in[5];
    const float* w2     = (const float*)d_in[6];
    const float* b2     = (const float*)d_in[7];
    const float* w_pw1  = (const float*)d_in[8];
    const float* gn1s   = (const float*)d_in[9];
    const float* gn1b   = (const float*)d_in[10];
    const float* w_dw   = (const float*)d_in[11];
    const float* gn2s   = (const float*)d_in[12];
    const float* gn2b   = (const float*)d_in[13];
    const float* w_pw2  = (const float*)d_in[14];
    const float* gn3s   = (const float*)d_in[15];
    const float* gn3b   = (const float*)d_in[16];
    float* out = (float*)d_out;

    const int expert_smem = (2 * WS_BUF + 2 * XS_BUF) * 4;   // 70656 B
    cudaFuncSetAttribute(k_expert, cudaFuncAttributeMaxDynamicSharedMemorySize,
                         expert_smem);

    // k_expert stays at slot 4 for the ncu window
    k_zero<<<8, 256>>>();
    k_wprep<<<(En * 16 * 9 * 8 * 128 + 255) / 256, 256>>>(w_exp);
    k_xprep<<<(Bn * Cn * HWn) / 256, 256>>>(x);
    {
        dim3 g(16, 2, En * Bn);
        k_expert<<<g, 256, expert_smem>>>();
    }
    k_w1prep<<<(4 * 16 * 8 * 128 + 255) / 256, 256>>>(w_pw1);
    k_w2prep<<<(64 * 8 * 128 + 255) / 256, 256>>>(w_pw2);
    k_router_fin<<<1, 256>>>(gns, gnb, w1, b1, w2, b2);
    k_combine<<<8192, 256>>>(x);
    {
        dim3 g(32, 4, Bn);
        k_pw1m<<<g, 256>>>();
    }
    {
        dim3 g(4, HCn, Bn);
        k_dw<<<g, 256>>>(w_dw, gn1s, gn1b);
    }
    {
        dim3 g(8, 1, Bn);
        k_pw2m<<<g, 256>>>(gn2s, gn2b);
    }
    k_out<<<8192, 256>>>(out, gn3s, gn3b);
}

// round 12
// speedup vs baseline: 1.5668x; 1.0153x over previous
#include <cuda_runtime.h>
#include <math.h>

#define En 8
#define Bn 16
#define Cn 128
#define Hn 64
#define Wn 64
#define HWn 4096
#define HCn 512
#define OHWn 1024

// ---------------- scratch (device globals; no allocation) ----------------
__device__ float g_y[(size_t)En * Bn * Cn * HWn];
__device__ unsigned g_combt[(size_t)Bn * Cn * HWn];    // combined, tf32 bits
__device__ float g_h1[(size_t)Bn * HCn * HWn];
__device__ float g_h2s[(size_t)Bn * HCn * OHWn];       // dw output, even px only (32x32)
__device__ float g_po[(size_t)2 * Bn * Cn * OHWn];     // pw2 K-split partials
__device__ float g_o[(size_t)Bn * Cn * OHWn];
__device__ unsigned g_wt[(size_t)En * 16 * 9 * 8 * 128];   // expert W tf32 staging order
__device__ unsigned g_w1t[(size_t)4 * 16 * 8 * 128];       // pw1 W tf32 staging order
__device__ unsigned g_w2t[(size_t)64 * 8 * 128];           // pw2 W tf32 staging order
__device__ unsigned g_xt[(size_t)Bn * Cn * HWn];           // x as tf32 bits
__device__ float g_estats[En * Bn * 8 * 2];
__device__ float g_eca[En * Bn * Cn];
__device__ float g_ecb[En * Bn * Cn];
__device__ float g_wts[16][En];
__device__ float g_s1[Bn * 8 * 2];
__device__ float g_s2[Bn * 8 * 2];
__device__ float g_s3[Bn * 8 * 2];

__device__ __forceinline__ float silu_f(float v) { return v / (1.f + __expf(-v)); }

__device__ __forceinline__ unsigned to_tf32(float f) {
    unsigned r;
    asm("cvt.rna.tf32.f32 %0, %1;" : "=r"(r) : "f"(f));
    return r;
}

__device__ __forceinline__ void mma_tf32(float& c0, float& c1, float& c2, float& c3,
                                         unsigned a0, unsigned a1, unsigned a2, unsigned a3,
                                         unsigned b0, unsigned b1) {
    asm volatile(
        "mma.sync.aligned.m16n8k8.row.col.f32.tf32.tf32.f32 "
        "{%0,%1,%2,%3}, {%4,%5,%6,%7}, {%8,%9}, {%0,%1,%2,%3};"
        : "+f"(c0), "+f"(c1), "+f"(c2), "+f"(c3)
        : "r"(a0), "r"(a1), "r"(a2), "r"(a3), "r"(b0), "r"(b1));
}

// ---- cp.async helpers ----
__device__ __forceinline__ void cpa16(unsigned dst, const void* src) {
    asm volatile("cp.async.cg.shared.global [%0], [%1], 16;" :: "r"(dst), "l"(src));
}
__device__ __forceinline__ void cpa16z(unsigned dst, const void* src, int sz) {
    asm volatile("cp.async.cg.shared.global [%0], [%1], 16, %2;"
                 :: "r"(dst), "l"(src), "r"(sz));
}
__device__ __forceinline__ void cp_commit() {
    asm volatile("cp.async.commit_group;");
}

// ---------------- K0: zero the stats accumulators ----------------
__global__ void k_zero() {
    int i = blockIdx.x * 256 + threadIdx.x;
    if (i < En * Bn * 8 * 2) g_estats[i] = 0.f;
    if (i < Bn * 8 * 2) { g_s1[i] = 0.f; g_s2[i] = 0.f; }
}

// ---------------- W preps ----------------
__global__ void k_wprep(const float* __restrict__ w_exp) {
    int i = blockIdx.x * 256 + threadIdx.x;
    if (i >= En * 16 * 9 * 8 * 128) return;
    int co = i & 127;
    int r = i >> 7;
    int ci = r & 7; r >>= 3;
    int tap = r % 9; r /= 9;
    int cc = r & 15;
    int e = r >> 4;
    g_wt[i] = to_tf32(w_exp[((size_t)(e * 128 + co) * 128 + cc * 8 + ci) * 9 + tap]);
}
__global__ void k_w1prep(const float* __restrict__ w_pw1) {
    int i = blockIdx.x * 256 + threadIdx.x;
    if (i >= 4 * 16 * 8 * 128) return;
    int hcl = i & 127;
    int ci = (i >> 7) & 7;
    int cc = (i >> 10) & 15;
    int blk = i >> 14;
    g_w1t[i] = to_tf32(w_pw1[(size_t)(blk * 128 + hcl) * 128 + cc * 8 + ci]);
}
__global__ void k_w2prep(const float* __restrict__ w_pw2) {
    int i = blockIdx.x * 256 + threadIdx.x;
    if (i >= 64 * 8 * 128) return;
    int co = i & 127;
    int ci = (i >> 7) & 7;
    int cc = i >> 10;
    g_w2t[i] = to_tf32(w_pw2[(size_t)co * 512 + cc * 8 + ci]);
}
__global__ void k_xprep(const float* __restrict__ x) {
    int i = blockIdx.x * 256 + threadIdx.x;
    g_xt[i] = to_tf32(x[i]);
}

// ---------------- K1: expert 3x3 conv via tf32 mma, cp.async double-buffered ----------------
#define WS_STRIDE 72
#define WS_BUF (72 * WS_STRIDE)
#define XR_STRIDE 76
#define XS_BUF (48 * XR_STRIDE)
__global__ __launch_bounds__(256, 2) void k_expert() {
    extern __shared__ unsigned sm[];
    const int ty0 = blockIdx.x * 4;
    const int chb = blockIdx.y;
    const int e = blockIdx.z >> 4;
    const int b = blockIdx.z & 15;

    const int tid = threadIdx.x;
    const int warp = tid >> 5;
    const int lane = tid & 31;
    const int wc = warp >> 2;
    const int wp = warp & 3;
    const int grp = lane >> 2;
    const int tig = lane & 3;

    const unsigned smbase = (unsigned)__cvta_generic_to_shared(sm);

    float acc[2][8][4];
    #pragma unroll
    for (int mt = 0; mt < 2; mt++)
        #pragma unroll
        for (int nt = 0; nt < 8; nt++)
            #pragma unroll
            for (int q = 0; q < 4; q++) acc[mt][nt][q] = 0.f;

    const unsigned* wt = g_wt + (size_t)e * 147456 + chb * 64;
    const unsigned* xt = g_xt + (size_t)b * Cn * HWn;

    if (tid < 96) {
        int buf = tid / 48;
        int r = tid - buf * 48;
        sm[2 * WS_BUF + buf * XS_BUF + r * XR_STRIDE + 3] = 0u;
        sm[2 * WS_BUF + buf * XS_BUF + r * XR_STRIDE + 68] = 0u;
    }
    __syncthreads();

    auto stage = [&](int cc, int buf) {
        const unsigned wsoff = buf * WS_BUF;
        #pragma unroll
        for (int it = 0; it < 5; it++) {
            int idx = tid + it * 256;
            if (idx < 1152) {
                int rw = idx >> 4, q = idx & 15;
                cpa16(smbase + (wsoff + rw * WS_STRIDE + q * 4) * 4,
                      wt + (size_t)cc * 9216 + rw * 128 + q * 4);
            }
        }
        const unsigned xsoff = 2 * WS_BUF + buf * XS_BUF;
        if (lane < 16) {
            const unsigned* src = xt + (size_t)(cc * 8 + warp) * HWn + (ty0 - 1) * 64 + lane * 4;
            #pragma unroll
            for (int rr = 0; rr < 6; rr++) {
                int gy = ty0 - 1 + rr;
                bool ok = (unsigned)gy < 64u;
                cpa16z(smbase + (xsoff + (warp * 6 + rr) * XR_STRIDE + 4 + lane * 4) * 4,
                       ok ? (const void*)(src + rr * 64) : (const void*)xt, ok ? 16 : 0);
            }
        }
    };

    stage(0, 0);
    cp_commit();

    for (int cc = 0; cc < 16; cc++) {
        if (cc < 15) {
            stage(cc + 1, (cc + 1) & 1);
            cp_commit();
            asm volatile("cp.async.wait_group 1;");
        } else {
            asm volatile("cp.async.wait_group 0;");
        }
        __syncthreads();

        const unsigned* ws = sm + (cc & 1) * WS_BUF;
        const unsigned* xs = sm + 2 * WS_BUF + (cc & 1) * XS_BUF;

        #pragma unroll
        for (int tap = 0; tap < 9; tap++) {
            const int kh = tap / 3, kw = tap % 3;
            unsigned a0[2], a1[2], a2[2], a3[2];
            #pragma unroll
            for (int mt = 0; mt < 2; mt++) {
                int co_r = wc * 32 + mt * 16 + grp;
                a0[mt] = ws[(tap * 8 + tig) * WS_STRIDE + co_r];
                a1[mt] = ws[(tap * 8 + tig) * WS_STRIDE + co_r + 8];
                a2[mt] = ws[(tap * 8 + tig + 4) * WS_STRIDE + co_r];
                a3[mt] = ws[(tap * 8 + tig + 4) * WS_STRIDE + co_r + 8];
            }
            #pragma unroll
            for (int nt = 0; nt < 8; nt++) {
                int col = 3 + nt * 8 + grp + kw;
                unsigned b0 = xs[(tig * 6 + wp + kh) * XR_STRIDE + col];
                unsigned b1 = xs[((tig + 4) * 6 + wp + kh) * XR_STRIDE + col];
                mma_tf32(acc[0][nt][0], acc[0][nt][1], acc[0][nt][2], acc[0][nt][3],
                         a0[0], a1[0], a2[0], a3[0], b0, b1);
                mma_tf32(acc[1][nt][0], acc[1][nt][1], acc[1][nt][2], acc[1][nt][3],
                         a0[1], a1[1], a2[1], a3[1], b0, b1);
            }
        }
        __syncthreads();
    }

    size_t ybase = (size_t)(e * Bn + b) * Cn * HWn;
    const int row = ty0 + wp;
    float ls[2] = {0.f, 0.f}, lq[2] = {0.f, 0.f};
    #pragma unroll
    for (int mt = 0; mt < 2; mt++) {
        int co = chb * 64 + wc * 32 + mt * 16 + grp;
        #pragma unroll
        for (int nt = 0; nt < 8; nt++) {
            int colx = nt * 8 + 2 * tig;
            float2 v0 = make_float2(acc[mt][nt][0], acc[mt][nt][1]);
            float2 v1 = make_float2(acc[mt][nt][2], acc[mt][nt][3]);
            *(float2*)(g_y + ybase + (size_t)co * HWn + row * 64 + colx) = v0;
            *(float2*)(g_y + ybase + (size_t)(co + 8) * HWn + row * 64 + colx) = v1;
            ls[mt] += v0.x + v0.y + v1.x + v1.y;
            lq[mt] += v0.x * v0.x + v0.y * v0.y + v1.x * v1.x + v1.y * v1.y;
        }
    }
    #pragma unroll
    for (int mt = 0; mt < 2; mt++) {
        float s = ls[mt], q = lq[mt];
        #pragma unroll
        for (int off = 16; off > 0; off >>= 1) {
            s += __shfl_xor_sync(0xFFFFFFFFu, s, off);
            q += __shfl_xor_sync(0xFFFFFFFFu, q, off);
        }
        if (lane == 0) {
            int g = chb * 4 + wc * 2 + mt;
            atomicAdd(&g_estats[((e * Bn + b) * 8 + g) * 2], s);
            atomicAdd(&g_estats[((e * Bn + b) * 8 + g) * 2 + 1], q);
        }
    }
}

// ---------------- K2: finalize expert GN coefs + router softmax ----------------
__global__ void k_router_fin(const float* __restrict__ gns, const float* __restrict__ gnb,
                             const float* __restrict__ w1, const float* __restrict__ b1,
                             const float* __restrict__ w2, const float* __restrict__ b2) {
    int tid = threadIdx.x;
    for (int i = tid; i < En * Bn * Cn; i += 256) {
        int e = i >> 11, b = (i >> 7) & 15, c = i & 127, g = c >> 4;
        float s = g_estats[((e * Bn + b) * 8 + g) * 2];
        float sq = g_estats[((e * Bn + b) * 8 + g) * 2 + 1];
        float mean = s * (1.f / 65536.f);
        float var = sq * (1.f / 65536.f) - mean * mean;
        float rstd = rsqrtf(var + 1e-5f);
        float a = rstd * gns[e * Cn + c];
        g_eca[i] = a;
        g_ecb[i] = gnb[e * Cn + c] - mean * a;
    }
    if (tid < 16) {
        int py = tid >> 2, px = tid & 3;
        float fe[32];
        float cy = (py + 0.5f) * 0.25f, cx = (px + 0.5f) * 0.25f;
        #pragma unroll
        for (int k = 0; k < 8; k++) {
            float fr = (float)(1 << k) * 3.14159265358979323846f;
            fe[k] = sinf(cy * fr);
            fe[8 + k] = cosf(cy * fr);
            fe[16 + k] = sinf(cx * fr);
            fe[24 + k] = cosf(cx * fr);
        }
        float hb[64];
        for (int j = 0; j < 64; j++) {
            float s = b1[j];
            for (int k = 0; k < 32; k++) s = fmaf(fe[k], w1[k * 64 + j], s);
            hb[j] = s / (1.f + expf(-s));
        }
        float lo[8];
        float mx = -1e30f;
        for (int ee = 0; ee < 8; ee++) {
            float s = b2[ee];
            for (int j = 0; j < 64; j++) s = fmaf(hb[j], w2[j * 8 + ee], s);
            lo[ee] = s;
            mx = fmaxf(mx, s);
        }
        float den = 0.f;
        for (int ee = 0; ee < 8; ee++) { lo[ee] = expf(lo[ee] - mx); den += lo[ee]; }
        float inv = 1.f / den;
        for (int ee = 0; ee < 8; ee++) g_wts[tid][ee] = lo[ee] * inv;
    }
}

// ---------------- K3: combine experts -> tf32 bits ----------------
__global__ void k_combine(const float* __restrict__ x) {
    size_t t = (size_t)blockIdx.x * 256 + threadIdx.x;
    size_t i = t * 4;
    int b = (int)(i >> 19);
    int c = (int)(i >> 12) & 127;
    int p = (int)(i & 4095);
    int patch = ((p >> 6) >> 4) * 4 + ((p & 63) >> 4);
    float4 outv = *(const float4*)(x + i);
    #pragma unroll
    for (int e = 0; e < 8; e++) {
        int ebc = (e * Bn + b) * Cn + c;
        float a = g_eca[ebc], bb = g_ecb[ebc];
        float wt = g_wts[patch][e];
        float4 y = *(const float4*)(g_y + (size_t)ebc * HWn + p);
        outv.x += wt * silu_f(fmaf(y.x, a, bb));
        outv.y += wt * silu_f(fmaf(y.y, a, bb));
        outv.z += wt * silu_f(fmaf(y.z, a, bb));
        outv.w += wt * silu_f(fmaf(y.w, a, bb));
    }
    uint4 o;
    o.x = to_tf32(outv.x);
    o.y = to_tf32(outv.y);
    o.z = to_tf32(outv.z);
    o.w = to_tf32(outv.w);
    *(uint4*)(g_combt + i) = o;
}

// ---------------- K4: pw1 1x1 (128->512) via tf32 mma, cp.async DB + gn1 stats ----------------
__global__ __launch_bounds__(256) void k_pw1m() {
    __shared__ unsigned As[2][8 * 136];
    __shared__ unsigned Bs[2][8 * 136];
    const int pxb = blockIdx.x * 128;
    const int hcb = blockIdx.y * 128;
    const int b = blockIdx.z;
    const int tid = threadIdx.x;
    const int warp = tid >> 5;
    const int lane = tid & 31;
    const int wc = warp >> 1;
    const int wpx = warp & 1;
    const int grp = lane >> 2;
    const int tig = lane & 3;

    const unsigned sa = (unsigned)__cvta_generic_to_shared(&As[0][0]);
    const unsigned sb = (unsigned)__cvta_generic_to_shared(&Bs[0][0]);

    float acc[2][8][4];
    #pragma unroll
    for (int mt = 0; mt < 2; mt++)
        #pragma unroll
        for (int nt = 0; nt < 8; nt++)
            #pragma unroll
            for (int q = 0; q < 4; q++) acc[mt][nt][q] = 0.f;

    auto stage = [&](int cc, int buf) {
        cpa16(sa + (buf * 1088 + (tid >> 5) * 136 + (tid & 31) * 4) * 4,
              g_w1t + (size_t)((blockIdx.y * 16 + cc) * 8) * 128 + (tid >> 5) * 128 + (tid & 31) * 4);
        cpa16(sb + (buf * 1088 + (tid >> 5) * 136 + (tid & 31) * 4) * 4,
              g_combt + (size_t)(b * Cn + cc * 8 + (tid >> 5)) * HWn + pxb + (tid & 31) * 4);
    };

    stage(0, 0);
    cp_commit();

    for (int cc = 0; cc < 16; cc++) {
        if (cc < 15) {
            stage(cc + 1, (cc + 1) & 1);
            cp_commit();
            asm volatile("cp.async.wait_group 1;");
        } else {
            asm volatile("cp.async.wait_group 0;");
        }
        __syncthreads();

        const unsigned* Ab = &As[cc & 1][0];
        const unsigned* Bb = &Bs[cc & 1][0];

        unsigned a0[2], a1[2], a2[2], a3[2];
        #pragma unroll
        for (int mt = 0; mt < 2; mt++) {
            int hc_r = wc * 32 + mt * 16 + grp;
            a0[mt] = Ab[tig * 136 + hc_r];
            a1[mt] = Ab[tig * 136 + hc_r + 8];
            a2[mt] = Ab[(tig + 4) * 136 + hc_r];
            a3[mt] = Ab[(tig + 4) * 136 + hc_r + 8];
        }
        #pragma unroll
        for (int nt = 0; nt < 8; nt++) {
            int col = wpx * 64 + nt * 8 + grp;
            unsigned b0 = Bb[tig * 136 + col];
            unsigned b1 = Bb[(tig + 4) * 136 + col];
            mma_tf32(acc[0][nt][0], acc[0][nt][1], acc[0][nt][2], acc[0][nt][3],
                     a0[0], a1[0], a2[0], a3[0], b0, b1);
            mma_tf32(acc[1][nt][0], acc[1][nt][1], acc[1][nt][2], acc[1][nt][3],
                     a0[1], a1[1], a2[1], a3[1], b0, b1);
        }
        __syncthreads();
    }

    #pragma unroll
    for (int mt = 0; mt < 2; mt++) {
        int hc0 = hcb + wc * 32 + mt * 16 + grp;
        float ls = 0.f, lq = 0.f;
        #pragma unroll
        for (int nt = 0; nt < 8; nt++) {
            int px = pxb + wpx * 64 + nt * 8 + 2 * tig;
            float2 v0 = make_float2(acc[mt][nt][0], acc[mt][nt][1]);
            float2 v1 = make_float2(acc[mt][nt][2], acc[mt][nt][3]);
            *(float2*)(g_h1 + (size_t)(b * HCn + hc0) * HWn + px) = v0;
            *(float2*)(g_h1 + (size_t)(b * HCn + hc0 + 8) * HWn + px) = v1;
            ls += v0.x + v0.y + v1.x + v1.y;
            lq += v0.x * v0.x + v0.y * v0.y + v1.x * v1.x + v1.y * v1.y;
        }
        #pragma unroll
        for (int off = 16; off > 0; off >>= 1) {
            ls += __shfl_xor_sync(0xFFFFFFFFu, ls, off);
            lq += __shfl_xor_sync(0xFFFFFFFFu, lq, off);
        }
        if (lane == 0) {
            int g = (hcb >> 6) + (wc >> 1);
            atomicAdd(&g_s1[(b * 8 + g) * 2], ls);
            atomicAdd(&g_s1[(b * 8 + g) * 2 + 1], lq);
        }
    }
}

// ---------------- K5: depthwise 3x3 (gn1 inline), compact even-px store + gn2 stats ----------------
__global__ __launch_bounds__(256) void k_dw(const float* __restrict__ w_dw,
                                            const float* __restrict__ gn1s,
                                            const float* __restrict__ gn1b) {
    int rt = blockIdx.x;
    int hc = blockIdx.y;
    int b = blockIdx.z;
    __shared__ float xs[18][66];
    __shared__ float sred[2];
    int tid = threadIdx.x;
    int g1 = hc >> 6;
    float su = g_s1[(b * 8 + g1) * 2], sq = g_s1[(b * 8 + g1) * 2 + 1];
    float mean = su * (1.f / 262144.f);
    float var = sq * (1.f / 262144.f) - mean * mean;
    float rstd = rsqrtf(var + 1e-5f);
    float a = rstd * gn1s[hc];
    float bb = gn1b[hc] - mean * a;

    const float* src = g_h1 + (size_t)(b * HCn + hc) * HWn;
    int r0 = rt * 16;
    for (int idx = tid; idx < 18 * 66; idx += 256) {
        int rr = idx / 66, cx = idx % 66;
        int gy = r0 - 1 + rr, gx = cx - 1;
        float v = 0.f;
        if ((unsigned)gy < 64u && (unsigned)gx < 64u)
            v = silu_f(fmaf(src[gy * 64 + gx], a, bb));
        xs[rr][cx] = v;
    }
    float wd[9];
    #pragma unroll
    for (int t9 = 0; t9 < 9; t9++) wd[t9] = __ldg(&w_dw[hc * 9 + t9]);
    __syncthreads();
    float lsum = 0.f, lsq = 0.f;
    float* dst = g_h2s + (size_t)(b * HCn + hc) * OHWn;
    #pragma unroll
    for (int k4 = 0; k4 < 4; k4++) {
        int idx = tid + k4 * 256;
        int row = idx >> 6, col = idx & 63;
        float sum = 0.f;
        #pragma unroll
        for (int kh = 0; kh < 3; kh++)
            #pragma unroll
            for (int kw = 0; kw < 3; kw++)
                sum = fmaf(wd[kh * 3 + kw], xs[row + kh][col + kw], sum);
        int gr = r0 + row;
        if (((gr & 1) | (col & 1)) == 0)
            dst[(gr >> 1) * 32 + (col >> 1)] = sum;   // compact even-px store
        lsum += sum;
        lsq += sum * sum;
    }
    if (tid < 2) sred[tid] = 0.f;
    __syncthreads();
    atomicAdd(&sred[0], lsum);
    atomicAdd(&sred[1], lsq);
    __syncthreads();
    if (tid == 0) {
        int g = hc >> 6;
        atomicAdd(&g_s2[(b * 8 + g) * 2], sred[0]);
        atomicAdd(&g_s2[(b * 8 + g) * 2 + 1], sred[1]);
    }
}

// ---------------- K6: pw2 1x1 stride-2 via tf32 mma, K-split x2, DB ----------------
__global__ __launch_bounds__(256) void k_pw2m(const float* __restrict__ gn2s,
                                              const float* __restrict__ gn2b) {
    __shared__ unsigned As[2][8 * 136];
    __shared__ unsigned Bs[2][8 * 136];
    const int pxb = blockIdx.x * 128;
    const int ky = blockIdx.y;               // K split: 0 or 1 (32 chunks each)
    const int b = blockIdx.z;
    const int tid = threadIdx.x;
    const int warp = tid >> 5;
    const int lane = tid & 31;
    const int wc = warp >> 1;
    const int wpx = warp & 1;
    const int grp = lane >> 2;
    const int tig = lane & 3;
    const int r = warp;
    const unsigned sa = (unsigned)__cvta_generic_to_shared(&As[0][0]);

    float acc[2][8][4];
    #pragma unroll
    for (int mt = 0; mt < 2; mt++)
        #pragma unroll
        for (int nt = 0; nt < 8; nt++)
            #pragma unroll
            for (int q = 0; q < 4; q++) acc[mt][nt][q] = 0.f;

    auto loadB = [&](int cc, float* breg) {
        int ch = (ky * 32 + cc) * 8 + r;
        float4 v = *(const float4*)(g_h2s + (size_t)(b * HCn + ch) * OHWn + pxb + lane * 4);
        breg[0] = v.x; breg[1] = v.y; breg[2] = v.z; breg[3] = v.w;
    };
    auto coefs = [&](int cc, float& a, float& bb) {
        int ch = (ky * 32 + cc) * 8 + r;
        int g2 = ch >> 6;
        float su = g_s2[(b * 8 + g2) * 2], sq = g_s2[(b * 8 + g2) * 2 + 1];
        float mean = su * (1.f / 262144.f);
        float var = sq * (1.f / 262144.f) - mean * mean;
        float rstd = rsqrtf(var + 1e-5f);
        a = rstd * gn2s[ch];
        bb = gn2b[ch] - mean * a;
    };
    auto stsB = [&](int buf, const float* breg, float a, float bb) {
        uint4 v;
        v.x = to_tf32(silu_f(fmaf(breg[0], a, bb)));
        v.y = to_tf32(silu_f(fmaf(breg[1], a, bb)));
        v.z = to_tf32(silu_f(fmaf(breg[2], a, bb)));
        v.w = to_tf32(silu_f(fmaf(breg[3], a, bb)));
        *(uint4*)(&Bs[buf][r * 136 + lane * 4]) = v;
    };
    auto stageA = [&](int cc, int buf) {
        cpa16(sa + (buf * 1088 + (tid >> 5) * 136 + (tid & 31) * 4) * 4,
              g_w2t + (size_t)(ky * 32 + cc) * 1024 + (tid >> 5) * 128 + (tid & 31) * 4);
    };

    float breg[4], brega, bregb;
    loadB(0, breg);
    coefs(0, brega, bregb);
    stageA(0, 0);
    cp_commit();
    stsB(0, breg, brega, bregb);

    for (int cc = 0; cc < 32; cc++) {
        float nreg[4], na, nb2;
        if (cc < 31) {
            loadB(cc + 1, nreg);
            coefs(cc + 1, na, nb2);
            stageA(cc + 1, (cc + 1) & 1);
            cp_commit();
            asm volatile("cp.async.wait_group 1;");
        } else {
            asm volatile("cp.async.wait_group 0;");
        }
        __syncthreads();

        const unsigned* Ab = &As[cc & 1][0];
        const unsigned* Bb = &Bs[cc & 1][0];

        unsigned a0[2], a1[2], a2[2], a3[2];
        #pragma unroll
        for (int mt = 0; mt < 2; mt++) {
            int co_r = wc * 32 + mt * 16 + grp;
            a0[mt] = Ab[tig * 136 + co_r];
            a1[mt] = Ab[tig * 136 + co_r + 8];
            a2[mt] = Ab[(tig + 4) * 136 + co_r];
            a3[mt] = Ab[(tig + 4) * 136 + co_r + 8];
        }
        #pragma unroll
        for (int nt = 0; nt < 8; nt++) {
            int col = wpx * 64 + nt * 8 + grp;
            unsigned b0 = Bb[tig * 136 + col];
            unsigned b1 = Bb[(tig + 4) * 136 + col];
            mma_tf32(acc[0][nt][0], acc[0][nt][1], acc[0][nt][2], acc[0][nt][3],
                     a0[0], a1[0], a2[0], a3[0], b0, b1);
            mma_tf32(acc[1][nt][0], acc[1][nt][1], acc[1][nt][2], acc[1][nt][3],
                     a0[1], a1[1], a2[1], a3[1], b0, b1);
        }
        __syncthreads();
        if (cc < 31) stsB((cc + 1) & 1, nreg, na, nb2);
    }

    float* po = g_po + (size_t)ky * (Bn * Cn * OHWn);
    #pragma unroll
    for (int mt = 0; mt < 2; mt++) {
        int co0 = wc * 32 + mt * 16 + grp;
        #pragma unroll
        for (int nt = 0; nt < 8; nt++) {
            int px = pxb + wpx * 64 + nt * 8 + 2 * tig;
            *(float2*)(po + (size_t)(b * Cn + co0) * OHWn + px) =
                make_float2(acc[mt][nt][0], acc[mt][nt][1]);
            *(float2*)(po + (size_t)(b * Cn + co0 + 8) * OHWn + px) =
                make_float2(acc[mt][nt][2], acc[mt][nt][3]);
        }
    }
}

// ---------------- K6b: sum K-split partials + gn3 stats ----------------
__global__ __launch_bounds__(256) void k_s3() {
    const int b = blockIdx.x;
    const int g = blockIdx.y;
    const int tid = threadIdx.x;
    __shared__ float rs[8], rq[8];
    float s = 0.f, q = 0.f;
    const size_t base = (size_t)(b * Cn + g * 16) * OHWn;
    for (int i = tid; i < 16 * OHWn; i += 256) {
        float v = g_po[base + i] + g_po[(size_t)(Bn * Cn * OHWn) + base + i];
        g_o[base + i] = v;
        s += v;
        q += v * v;
    }
    #pragma unroll
    for (int off = 16; off > 0; off >>= 1) {
        s += __shfl_xor_sync(0xFFFFFFFFu, s, off);
        q += __shfl_xor_sync(0xFFFFFFFFu, q, off);
    }
    if ((tid & 31) == 0) { rs[tid >> 5] = s; rq[tid >> 5] = q; }
    __syncthreads();
    if (tid == 0) {
        float ts = 0.f, tq = 0.f;
        #pragma unroll
        for (int w = 0; w < 8; w++) { ts += rs[w]; tq += rq[w]; }
        g_s3[(b * 8 + g) * 2] = ts;
        g_s3[(b * 8 + g) * 2 + 1] = tq;
    }
}

// ---------------- K7: final gn3 + silu ----------------
__global__ void k_out(float* __restrict__ out, const float* __restrict__ gn3s,
                      const float* __restrict__ gn3b) {
    int i = blockIdx.x * 256 + threadIdx.x;
    int b = i >> 17;
    int c = (i >> 10) & 127;
    int g = c >> 4;
    float su = g_s3[(b * 8 + g) * 2], sq = g_s3[(b * 8 + g) * 2 + 1];
    float mean = su * (1.f / 16384.f);
    float var = sq * (1.f / 16384.f) - mean * mean;
    float rstd = rsqrtf(var + 1e-5f);
    float a = rstd * gn3s[c];
    float bb = gn3b[c] - mean * a;
    out[i] = silu_f(fmaf(g_o[i], a, bb));
}

// ---------------- launch ----------------
extern "C" void kernel_launch(void* const* d_in, const int* in_sizes, int n_in,
                              void* d_out, int out_size) {
    const float* x      = (const float*)d_in[0];
    const float* w_exp  = (const float*)d_in[1];
    const float* gns    = (const float*)d_in[2];
    const float* gnb    = (const float*)d_in[3];
    const float* w1     = (const float*)d_in[4];
    const float* b1     = (const float*)d_in[5];
    const float* w2     = (const float*)d_in[6];
    const float* b2     = (const float*)d_in[7];
    const float* w_pw1  = (const float*)d_in[8];
    const float* gn1s   = (const float*)d_in[9];
    const float* gn1b   = (const float*)d_in[10];
    const float* w_dw   = (const float*)d_in[11];
    const float* gn2s   = (const float*)d_in[12];
    const float* gn2b   = (const float*)d_in[13];
    const float* w_pw2  = (const float*)d_in[14];
    const float* gn3s   = (const float*)d_in[15];
    const float* gn3b   = (const float*)d_in[16];
    float* out = (float*)d_out;

    const int expert_smem = (2 * WS_BUF + 2 * XS_BUF) * 4;
    cudaFuncSetAttribute(k_expert, cudaFuncAttributeMaxDynamicSharedMemorySize,
                         expert_smem);

    // k_expert stays at slot 4 for the ncu window
    k_zero<<<8, 256>>>();
    k_wprep<<<(En * 16 * 9 * 8 * 128 + 255) / 256, 256>>>(w_exp);
    k_xprep<<<(Bn * Cn * HWn) / 256, 256>>>(x);
    {
        dim3 g(16, 2, En * Bn);
        k_expert<<<g, 256, expert_smem>>>();
    }
    k_w1prep<<<(4 * 16 * 8 * 128 + 255) / 256, 256>>>(w_pw1);
    k_w2prep<<<(64 * 8 * 128 + 255) / 256, 256>>>(w_pw2);
    k_router_fin<<<1, 256>>>(gns, gnb, w1, b1, w2, b2);
    k_combine<<<8192, 256>>>(x);
    {
        dim3 g(32, 4, Bn);
        k_pw1m<<<g, 256>>>();
    }
    {
        dim3 g(4, HCn, Bn);
        k_dw<<<g, 256>>>(w_dw, gn1s, gn1b);
    }
    {
        dim3 g(8, 2, Bn);
        k_pw2m<<<g, 256>>>(gn2s, gn2b);
    }
    {
        dim3 g(Bn, 8);
        k_s3<<<g, 256>>>();
    }
    k_out<<<8192, 256>>>(out, gn3s, gn3b);
}

// round 13
// speedup vs baseline: 1.5807x; 1.0089x over previous
#include <cuda_runtime.h>
#include <math.h>

#define En 8
#define Bn 16
#define Cn 128
#define Hn 64
#define Wn 64
#define HWn 4096
#define HCn 512
#define OHWn 1024

// ---------------- scratch (device globals; no allocation) ----------------
__device__ float g_y[(size_t)En * Bn * Cn * HWn];
__device__ unsigned g_combt[(size_t)Bn * Cn * HWn];    // combined, tf32 bits
__device__ float g_h1[(size_t)Bn * HCn * HWn];
__device__ float g_h2s[(size_t)Bn * HCn * OHWn];       // dw output, even px only (32x32)
__device__ unsigned g_h2t[(size_t)Bn * HCn * OHWn];    // gn2+silu applied, tf32 bits
__device__ float g_po[(size_t)2 * Bn * Cn * OHWn];     // pw2 K-split partials
__device__ unsigned g_wt[(size_t)En * 16 * 9 * 8 * 128];
__device__ unsigned g_w1t[(size_t)4 * 16 * 8 * 128];
__device__ unsigned g_w2t[(size_t)64 * 8 * 128];
__device__ unsigned g_xt[(size_t)Bn * Cn * HWn];
__device__ float g_estats[En * Bn * 8 * 2];
__device__ float g_eca[En * Bn * Cn];
__device__ float g_ecb[En * Bn * Cn];
__device__ float g_wts[16][En];
__device__ float g_s1[Bn * 8 * 2];
__device__ float g_s2[Bn * 8 * 2];
__device__ float g_s3[Bn * 8 * 2];

__device__ __forceinline__ float silu_f(float v) { return v / (1.f + __expf(-v)); }

__device__ __forceinline__ unsigned to_tf32(float f) {
    unsigned r;
    asm("cvt.rna.tf32.f32 %0, %1;" : "=r"(r) : "f"(f));
    return r;
}

__device__ __forceinline__ void mma_tf32(float& c0, float& c1, float& c2, float& c3,
                                         unsigned a0, unsigned a1, unsigned a2, unsigned a3,
                                         unsigned b0, unsigned b1) {
    asm volatile(
        "mma.sync.aligned.m16n8k8.row.col.f32.tf32.tf32.f32 "
        "{%0,%1,%2,%3}, {%4,%5,%6,%7}, {%8,%9}, {%0,%1,%2,%3};"
        : "+f"(c0), "+f"(c1), "+f"(c2), "+f"(c3)
        : "r"(a0), "r"(a1), "r"(a2), "r"(a3), "r"(b0), "r"(b1));
}

// ---- cp.async helpers ----
__device__ __forceinline__ void cpa16(unsigned dst, const void* src) {
    asm volatile("cp.async.cg.shared.global [%0], [%1], 16;" :: "r"(dst), "l"(src));
}
__device__ __forceinline__ void cpa16z(unsigned dst, const void* src, int sz) {
    asm volatile("cp.async.cg.shared.global [%0], [%1], 16, %2;"
                 :: "r"(dst), "l"(src), "r"(sz));
}
__device__ __forceinline__ void cp_commit() {
    asm volatile("cp.async.commit_group;");
}

// ---------------- K0: zero the stats accumulators ----------------
__global__ void k_zero() {
    int i = blockIdx.x * 256 + threadIdx.x;
    if (i < En * Bn * 8 * 2) g_estats[i] = 0.f;
    if (i < Bn * 8 * 2) { g_s1[i] = 0.f; g_s2[i] = 0.f; }
}

// ---------------- W preps ----------------
__global__ void k_wprep(const float* __restrict__ w_exp) {
    int i = blockIdx.x * 256 + threadIdx.x;
    if (i >= En * 16 * 9 * 8 * 128) return;
    int co = i & 127;
    int r = i >> 7;
    int ci = r & 7; r >>= 3;
    int tap = r % 9; r /= 9;
    int cc = r & 15;
    int e = r >> 4;
    g_wt[i] = to_tf32(w_exp[((size_t)(e * 128 + co) * 128 + cc * 8 + ci) * 9 + tap]);
}
__global__ void k_w1prep(const float* __restrict__ w_pw1) {
    int i = blockIdx.x * 256 + threadIdx.x;
    if (i >= 4 * 16 * 8 * 128) return;
    int hcl = i & 127;
    int ci = (i >> 7) & 7;
    int cc = (i >> 10) & 15;
    int blk = i >> 14;
    g_w1t[i] = to_tf32(w_pw1[(size_t)(blk * 128 + hcl) * 128 + cc * 8 + ci]);
}
__global__ void k_w2prep(const float* __restrict__ w_pw2) {
    int i = blockIdx.x * 256 + threadIdx.x;
    if (i >= 64 * 8 * 128) return;
    int co = i & 127;
    int ci = (i >> 7) & 7;
    int cc = i >> 10;
    g_w2t[i] = to_tf32(w_pw2[(size_t)co * 512 + cc * 8 + ci]);
}
__global__ void k_xprep(const float* __restrict__ x) {
    int i = blockIdx.x * 256 + threadIdx.x;
    g_xt[i] = to_tf32(x[i]);
}

// ---------------- K1: expert 3x3 conv via tf32 mma (unchanged from R11) ----------------
#define WS_STRIDE 72
#define WS_BUF (72 * WS_STRIDE)
#define XR_STRIDE 76
#define XS_BUF (48 * XR_STRIDE)
__global__ __launch_bounds__(256, 2) void k_expert() {
    extern __shared__ unsigned sm[];
    const int ty0 = blockIdx.x * 4;
    const int chb = blockIdx.y;
    const int e = blockIdx.z >> 4;
    const int b = blockIdx.z & 15;

    const int tid = threadIdx.x;
    const int warp = tid >> 5;
    const int lane = tid & 31;
    const int wc = warp >> 2;
    const int wp = warp & 3;
    const int grp = lane >> 2;
    const int tig = lane & 3;

    const unsigned smbase = (unsigned)__cvta_generic_to_shared(sm);

    float acc[2][8][4];
    #pragma unroll
    for (int mt = 0; mt < 2; mt++)
        #pragma unroll
        for (int nt = 0; nt < 8; nt++)
            #pragma unroll
            for (int q = 0; q < 4; q++) acc[mt][nt][q] = 0.f;

    const unsigned* wt = g_wt + (size_t)e * 147456 + chb * 64;
    const unsigned* xt = g_xt + (size_t)b * Cn * HWn;

    if (tid < 96) {
        int buf = tid / 48;
        int r = tid - buf * 48;
        sm[2 * WS_BUF + buf * XS_BUF + r * XR_STRIDE + 3] = 0u;
        sm[2 * WS_BUF + buf * XS_BUF + r * XR_STRIDE + 68] = 0u;
    }
    __syncthreads();

    auto stage = [&](int cc, int buf) {
        const unsigned wsoff = buf * WS_BUF;
        #pragma unroll
        for (int it = 0; it < 5; it++) {
            int idx = tid + it * 256;
            if (idx < 1152) {
                int rw = idx >> 4, q = idx & 15;
                cpa16(smbase + (wsoff + rw * WS_STRIDE + q * 4) * 4,
                      wt + (size_t)cc * 9216 + rw * 128 + q * 4);
            }
        }
        const unsigned xsoff = 2 * WS_BUF + buf * XS_BUF;
        if (lane < 16) {
            const unsigned* src = xt + (size_t)(cc * 8 + warp) * HWn + (ty0 - 1) * 64 + lane * 4;
            #pragma unroll
            for (int rr = 0; rr < 6; rr++) {
                int gy = ty0 - 1 + rr;
                bool ok = (unsigned)gy < 64u;
                cpa16z(smbase + (xsoff + (warp * 6 + rr) * XR_STRIDE + 4 + lane * 4) * 4,
                       ok ? (const void*)(src + rr * 64) : (const void*)xt, ok ? 16 : 0);
            }
        }
    };

    stage(0, 0);
    cp_commit();

    for (int cc = 0; cc < 16; cc++) {
        if (cc < 15) {
            stage(cc + 1, (cc + 1) & 1);
            cp_commit();
            asm volatile("cp.async.wait_group 1;");
        } else {
            asm volatile("cp.async.wait_group 0;");
        }
        __syncthreads();

        const unsigned* ws = sm + (cc & 1) * WS_BUF;
        const unsigned* xs = sm + 2 * WS_BUF + (cc & 1) * XS_BUF;

        #pragma unroll
        for (int tap = 0; tap < 9; tap++) {
            const int kh = tap / 3, kw = tap % 3;
            unsigned a0[2], a1[2], a2[2], a3[2];
            #pragma unroll
            for (int mt = 0; mt < 2; mt++) {
                int co_r = wc * 32 + mt * 16 + grp;
                a0[mt] = ws[(tap * 8 + tig) * WS_STRIDE + co_r];
                a1[mt] = ws[(tap * 8 + tig) * WS_STRIDE + co_r + 8];
                a2[mt] = ws[(tap * 8 + tig + 4) * WS_STRIDE + co_r];
                a3[mt] = ws[(tap * 8 + tig + 4) * WS_STRIDE + co_r + 8];
            }
            #pragma unroll
            for (int nt = 0; nt < 8; nt++) {
                int col = 3 + nt * 8 + grp + kw;
                unsigned b0 = xs[(tig * 6 + wp + kh) * XR_STRIDE + col];
                unsigned b1 = xs[((tig + 4) * 6 + wp + kh) * XR_STRIDE + col];
                mma_tf32(acc[0][nt][0], acc[0][nt][1], acc[0][nt][2], acc[0][nt][3],
                         a0[0], a1[0], a2[0], a3[0], b0, b1);
                mma_tf32(acc[1][nt][0], acc[1][nt][1], acc[1][nt][2], acc[1][nt][3],
                         a0[1], a1[1], a2[1], a3[1], b0, b1);
            }
        }
        __syncthreads();
    }

    size_t ybase = (size_t)(e * Bn + b) * Cn * HWn;
    const int row = ty0 + wp;
    float ls[2] = {0.f, 0.f}, lq[2] = {0.f, 0.f};
    #pragma unroll
    for (int mt = 0; mt < 2; mt++) {
        int co = chb * 64 + wc * 32 + mt * 16 + grp;
        #pragma unroll
        for (int nt = 0; nt < 8; nt++) {
            int colx = nt * 8 + 2 * tig;
            float2 v0 = make_float2(acc[mt][nt][0], acc[mt][nt][1]);
            float2 v1 = make_float2(acc[mt][nt][2], acc[mt][nt][3]);
            *(float2*)(g_y + ybase + (size_t)co * HWn + row * 64 + colx) = v0;
            *(float2*)(g_y + ybase + (size_t)(co + 8) * HWn + row * 64 + colx) = v1;
            ls[mt] += v0.x + v0.y + v1.x + v1.y;
            lq[mt] += v0.x * v0.x + v0.y * v0.y + v1.x * v1.x + v1.y * v1.y;
        }
    }
    #pragma unroll
    for (int mt = 0; mt < 2; mt++) {
        float s = ls[mt], q = lq[mt];
        #pragma unroll
        for (int off = 16; off > 0; off >>= 1) {
            s += __shfl_xor_sync(0xFFFFFFFFu, s, off);
            q += __shfl_xor_sync(0xFFFFFFFFu, q, off);
        }
        if (lane == 0) {
            int g = chb * 4 + wc * 2 + mt;
            atomicAdd(&g_estats[((e * Bn + b) * 8 + g) * 2], s);
            atomicAdd(&g_estats[((e * Bn + b) * 8 + g) * 2 + 1], q);
        }
    }
}

// ---------------- K2: finalize expert GN coefs + router softmax ----------------
__global__ void k_router_fin(const float* __restrict__ gns, const float* __restrict__ gnb,
                             const float* __restrict__ w1, const float* __restrict__ b1,
                             const float* __restrict__ w2, const float* __restrict__ b2) {
    int tid = threadIdx.x;
    for (int i = tid; i < En * Bn * Cn; i += 256) {
        int e = i >> 11, b = (i >> 7) & 15, c = i & 127, g = c >> 4;
        float s = g_estats[((e * Bn + b) * 8 + g) * 2];
        float sq = g_estats[((e * Bn + b) * 8 + g) * 2 + 1];
        float mean = s * (1.f / 65536.f);
        float var = sq * (1.f / 65536.f) - mean * mean;
        float rstd = rsqrtf(var + 1e-5f);
        float a = rstd * gns[e * Cn + c];
        g_eca[i] = a;
        g_ecb[i] = gnb[e * Cn + c] - mean * a;
    }
    if (tid < 16) {
        int py = tid >> 2, px = tid & 3;
        float fe[32];
        float cy = (py + 0.5f) * 0.25f, cx = (px + 0.5f) * 0.25f;
        #pragma unroll
        for (int k = 0; k < 8; k++) {
            float fr = (float)(1 << k) * 3.14159265358979323846f;
            fe[k] = sinf(cy * fr);
            fe[8 + k] = cosf(cy * fr);
            fe[16 + k] = sinf(cx * fr);
            fe[24 + k] = cosf(cx * fr);
        }
        float hb[64];
        for (int j = 0; j < 64; j++) {
            float s = b1[j];
            for (int k = 0; k < 32; k++) s = fmaf(fe[k], w1[k * 64 + j], s);
            hb[j] = s / (1.f + expf(-s));
        }
        float lo[8];
        float mx = -1e30f;
        for (int ee = 0; ee < 8; ee++) {
            float s = b2[ee];
            for (int j = 0; j < 64; j++) s = fmaf(hb[j], w2[j * 8 + ee], s);
            lo[ee] = s;
            mx = fmaxf(mx, s);
        }
        float den = 0.f;
        for (int ee = 0; ee < 8; ee++) { lo[ee] = expf(lo[ee] - mx); den += lo[ee]; }
        float inv = 1.f / den;
        for (int ee = 0; ee < 8; ee++) g_wts[tid][ee] = lo[ee] * inv;
    }
}

// ---------------- K3: combine experts -> tf32 bits ----------------
__global__ void k_combine(const float* __restrict__ x) {
    size_t t = (size_t)blockIdx.x * 256 + threadIdx.x;
    size_t i = t * 4;
    int b = (int)(i >> 19);
    int c = (int)(i >> 12) & 127;
    int p = (int)(i & 4095);
    int patch = ((p >> 6) >> 4) * 4 + ((p & 63) >> 4);
    float4 outv = *(const float4*)(x + i);
    #pragma unroll
    for (int e = 0; e < 8; e++) {
        int ebc = (e * Bn + b) * Cn + c;
        float a = g_eca[ebc], bb = g_ecb[ebc];
        float wt = g_wts[patch][e];
        float4 y = *(const float4*)(g_y + (size_t)ebc * HWn + p);
        outv.x += wt * silu_f(fmaf(y.x, a, bb));
        outv.y += wt * silu_f(fmaf(y.y, a, bb));
        outv.z += wt * silu_f(fmaf(y.z, a, bb));
        outv.w += wt * silu_f(fmaf(y.w, a, bb));
    }
    uint4 o;
    o.x = to_tf32(outv.x);
    o.y = to_tf32(outv.y);
    o.z = to_tf32(outv.z);
    o.w = to_tf32(outv.w);
    *(uint4*)(g_combt + i) = o;
}

// ---------------- K4: pw1 1x1 via tf32 mma, 4-stage cp.async + gn1 stats ----------------
__global__ __launch_bounds__(256) void k_pw1m() {
    __shared__ unsigned As[4][8 * 136];
    __shared__ unsigned Bs[4][8 * 136];
    const int pxb = blockIdx.x * 128;
    const int hcb = blockIdx.y * 128;
    const int b = blockIdx.z;
    const int tid = threadIdx.x;
    const int lane = tid & 31;
    const int warp = tid >> 5;
    const int wc = warp >> 1;
    const int wpx = warp & 1;
    const int grp = lane >> 2;
    const int tig = lane & 3;

    const unsigned sa = (unsigned)__cvta_generic_to_shared(&As[0][0]);
    const unsigned sb = (unsigned)__cvta_generic_to_shared(&Bs[0][0]);

    float acc[2][8][4];
    #pragma unroll
    for (int mt = 0; mt < 2; mt++)
        #pragma unroll
        for (int nt = 0; nt < 8; nt++)
            #pragma unroll
            for (int q = 0; q < 4; q++) acc[mt][nt][q] = 0.f;

    auto stage = [&](int cc, int buf) {
        cpa16(sa + (buf * 1088 + warp * 136 + lane * 4) * 4,
              g_w1t + (size_t)((blockIdx.y * 16 + cc) * 8) * 128 + warp * 128 + lane * 4);
        cpa16(sb + (buf * 1088 + warp * 136 + lane * 4) * 4,
              g_combt + (size_t)(b * Cn + cc * 8 + warp) * HWn + pxb + lane * 4);
    };

    stage(0, 0); cp_commit();
    stage(1, 1); cp_commit();
    stage(2, 2); cp_commit();

    for (int cc = 0; cc < 16; cc++) {
        if (cc + 3 < 16) {
            stage(cc + 3, (cc + 3) & 3);
            cp_commit();
            asm volatile("cp.async.wait_group 3;");
        } else if (cc == 13) {
            asm volatile("cp.async.wait_group 2;");
        } else if (cc == 14) {
            asm volatile("cp.async.wait_group 1;");
        } else {
            asm volatile("cp.async.wait_group 0;");
        }
        __syncthreads();

        const unsigned* Ab = &As[cc & 3][0];
        const unsigned* Bb = &Bs[cc & 3][0];

        unsigned a0[2], a1[2], a2[2], a3[2];
        #pragma unroll
        for (int mt = 0; mt < 2; mt++) {
            int hc_r = wc * 32 + mt * 16 + grp;
            a0[mt] = Ab[tig * 136 + hc_r];
            a1[mt] = Ab[tig * 136 + hc_r + 8];
            a2[mt] = Ab[(tig + 4) * 136 + hc_r];
            a3[mt] = Ab[(tig + 4) * 136 + hc_r + 8];
        }
        #pragma unroll
        for (int nt = 0; nt < 8; nt++) {
            int col = wpx * 64 + nt * 8 + grp;
            unsigned b0 = Bb[tig * 136 + col];
            unsigned b1 = Bb[(tig + 4) * 136 + col];
            mma_tf32(acc[0][nt][0], acc[0][nt][1], acc[0][nt][2], acc[0][nt][3],
                     a0[0], a1[0], a2[0], a3[0], b0, b1);
            mma_tf32(acc[1][nt][0], acc[1][nt][1], acc[1][nt][2], acc[1][nt][3],
                     a0[1], a1[1], a2[1], a3[1], b0, b1);
        }
        __syncthreads();
    }

    #pragma unroll
    for (int mt = 0; mt < 2; mt++) {
        int hc0 = hcb + wc * 32 + mt * 16 + grp;
        float ls = 0.f, lq = 0.f;
        #pragma unroll
        for (int nt = 0; nt < 8; nt++) {
            int px = pxb + wpx * 64 + nt * 8 + 2 * tig;
            float2 v0 = make_float2(acc[mt][nt][0], acc[mt][nt][1]);
            float2 v1 = make_float2(acc[mt][nt][2], acc[mt][nt][3]);
            *(float2*)(g_h1 + (size_t)(b * HCn + hc0) * HWn + px) = v0;
            *(float2*)(g_h1 + (size_t)(b * HCn + hc0 + 8) * HWn + px) = v1;
            ls += v0.x + v0.y + v1.x + v1.y;
            lq += v0.x * v0.x + v0.y * v0.y + v1.x * v1.x + v1.y * v1.y;
        }
        #pragma unroll
        for (int off = 16; off > 0; off >>= 1) {
            ls += __shfl_xor_sync(0xFFFFFFFFu, ls, off);
            lq += __shfl_xor_sync(0xFFFFFFFFu, lq, off);
        }
        if (lane == 0) {
            int g = (hcb >> 6) + (wc >> 1);
            atomicAdd(&g_s1[(b * 8 + g) * 2], ls);
            atomicAdd(&g_s1[(b * 8 + g) * 2 + 1], lq);
        }
    }
}

// ---------------- K5: depthwise 3x3 (gn1 inline), compact even-px store + gn2 stats ----------------
__global__ __launch_bounds__(256) void k_dw(const float* __restrict__ w_dw,
                                            const float* __restrict__ gn1s,
                                            const float* __restrict__ gn1b) {
    int rt = blockIdx.x;
    int hc = blockIdx.y;
    int b = blockIdx.z;
    __shared__ float xs[18][66];
    __shared__ float sred[2];
    int tid = threadIdx.x;
    int g1 = hc >> 6;
    float su = g_s1[(b * 8 + g1) * 2], sq = g_s1[(b * 8 + g1) * 2 + 1];
    float mean = su * (1.f / 262144.f);
    float var = sq * (1.f / 262144.f) - mean * mean;
    float rstd = rsqrtf(var + 1e-5f);
    float a = rstd * gn1s[hc];
    float bb = gn1b[hc] - mean * a;

    const float* src = g_h1 + (size_t)(b * HCn + hc) * HWn;
    int r0 = rt * 16;
    for (int idx = tid; idx < 18 * 66; idx += 256) {
        int rr = idx / 66, cx = idx % 66;
        int gy = r0 - 1 + rr, gx = cx - 1;
        float v = 0.f;
        if ((unsigned)gy < 64u && (unsigned)gx < 64u)
            v = silu_f(fmaf(src[gy * 64 + gx], a, bb));
        xs[rr][cx] = v;
    }
    float wd[9];
    #pragma unroll
    for (int t9 = 0; t9 < 9; t9++) wd[t9] = __ldg(&w_dw[hc * 9 + t9]);
    __syncthreads();
    float lsum = 0.f, lsq = 0.f;
    float* dst = g_h2s + (size_t)(b * HCn + hc) * OHWn;
    #pragma unroll
    for (int k4 = 0; k4 < 4; k4++) {
        int idx = tid + k4 * 256;
        int row = idx >> 6, col = idx & 63;
        float sum = 0.f;
        #pragma unroll
        for (int kh = 0; kh < 3; kh++)
            #pragma unroll
            for (int kw = 0; kw < 3; kw++)
                sum = fmaf(wd[kh * 3 + kw], xs[row + kh][col + kw], sum);
        int gr = r0 + row;
        if (((gr & 1) | (col & 1)) == 0)
            dst[(gr >> 1) * 32 + (col >> 1)] = sum;
        lsum += sum;
        lsq += sum * sum;
    }
    if (tid < 2) sred[tid] = 0.f;
    __syncthreads();
    atomicAdd(&sred[0], lsum);
    atomicAdd(&sred[1], lsq);
    __syncthreads();
    if (tid == 0) {
        int g = hc >> 6;
        atomicAdd(&g_s2[(b * 8 + g) * 2], sred[0]);
        atomicAdd(&g_s2[(b * 8 + g) * 2 + 1], sred[1]);
    }
}

// ---------------- K5b: apply gn2+silu -> tf32 bits (pw2 B operand prep) ----------------
__global__ void k_h2t(const float* __restrict__ gn2s, const float* __restrict__ gn2b) {
    int i = blockIdx.x * 256 + threadIdx.x;   // 8.4M elements
    int ch = (i >> 10) & 511;
    int b = i >> 19;
    int g2 = ch >> 6;
    float su = g_s2[(b * 8 + g2) * 2], sq = g_s2[(b * 8 + g2) * 2 + 1];
    float mean = su * (1.f / 262144.f);
    float var = sq * (1.f / 262144.f) - mean * mean;
    float rstd = rsqrtf(var + 1e-5f);
    float a = rstd * gn2s[ch];
    float bb = gn2b[ch] - mean * a;
    g_h2t[i] = to_tf32(silu_f(fmaf(g_h2s[i], a, bb)));
}

// ---------------- K6: pw2 pure GEMM, K-split x2, 4-stage cp.async ----------------
__global__ __launch_bounds__(256) void k_pw2m() {
    __shared__ unsigned As[4][8 * 136];
    __shared__ unsigned Bs[4][8 * 136];
    const int pxb = blockIdx.x * 128;
    const int ky = blockIdx.y;
    const int b = blockIdx.z;
    const int tid = threadIdx.x;
    const int lane = tid & 31;
    const int warp = tid >> 5;
    const int wc = warp >> 1;
    const int wpx = warp & 1;
    const int grp = lane >> 2;
    const int tig = lane & 3;

    const unsigned sa = (unsigned)__cvta_generic_to_shared(&As[0][0]);
    const unsigned sb = (unsigned)__cvta_generic_to_shared(&Bs[0][0]);

    float acc[2][8][4];
    #pragma unroll
    for (int mt = 0; mt < 2; mt++)
        #pragma unroll
        for (int nt = 0; nt < 8; nt++)
            #pragma unroll
            for (int q = 0; q < 4; q++) acc[mt][nt][q] = 0.f;

    auto stage = [&](int cc, int buf) {
        cpa16(sa + (buf * 1088 + warp * 136 + lane * 4) * 4,
              g_w2t + (size_t)(ky * 32 + cc) * 1024 + warp * 128 + lane * 4);
        cpa16(sb + (buf * 1088 + warp * 136 + lane * 4) * 4,
              g_h2t + (size_t)(b * HCn + (ky * 32 + cc) * 8 + warp) * OHWn + pxb + lane * 4);
    };

    stage(0, 0); cp_commit();
    stage(1, 1); cp_commit();
    stage(2, 2); cp_commit();

    for (int cc = 0; cc < 32; cc++) {
        if (cc + 3 < 32) {
            stage(cc + 3, (cc + 3) & 3);
            cp_commit();
            asm volatile("cp.async.wait_group 3;");
        } else if (cc == 29) {
            asm volatile("cp.async.wait_group 2;");
        } else if (cc == 30) {
            asm volatile("cp.async.wait_group 1;");
        } else {
            asm volatile("cp.async.wait_group 0;");
        }
        __syncthreads();

        const unsigned* Ab = &As[cc & 3][0];
        const unsigned* Bb = &Bs[cc & 3][0];

        unsigned a0[2], a1[2], a2[2], a3[2];
        #pragma unroll
        for (int mt = 0; mt < 2; mt++) {
            int co_r = wc * 32 + mt * 16 + grp;
            a0[mt] = Ab[tig * 136 + co_r];
            a1[mt] = Ab[tig * 136 + co_r + 8];
            a2[mt] = Ab[(tig + 4) * 136 + co_r];
            a3[mt] = Ab[(tig + 4) * 136 + co_r + 8];
        }
        #pragma unroll
        for (int nt = 0; nt < 8; nt++) {
            int col = wpx * 64 + nt * 8 + grp;
            unsigned b0 = Bb[tig * 136 + col];
            unsigned b1 = Bb[(tig + 4) * 136 + col];
            mma_tf32(acc[0][nt][0], acc[0][nt][1], acc[0][nt][2], acc[0][nt][3],
                     a0[0], a1[0], a2[0], a3[0], b0, b1);
            mma_tf32(acc[1][nt][0], acc[1][nt][1], acc[1][nt][2], acc[1][nt][3],
                     a0[1], a1[1], a2[1], a3[1], b0, b1);
        }
        __syncthreads();
    }

    float* po = g_po + (size_t)ky * (Bn * Cn * OHWn);
    #pragma unroll
    for (int mt = 0; mt < 2; mt++) {
        int co0 = wc * 32 + mt * 16 + grp;
        #pragma unroll
        for (int nt = 0; nt < 8; nt++) {
            int px = pxb + wpx * 64 + nt * 8 + 2 * tig;
            *(float2*)(po + (size_t)(b * Cn + co0) * OHWn + px) =
                make_float2(acc[mt][nt][0], acc[mt][nt][1]);
            *(float2*)(po + (size_t)(b * Cn + co0 + 8) * OHWn + px) =
                make_float2(acc[mt][nt][2], acc[mt][nt][3]);
        }
    }
}

// ---------------- K6b: gn3 stats from K-split partials ----------------
__global__ __launch_bounds__(256) void k_s3() {
    const int b = blockIdx.x;
    const int g = blockIdx.y;
    const int tid = threadIdx.x;
    __shared__ float rs[8], rq[8];
    float s = 0.f, q = 0.f;
    const size_t base = (size_t)(b * Cn + g * 16) * OHWn;
    for (int i = tid; i < 16 * OHWn; i += 256) {
        float v = g_po[base + i] + g_po[(size_t)(Bn * Cn * OHWn) + base + i];
        s += v;
        q += v * v;
    }
    #pragma unroll
    for (int off = 16; off > 0; off >>= 1) {
        s += __shfl_xor_sync(0xFFFFFFFFu, s, off);
        q += __shfl_xor_sync(0xFFFFFFFFu, q, off);
    }
    if ((tid & 31) == 0) { rs[tid >> 5] = s; rq[tid >> 5] = q; }
    __syncthreads();
    if (tid == 0) {
        float ts = 0.f, tq = 0.f;
        #pragma unroll
        for (int w = 0; w < 8; w++) { ts += rs[w]; tq += rq[w]; }
        g_s3[(b * 8 + g) * 2] = ts;
        g_s3[(b * 8 + g) * 2 + 1] = tq;
    }
}

// ---------------- K7: final gn3 + silu (reads partials directly) ----------------
__global__ void k_out(float* __restrict__ out, const float* __restrict__ gn3s,
                      const float* __restrict__ gn3b) {
    int i = blockIdx.x * 256 + threadIdx.x;
    int b = i >> 17;
    int c = (i >> 10) & 127;
    int g = c >> 4;
    float su = g_s3[(b * 8 + g) * 2], sq = g_s3[(b * 8 + g) * 2 + 1];
    float mean = su * (1.f / 16384.f);
    float var = sq * (1.f / 16384.f) - mean * mean;
    float rstd = rsqrtf(var + 1e-5f);
    float a = rstd * gn3s[c];
    float bb = gn3b[c] - mean * a;
    float v = g_po[i] + g_po[(size_t)(Bn * Cn * OHWn) + i];
    out[i] = silu_f(fmaf(v, a, bb));
}

// ---------------- launch ----------------
extern "C" void kernel_launch(void* const* d_in, const int* in_sizes, int n_in,
                              void* d_out, int out_size) {
    const float* x      = (const float*)d_in[0];
    const float* w_exp  = (const float*)d_in[1];
    const float* gns    = (const float*)d_in[2];
    const float* gnb    = (const float*)d_in[3];
    const float* w1     = (const float*)d_in[4];
    const float* b1     = (const float*)d_in[5];
    const float* w2     = (const float*)d_in[6];
    const float* b2     = (const float*)d_in[7];
    const float* w_pw1  = (const float*)d_in[8];
    const float* gn1s   = (const float*)d_in[9];
    const float* gn1b   = (const float*)d_in[10];
    const float* w_dw   = (const float*)d_in[11];
    const float* gn2s   = (const float*)d_in[12];
    const float* gn2b   = (const float*)d_in[13];
    const float* w_pw2  = (const float*)d_in[14];
    const float* gn3s   = (const float*)d_in[15];
    const float* gn3b   = (const float*)d_in[16];
    float* out = (float*)d_out;

    const int expert_smem = (2 * WS_BUF + 2 * XS_BUF) * 4;
    cudaFuncSetAttribute(k_expert, cudaFuncAttributeMaxDynamicSharedMemorySize,
                         expert_smem);

    // k_expert stays at slot 4 for the ncu window
    k_zero<<<8, 256>>>();
    k_wprep<<<(En * 16 * 9 * 8 * 128 + 255) / 256, 256>>>(w_exp);
    k_xprep<<<(Bn * Cn * HWn) / 256, 256>>>(x);
    {
        dim3 g(16, 2, En * Bn);
        k_expert<<<g, 256, expert_smem>>>();
    }
    k_w1prep<<<(4 * 16 * 8 * 128 + 255) / 256, 256>>>(w_pw1);
    k_w2prep<<<(64 * 8 * 128 + 255) / 256, 256>>>(w_pw2);
    k_router_fin<<<1, 256>>>(gns, gnb, w1, b1, w2, b2);
    k_combine<<<8192, 256>>>(x);
    {
        dim3 g(32, 4, Bn);
        k_pw1m<<<g, 256>>>();
    }
    {
        dim3 g(4, HCn, Bn);
        k_dw<<<g, 256>>>(w_dw, gn1s, gn1b);
    }
    k_h2t<<<(Bn * HCn * OHWn) / 256, 256>>>(gn2s, gn2b);
    {
        dim3 g(8, 2, Bn);
        k_pw2m<<<g, 256>>>();
    }
    {
        dim3 g(Bn, 8);
        k_s3<<<g, 256>>>();
    }
    k_out<<<8192, 256>>>(out, gn3s, gn3b);
}

// round 14
// speedup vs baseline: 2.4489x; 1.5492x over previous
#include <cuda_runtime.h>
#include <math.h>

#define En 8
#define Bn 16
#define Cn 128
#define Hn 64
#define Wn 64
#define HWn 4096
#define HCn 512
#define OHWn 1024

// ---------------- scratch (device globals; no allocation) ----------------
__device__ float g_y[(size_t)En * Bn * Cn * HWn];
__device__ unsigned g_combt[(size_t)Bn * Cn * HWn];    // combined, tf32 bits
__device__ float g_h1[(size_t)Bn * HCn * HWn];
__device__ float g_h2s[(size_t)Bn * HCn * OHWn];       // dw output, even px only (32x32)
__device__ float g_po[(size_t)2 * Bn * Cn * OHWn];     // pw2 K-split partials
__device__ unsigned g_wt[(size_t)En * 16 * 9 * 8 * 128];
__device__ unsigned g_w1t[(size_t)4 * 16 * 8 * 128];
__device__ unsigned g_w2t[(size_t)64 * 8 * 128];
__device__ unsigned g_xt[(size_t)Bn * Cn * HWn];
__device__ float g_estats[En * Bn * 8 * 2];
__device__ float g_eca[En * Bn * Cn];
__device__ float g_ecb[En * Bn * Cn];
__device__ float g_wts[16][En];
__device__ float g_s1[Bn * 8 * 2];
__device__ float g_s2[Bn * 8 * 2];

__device__ __forceinline__ float silu_f(float v) { return v / (1.f + __expf(-v)); }

__device__ __forceinline__ unsigned to_tf32(float f) {
    unsigned r;
    asm("cvt.rna.tf32.f32 %0, %1;" : "=r"(r) : "f"(f));
    return r;
}

__device__ __forceinline__ void mma_tf32(float& c0, float& c1, float& c2, float& c3,
                                         unsigned a0, unsigned a1, unsigned a2, unsigned a3,
                                         unsigned b0, unsigned b1) {
    asm volatile(
        "mma.sync.aligned.m16n8k8.row.col.f32.tf32.tf32.f32 "
        "{%0,%1,%2,%3}, {%4,%5,%6,%7}, {%8,%9}, {%0,%1,%2,%3};"
        : "+f"(c0), "+f"(c1), "+f"(c2), "+f"(c3)
        : "r"(a0), "r"(a1), "r"(a2), "r"(a3), "r"(b0), "r"(b1));
}

// ---- cp.async helpers ----
__device__ __forceinline__ void cpa16(unsigned dst, const void* src) {
    asm volatile("cp.async.cg.shared.global [%0], [%1], 16;" :: "r"(dst), "l"(src));
}
__device__ __forceinline__ void cpa16z(unsigned dst, const void* src, int sz) {
    asm volatile("cp.async.cg.shared.global [%0], [%1], 16, %2;"
                 :: "r"(dst), "l"(src), "r"(sz));
}
__device__ __forceinline__ void cp_commit() {
    asm volatile("cp.async.commit_group;");
}

// ---------------- K0: zero the stats accumulators ----------------
__global__ void k_zero() {
    int i = blockIdx.x * 256 + threadIdx.x;
    if (i < En * Bn * 8 * 2) g_estats[i] = 0.f;
    if (i < Bn * 8 * 2) { g_s1[i] = 0.f; g_s2[i] = 0.f; }
}

// ---------------- W preps ----------------
__global__ void k_wprep(const float* __restrict__ w_exp) {
    int i = blockIdx.x * 256 + threadIdx.x;
    if (i >= En * 16 * 9 * 8 * 128) return;
    int co = i & 127;
    int r = i >> 7;
    int ci = r & 7; r >>= 3;
    int tap = r % 9; r /= 9;
    int cc = r & 15;
    int e = r >> 4;
    g_wt[i] = to_tf32(w_exp[((size_t)(e * 128 + co) * 128 + cc * 8 + ci) * 9 + tap]);
}
__global__ void k_w1prep(const float* __restrict__ w_pw1) {
    int i = blockIdx.x * 256 + threadIdx.x;
    if (i >= 4 * 16 * 8 * 128) return;
    int hcl = i & 127;
    int ci = (i >> 7) & 7;
    int cc = (i >> 10) & 15;
    int blk = i >> 14;
    g_w1t[i] = to_tf32(w_pw1[(size_t)(blk * 128 + hcl) * 128 + cc * 8 + ci]);
}
__global__ void k_w2prep(const float* __restrict__ w_pw2) {
    int i = blockIdx.x * 256 + threadIdx.x;
    if (i >= 64 * 8 * 128) return;
    int co = i & 127;
    int ci = (i >> 7) & 7;
    int cc = i >> 10;
    g_w2t[i] = to_tf32(w_pw2[(size_t)co * 512 + cc * 8 + ci]);
}
__global__ void k_xprep(const float* __restrict__ x) {
    int i = blockIdx.x * 256 + threadIdx.x;
    g_xt[i] = to_tf32(x[i]);
}

// ---------------- K1: expert 3x3 conv via tf32 mma (unchanged) ----------------
#define WS_STRIDE 72
#define WS_BUF (72 * WS_STRIDE)
#define XR_STRIDE 76
#define XS_BUF (48 * XR_STRIDE)
__global__ __launch_bounds__(256, 2) void k_expert() {
    extern __shared__ unsigned sm[];
    const int ty0 = blockIdx.x * 4;
    const int chb = blockIdx.y;
    const int e = blockIdx.z >> 4;
    const int b = blockIdx.z & 15;

    const int tid = threadIdx.x;
    const int warp = tid >> 5;
    const int lane = tid & 31;
    const int wc = warp >> 2;
    const int wp = warp & 3;
    const int grp = lane >> 2;
    const int tig = lane & 3;

    const unsigned smbase = (unsigned)__cvta_generic_to_shared(sm);

    float acc[2][8][4];
    #pragma unroll
    for (int mt = 0; mt < 2; mt++)
        #pragma unroll
        for (int nt = 0; nt < 8; nt++)
            #pragma unroll
            for (int q = 0; q < 4; q++) acc[mt][nt][q] = 0.f;

    const unsigned* wt = g_wt + (size_t)e * 147456 + chb * 64;
    const unsigned* xt = g_xt + (size_t)b * Cn * HWn;

    if (tid < 96) {
        int buf = tid / 48;
        int r = tid - buf * 48;
        sm[2 * WS_BUF + buf * XS_BUF + r * XR_STRIDE + 3] = 0u;
        sm[2 * WS_BUF + buf * XS_BUF + r * XR_STRIDE + 68] = 0u;
    }
    __syncthreads();

    auto stage = [&](int cc, int buf) {
        const unsigned wsoff = buf * WS_BUF;
        #pragma unroll
        for (int it = 0; it < 5; it++) {
            int idx = tid + it * 256;
            if (idx < 1152) {
                int rw = idx >> 4, q = idx & 15;
                cpa16(smbase + (wsoff + rw * WS_STRIDE + q * 4) * 4,
                      wt + (size_t)cc * 9216 + rw * 128 + q * 4);
            }
        }
        const unsigned xsoff = 2 * WS_BUF + buf * XS_BUF;
        if (lane < 16) {
            const unsigned* src = xt + (size_t)(cc * 8 + warp) * HWn + (ty0 - 1) * 64 + lane * 4;
            #pragma unroll
            for (int rr = 0; rr < 6; rr++) {
                int gy = ty0 - 1 + rr;
                bool ok = (unsigned)gy < 64u;
                cpa16z(smbase + (xsoff + (warp * 6 + rr) * XR_STRIDE + 4 + lane * 4) * 4,
                       ok ? (const void*)(src + rr * 64) : (const void*)xt, ok ? 16 : 0);
            }
        }
    };

    stage(0, 0);
    cp_commit();

    for (int cc = 0; cc < 16; cc++) {
        if (cc < 15) {
            stage(cc + 1, (cc + 1) & 1);
            cp_commit();
            asm volatile("cp.async.wait_group 1;");
        } else {
            asm volatile("cp.async.wait_group 0;");
        }
        __syncthreads();

        const unsigned* ws = sm + (cc & 1) * WS_BUF;
        const unsigned* xs = sm + 2 * WS_BUF + (cc & 1) * XS_BUF;

        #pragma unroll
        for (int tap = 0; tap < 9; tap++) {
            const int kh = tap / 3, kw = tap % 3;
            unsigned a0[2], a1[2], a2[2], a3[2];
            #pragma unroll
            for (int mt = 0; mt < 2; mt++) {
                int co_r = wc * 32 + mt * 16 + grp;
                a0[mt] = ws[(tap * 8 + tig) * WS_STRIDE + co_r];
                a1[mt] = ws[(tap * 8 + tig) * WS_STRIDE + co_r + 8];
                a2[mt] = ws[(tap * 8 + tig + 4) * WS_STRIDE + co_r];
                a3[mt] = ws[(tap * 8 + tig + 4) * WS_STRIDE + co_r + 8];
            }
            #pragma unroll
            for (int nt = 0; nt < 8; nt++) {
                int col = 3 + nt * 8 + grp + kw;
                unsigned b0 = xs[(tig * 6 + wp + kh) * XR_STRIDE + col];
                unsigned b1 = xs[((tig + 4) * 6 + wp + kh) * XR_STRIDE + col];
                mma_tf32(acc[0][nt][0], acc[0][nt][1], acc[0][nt][2], acc[0][nt][3],
                         a0[0], a1[0], a2[0], a3[0], b0, b1);
                mma_tf32(acc[1][nt][0], acc[1][nt][1], acc[1][nt][2], acc[1][nt][3],
                         a0[1], a1[1], a2[1], a3[1], b0, b1);
            }
        }
        __syncthreads();
    }

    size_t ybase = (size_t)(e * Bn + b) * Cn * HWn;
    const int row = ty0 + wp;
    float ls[2] = {0.f, 0.f}, lq[2] = {0.f, 0.f};
    #pragma unroll
    for (int mt = 0; mt < 2; mt++) {
        int co = chb * 64 + wc * 32 + mt * 16 + grp;
        #pragma unroll
        for (int nt = 0; nt < 8; nt++) {
            int colx = nt * 8 + 2 * tig;
            float2 v0 = make_float2(acc[mt][nt][0], acc[mt][nt][1]);
            float2 v1 = make_float2(acc[mt][nt][2], acc[mt][nt][3]);
            *(float2*)(g_y + ybase + (size_t)co * HWn + row * 64 + colx) = v0;
            *(float2*)(g_y + ybase + (size_t)(co + 8) * HWn + row * 64 + colx) = v1;
            ls[mt] += v0.x + v0.y + v1.x + v1.y;
            lq[mt] += v0.x * v0.x + v0.y * v0.y + v1.x * v1.x + v1.y * v1.y;
        }
    }
    #pragma unroll
    for (int mt = 0; mt < 2; mt++) {
        float s = ls[mt], q = lq[mt];
        #pragma unroll
        for (int off = 16; off > 0; off >>= 1) {
            s += __shfl_xor_sync(0xFFFFFFFFu, s, off);
            q += __shfl_xor_sync(0xFFFFFFFFu, q, off);
        }
        if (lane == 0) {
            int g = chb * 4 + wc * 2 + mt;
            atomicAdd(&g_estats[((e * Bn + b) * 8 + g) * 2], s);
            atomicAdd(&g_estats[((e * Bn + b) * 8 + g) * 2 + 1], q);
        }
    }
}

// ---------------- K2: finalize expert GN coefs + router softmax ----------------
__global__ void k_router_fin(const float* __restrict__ gns, const float* __restrict__ gnb,
                             const float* __restrict__ w1, const float* __restrict__ b1,
                             const float* __restrict__ w2, const float* __restrict__ b2) {
    int tid = threadIdx.x;
    for (int i = tid; i < En * Bn * Cn; i += 256) {
        int e = i >> 11, b = (i >> 7) & 15, c = i & 127, g = c >> 4;
        float s = g_estats[((e * Bn + b) * 8 + g) * 2];
        float sq = g_estats[((e * Bn + b) * 8 + g) * 2 + 1];
        float mean = s * (1.f / 65536.f);
        float var = sq * (1.f / 65536.f) - mean * mean;
        float rstd = rsqrtf(var + 1e-5f);
        float a = rstd * gns[e * Cn + c];
        g_eca[i] = a;
        g_ecb[i] = gnb[e * Cn + c] - mean * a;
    }
    if (tid < 16) {
        int py = tid >> 2, px = tid & 3;
        float fe[32];
        float cy = (py + 0.5f) * 0.25f, cx = (px + 0.5f) * 0.25f;
        #pragma unroll
        for (int k = 0; k < 8; k++) {
            float fr = (float)(1 << k) * 3.14159265358979323846f;
            fe[k] = sinf(cy * fr);
            fe[8 + k] = cosf(cy * fr);
            fe[16 + k] = sinf(cx * fr);
            fe[24 + k] = cosf(cx * fr);
        }
        float hb[64];
        for (int j = 0; j < 64; j++) {
            float s = b1[j];
            for (int k = 0; k < 32; k++) s = fmaf(fe[k], w1[k * 64 + j], s);
            hb[j] = s / (1.f + expf(-s));
        }
        float lo[8];
        float mx = -1e30f;
        for (int ee = 0; ee < 8; ee++) {
            float s = b2[ee];
            for (int j = 0; j < 64; j++) s = fmaf(hb[j], w2[j * 8 + ee], s);
            lo[ee] = s;
            mx = fmaxf(mx, s);
        }
        float den = 0.f;
        for (int ee = 0; ee < 8; ee++) { lo[ee] = expf(lo[ee] - mx); den += lo[ee]; }
        float inv = 1.f / den;
        for (int ee = 0; ee < 8; ee++) g_wts[tid][ee] = lo[ee] * inv;
    }
}

// ---------------- K3: combine experts -> tf32 bits ----------------
__global__ void k_combine(const float* __restrict__ x) {
    size_t t = (size_t)blockIdx.x * 256 + threadIdx.x;
    size_t i = t * 4;
    int b = (int)(i >> 19);
    int c = (int)(i >> 12) & 127;
    int p = (int)(i & 4095);
    int patch = ((p >> 6) >> 4) * 4 + ((p & 63) >> 4);
    float4 outv = *(const float4*)(x + i);
    #pragma unroll
    for (int e = 0; e < 8; e++) {
        int ebc = (e * Bn + b) * Cn + c;
        float a = g_eca[ebc], bb = g_ecb[ebc];
        float wt = g_wts[patch][e];
        float4 y = *(const float4*)(g_y + (size_t)ebc * HWn + p);
        outv.x += wt * silu_f(fmaf(y.x, a, bb));
        outv.y += wt * silu_f(fmaf(y.y, a, bb));
        outv.z += wt * silu_f(fmaf(y.z, a, bb));
        outv.w += wt * silu_f(fmaf(y.w, a, bb));
    }
    uint4 o;
    o.x = to_tf32(outv.x);
    o.y = to_tf32(outv.y);
    o.z = to_tf32(outv.z);
    o.w = to_tf32(outv.w);
    *(uint4*)(g_combt + i) = o;
}

// ---------------- K4: pw1 1x1 via tf32 mma, 4-stage cp.async + gn1 stats ----------------
__global__ __launch_bounds__(256) void k_pw1m() {
    __shared__ unsigned As[4][8 * 136];
    __shared__ unsigned Bs[4][8 * 136];
    const int pxb = blockIdx.x * 128;
    const int hcb = blockIdx.y * 128;
    const int b = blockIdx.z;
    const int tid = threadIdx.x;
    const int lane = tid & 31;
    const int warp = tid >> 5;
    const int wc = warp >> 1;
    const int wpx = warp & 1;
    const int grp = lane >> 2;
    const int tig = lane & 3;

    const unsigned sa = (unsigned)__cvta_generic_to_shared(&As[0][0]);
    const unsigned sb = (unsigned)__cvta_generic_to_shared(&Bs[0][0]);

    float acc[2][8][4];
    #pragma unroll
    for (int mt = 0; mt < 2; mt++)
        #pragma unroll
        for (int nt = 0; nt < 8; nt++)
            #pragma unroll
            for (int q = 0; q < 4; q++) acc[mt][nt][q] = 0.f;

    auto stage = [&](int cc, int buf) {
        cpa16(sa + (buf * 1088 + warp * 136 + lane * 4) * 4,
              g_w1t + (size_t)((blockIdx.y * 16 + cc) * 8) * 128 + warp * 128 + lane * 4);
        cpa16(sb + (buf * 1088 + warp * 136 + lane * 4) * 4,
              g_combt + (size_t)(b * Cn + cc * 8 + warp) * HWn + pxb + lane * 4);
    };

    stage(0, 0); cp_commit();
    stage(1, 1); cp_commit();
    stage(2, 2); cp_commit();

    for (int cc = 0; cc < 16; cc++) {
        if (cc + 3 < 16) {
            stage(cc + 3, (cc + 3) & 3);
            cp_commit();
            asm volatile("cp.async.wait_group 3;");
        } else if (cc == 13) {
            asm volatile("cp.async.wait_group 2;");
        } else if (cc == 14) {
            asm volatile("cp.async.wait_group 1;");
        } else {
            asm volatile("cp.async.wait_group 0;");
        }
        __syncthreads();

        const unsigned* Ab = &As[cc & 3][0];
        const unsigned* Bb = &Bs[cc & 3][0];

        unsigned a0[2], a1[2], a2[2], a3[2];
        #pragma unroll
        for (int mt = 0; mt < 2; mt++) {
            int hc_r = wc * 32 + mt * 16 + grp;
            a0[mt] = Ab[tig * 136 + hc_r];
            a1[mt] = Ab[tig * 136 + hc_r + 8];
            a2[mt] = Ab[(tig + 4) * 136 + hc_r];
            a3[mt] = Ab[(tig + 4) * 136 + hc_r + 8];
        }
        #pragma unroll
        for (int nt = 0; nt < 8; nt++) {
            int col = wpx * 64 + nt * 8 + grp;
            unsigned b0 = Bb[tig * 136 + col];
            unsigned b1 = Bb[(tig + 4) * 136 + col];
            mma_tf32(acc[0][nt][0], acc[0][nt][1], acc[0][nt][2], acc[0][nt][3],
                     a0[0], a1[0], a2[0], a3[0], b0, b1);
            mma_tf32(acc[1][nt][0], acc[1][nt][1], acc[1][nt][2], acc[1][nt][3],
                     a0[1], a1[1], a2[1], a3[1], b0, b1);
        }
        __syncthreads();
    }

    #pragma unroll
    for (int mt = 0; mt < 2; mt++) {
        int hc0 = hcb + wc * 32 + mt * 16 + grp;
        float ls = 0.f, lq = 0.f;
        #pragma unroll
        for (int nt = 0; nt < 8; nt++) {
            int px = pxb + wpx * 64 + nt * 8 + 2 * tig;
            float2 v0 = make_float2(acc[mt][nt][0], acc[mt][nt][1]);
            float2 v1 = make_float2(acc[mt][nt][2], acc[mt][nt][3]);
            *(float2*)(g_h1 + (size_t)(b * HCn + hc0) * HWn + px) = v0;
            *(float2*)(g_h1 + (size_t)(b * HCn + hc0 + 8) * HWn + px) = v1;
            ls += v0.x + v0.y + v1.x + v1.y;
            lq += v0.x * v0.x + v0.y * v0.y + v1.x * v1.x + v1.y * v1.y;
        }
        #pragma unroll
        for (int off = 16; off > 0; off >>= 1) {
            ls += __shfl_xor_sync(0xFFFFFFFFu, ls, off);
            lq += __shfl_xor_sync(0xFFFFFFFFu, lq, off);
        }
        if (lane == 0) {
            int g = (hcb >> 6) + (wc >> 1);
            atomicAdd(&g_s1[(b * 8 + g) * 2], ls);
            atomicAdd(&g_s1[(b * 8 + g) * 2 + 1], lq);
        }
    }
}

// ---------------- K5: depthwise 3x3, one block per (hc,b), halo loaded once ----------------
__global__ __launch_bounds__(256) void k_dw(const float* __restrict__ w_dw,
                                            const float* __restrict__ gn1s,
                                            const float* __restrict__ gn1b) {
    const int hc = blockIdx.x;
    const int b = blockIdx.y;
    __shared__ float xs[66][68];
    __shared__ float sred[2];
    const int tid = threadIdx.x;
    int g1 = hc >> 6;
    float su = g_s1[(b * 8 + g1) * 2], sq = g_s1[(b * 8 + g1) * 2 + 1];
    float mean = su * (1.f / 262144.f);
    float var = sq * (1.f / 262144.f) - mean * mean;
    float rstd = rsqrtf(var + 1e-5f);
    float a = rstd * gn1s[hc];
    float bb = gn1b[hc] - mean * a;

    const float* src = g_h1 + (size_t)(b * HCn + hc) * HWn;
    for (int idx = tid; idx < 66 * 66; idx += 256) {
        int rr = idx / 66, cx = idx - rr * 66;
        int gy = rr - 1, gx = cx - 1;
        float v = 0.f;
        if ((unsigned)gy < 64u && (unsigned)gx < 64u)
            v = silu_f(fmaf(src[gy * 64 + gx], a, bb));
        xs[rr][cx] = v;
    }
    float wd[9];
    #pragma unroll
    for (int t9 = 0; t9 < 9; t9++) wd[t9] = __ldg(&w_dw[hc * 9 + t9]);
    __syncthreads();

    float lsum = 0.f, lsq = 0.f;
    float* dst = g_h2s + (size_t)(b * HCn + hc) * OHWn;
    #pragma unroll
    for (int k16 = 0; k16 < 16; k16++) {
        int idx = tid + k16 * 256;
        int row = idx >> 6, col = idx & 63;
        float sum = 0.f;
        #pragma unroll
        for (int kh = 0; kh < 3; kh++)
            #pragma unroll
            for (int kw = 0; kw < 3; kw++)
                sum = fmaf(wd[kh * 3 + kw], xs[row + kh][col + kw], sum);
        if (((row & 1) | (col & 1)) == 0)
            dst[(row >> 1) * 32 + (col >> 1)] = sum;
        lsum += sum;
        lsq += sum * sum;
    }
    #pragma unroll
    for (int off = 16; off > 0; off >>= 1) {
        lsum += __shfl_xor_sync(0xFFFFFFFFu, lsum, off);
        lsq += __shfl_xor_sync(0xFFFFFFFFu, lsq, off);
    }
    if (tid < 2) sred[tid] = 0.f;
    __syncthreads();
    if ((tid & 31) == 0) {
        atomicAdd(&sred[0], lsum);
        atomicAdd(&sred[1], lsq);
    }
    __syncthreads();
    if (tid == 0) {
        int g = hc >> 6;
        atomicAdd(&g_s2[(b * 8 + g) * 2], sred[0]);
        atomicAdd(&g_s2[(b * 8 + g) * 2 + 1], sred[1]);
    }
}

// ---------------- K6: pw2 via tf32 mma, K-split x2, gn2 inline (reg prefetch B) ----------------
__global__ __launch_bounds__(256) void k_pw2m(const float* __restrict__ gn2s,
                                              const float* __restrict__ gn2b) {
    __shared__ unsigned As[2][8 * 136];
    __shared__ unsigned Bs[2][8 * 136];
    const int pxb = blockIdx.x * 128;
    const int ky = blockIdx.y;
    const int b = blockIdx.z;
    const int tid = threadIdx.x;
    const int lane = tid & 31;
    const int warp = tid >> 5;
    const int wc = warp >> 1;
    const int wpx = warp & 1;
    const int grp = lane >> 2;
    const int tig = lane & 3;
    const int r = warp;
    const unsigned sa = (unsigned)__cvta_generic_to_shared(&As[0][0]);

    float acc[2][8][4];
    #pragma unroll
    for (int mt = 0; mt < 2; mt++)
        #pragma unroll
        for (int nt = 0; nt < 8; nt++)
            #pragma unroll
            for (int q = 0; q < 4; q++) acc[mt][nt][q] = 0.f;

    auto loadB = [&](int cc, float* breg) {
        int ch = (ky * 32 + cc) * 8 + r;
        float4 v = *(const float4*)(g_h2s + (size_t)(b * HCn + ch) * OHWn + pxb + lane * 4);
        breg[0] = v.x; breg[1] = v.y; breg[2] = v.z; breg[3] = v.w;
    };
    auto coefs = [&](int cc, float& a, float& bb) {
        int ch = (ky * 32 + cc) * 8 + r;
        int g2 = ch >> 6;
        float su = g_s2[(b * 8 + g2) * 2], sq = g_s2[(b * 8 + g2) * 2 + 1];
        float mean = su * (1.f / 262144.f);
        float var = sq * (1.f / 262144.f) - mean * mean;
        float rstd = rsqrtf(var + 1e-5f);
        a = rstd * gn2s[ch];
        bb = gn2b[ch] - mean * a;
    };
    auto stsB = [&](int buf, const float* breg, float a, float bb) {
        uint4 v;
        v.x = to_tf32(silu_f(fmaf(breg[0], a, bb)));
        v.y = to_tf32(silu_f(fmaf(breg[1], a, bb)));
        v.z = to_tf32(silu_f(fmaf(breg[2], a, bb)));
        v.w = to_tf32(silu_f(fmaf(breg[3], a, bb)));
        *(uint4*)(&Bs[buf][r * 136 + lane * 4]) = v;
    };
    auto stageA = [&](int cc, int buf) {
        cpa16(sa + (buf * 1088 + warp * 136 + lane * 4) * 4,
              g_w2t + (size_t)(ky * 32 + cc) * 1024 + warp * 128 + lane * 4);
    };

    float breg[4], brega, bregb;
    loadB(0, breg);
    coefs(0, brega, bregb);
    stageA(0, 0);
    cp_commit();
    stsB(0, breg, brega, bregb);

    for (int cc = 0; cc < 32; cc++) {
        float nreg[4], na, nb2;
        if (cc < 31) {
            loadB(cc + 1, nreg);
            coefs(cc + 1, na, nb2);
            stageA(cc + 1, (cc + 1) & 1);
            cp_commit();
            asm volatile("cp.async.wait_group 1;");
        } else {
            asm volatile("cp.async.wait_group 0;");
        }
        __syncthreads();

        const unsigned* Ab = &As[cc & 1][0];
        const unsigned* Bb = &Bs[cc & 1][0];

        unsigned a0[2], a1[2], a2[2], a3[2];
        #pragma unroll
        for (int mt = 0; mt < 2; mt++) {
            int co_r = wc * 32 + mt * 16 + grp;
            a0[mt] = Ab[tig * 136 + co_r];
            a1[mt] = Ab[tig * 136 + co_r + 8];
            a2[mt] = Ab[(tig + 4) * 136 + co_r];
            a3[mt] = Ab[(tig + 4) * 136 + co_r + 8];
        }
        #pragma unroll
        for (int nt = 0; nt < 8; nt++) {
            int col = wpx * 64 + nt * 8 + grp;
            unsigned b0 = Bb[tig * 136 + col];
            unsigned b1 = Bb[(tig + 4) * 136 + col];
            mma_tf32(acc[0][nt][0], acc[0][nt][1], acc[0][nt][2], acc[0][nt][3],
                     a0[0], a1[0], a2[0], a3[0], b0, b1);
            mma_tf32(acc[1][nt][0], acc[1][nt][1], acc[1][nt][2], acc[1][nt][3],
                     a0[1], a1[1], a2[1], a3[1], b0, b1);
        }
        __syncthreads();
        if (cc < 31) stsB((cc + 1) & 1, nreg, na, nb2);
    }

    float* po = g_po + (size_t)ky * (Bn * Cn * OHWn);
    #pragma unroll
    for (int mt = 0; mt < 2; mt++) {
        int co0 = wc * 32 + mt * 16 + grp;
        #pragma unroll
        for (int nt = 0; nt < 8; nt++) {
            int px = pxb + wpx * 64 + nt * 8 + 2 * tig;
            *(float2*)(po + (size_t)(b * Cn + co0) * OHWn + px) =
                make_float2(acc[mt][nt][0], acc[mt][nt][1]);
            *(float2*)(po + (size_t)(b * Cn + co0 + 8) * OHWn + px) =
                make_float2(acc[mt][nt][2], acc[mt][nt][3]);
        }
    }
}

// ---------------- K7: fused gn3 stats + apply + write output ----------------
// block = (b, group): 128 blocks; pass1 reduce, pass2 apply (po re-read hits L2/L1).
__global__ __launch_bounds__(256) void k_sout(float* __restrict__ out,
                                              const float* __restrict__ gn3s,
                                              const float* __restrict__ gn3b) {
    const int b = blockIdx.x;
    const int g = blockIdx.y;
    const int tid = threadIdx.x;
    __shared__ float rs[8], rq[8];
    __shared__ float smean, srstd;
    const size_t base = (size_t)(b * Cn + g * 16) * OHWn;
    float s = 0.f, q = 0.f;
    for (int i = tid; i < 16 * OHWn; i += 256) {
        float v = g_po[base + i] + g_po[(size_t)(Bn * Cn * OHWn) + base + i];
        s += v;
        q += v * v;
    }
    #pragma unroll
    for (int off = 16; off > 0; off >>= 1) {
        s += __shfl_xor_sync(0xFFFFFFFFu, s, off);
        q += __shfl_xor_sync(0xFFFFFFFFu, q, off);
    }
    if ((tid & 31) == 0) { rs[tid >> 5] = s; rq[tid >> 5] = q; }
    __syncthreads();
    if (tid == 0) {
        float ts = 0.f, tq = 0.f;
        #pragma unroll
        for (int w = 0; w < 8; w++) { ts += rs[w]; tq += rq[w]; }
        float mean = ts * (1.f / 16384.f);
        float var = tq * (1.f / 16384.f) - mean * mean;
        smean = mean;
        srstd = rsqrtf(var + 1e-5f);
    }
    __syncthreads();
    float mean = smean, rstd = srstd;
    for (int i = tid; i < 16 * OHWn; i += 256) {
        int c = g * 16 + (i >> 10);
        float a = rstd * gn3s[c];
        float bb = gn3b[c] - mean * a;
        float v = g_po[base + i] + g_po[(size_t)(Bn * Cn * OHWn) + base + i];
        out[base + i] = silu_f(fmaf(v, a, bb));
    }
}

// ---------------- launch ----------------
extern "C" void kernel_launch(void* const* d_in, const int* in_sizes, int n_in,
                              void* d_out, int out_size) {
    const float* x      = (const float*)d_in[0];
    const float* w_exp  = (const float*)d_in[1];
    const float* gns    = (const float*)d_in[2];
    const float* gnb    = (const float*)d_in[3];
    const float* w1     = (const float*)d_in[4];
    const float* b1     = (const float*)d_in[5];
    const float* w2     = (const float*)d_in[6];
    const float* b2     = (const float*)d_in[7];
    const float* w_pw1  = (const float*)d_in[8];
    const float* gn1s   = (const float*)d_in[9];
    const float* gn1b   = (const float*)d_in[10];
    const float* w_dw   = (const float*)d_in[11];
    const float* gn2s   = (const float*)d_in[12];
    const float* gn2b   = (const float*)d_in[13];
    const float* w_pw2  = (const float*)d_in[14];
    const float* gn3s   = (const float*)d_in[15];
    const float* gn3b   = (const float*)d_in[16];
    float* out = (float*)d_out;

    const int expert_smem = (2 * WS_BUF + 2 * XS_BUF) * 4;
    cudaFuncSetAttribute(k_expert, cudaFuncAttributeMaxDynamicSharedMemorySize,
                         expert_smem);

    // k_expert stays at slot 4 for the ncu window
    k_zero<<<8, 256>>>();
    k_wprep<<<(En * 16 * 9 * 8 * 128 + 255) / 256, 256>>>(w_exp);
    k_xprep<<<(Bn * Cn * HWn) / 256, 256>>>(x);
    {
        dim3 g(16, 2, En * Bn);
        k_expert<<<g, 256, expert_smem>>>();
    }
    k_w1prep<<<(4 * 16 * 8 * 128 + 255) / 256, 256>>>(w_pw1);
    k_w2prep<<<(64 * 8 * 128 + 255) / 256, 256>>>(w_pw2);
    k_router_fin<<<1, 256>>>(gns, gnb, w1, b1, w2, b2);
    k_combine<<<8192, 256>>>(x);
    {
        dim3 g(32, 4, Bn);
        k_pw1m<<<g, 256>>>();
    }
    {
        dim3 g(HCn, Bn);
        k_dw<<<g, 256>>>(w_dw, gn1s, gn1b);
    }
    {
        dim3 g(8, 2, Bn);
        k_pw2m<<<g, 256>>>(gn2s, gn2b);
    }
    {
        dim3 g(Bn, 8);
        k_sout<<<g, 256>>>(out, gn3s, gn3b);
    }
}

// round 15
// speedup vs baseline: 2.4793x; 1.0124x over previous
#include <cuda_runtime.h>
#include <math.h>

#define En 8
#define Bn 16
#define Cn 128
#define Hn 64
#define Wn 64
#define HWn 4096
#define HCn 512
#define OHWn 1024

// ---------------- scratch (device globals; no allocation) ----------------
__device__ float g_y[(size_t)En * Bn * Cn * HWn];
__device__ unsigned g_combt[(size_t)Bn * Cn * HWn];    // combined, tf32 bits
__device__ float g_h1[(size_t)Bn * HCn * HWn];
__device__ float g_h2s[(size_t)Bn * HCn * OHWn];       // dw output, even px only (32x32)
__device__ float g_po[(size_t)2 * Bn * Cn * OHWn];     // pw2 K-split partials
__device__ unsigned g_wt[(size_t)En * 16 * 9 * 8 * 128];
__device__ unsigned g_w1t[(size_t)4 * 16 * 8 * 128];
__device__ unsigned g_w2t[(size_t)64 * 8 * 128];
__device__ unsigned g_xt[(size_t)Bn * Cn * HWn];
__device__ float g_estats[En * Bn * 8 * 2];
__device__ float g_eca[En * Bn * Cn];
__device__ float g_ecb[En * Bn * Cn];
__device__ float g_wts[16][En];
__device__ float g_s1[Bn * 8 * 2];
__device__ float g_s2[Bn * 8 * 2];

__device__ __forceinline__ float silu_f(float v) { return v / (1.f + __expf(-v)); }

__device__ __forceinline__ unsigned to_tf32(float f) {
    unsigned r;
    asm("cvt.rna.tf32.f32 %0, %1;" : "=r"(r) : "f"(f));
    return r;
}

__device__ __forceinline__ void mma_tf32(float& c0, float& c1, float& c2, float& c3,
                                         unsigned a0, unsigned a1, unsigned a2, unsigned a3,
                                         unsigned b0, unsigned b1) {
    asm volatile(
        "mma.sync.aligned.m16n8k8.row.col.f32.tf32.tf32.f32 "
        "{%0,%1,%2,%3}, {%4,%5,%6,%7}, {%8,%9}, {%0,%1,%2,%3};"
        : "+f"(c0), "+f"(c1), "+f"(c2), "+f"(c3)
        : "r"(a0), "r"(a1), "r"(a2), "r"(a3), "r"(b0), "r"(b1));
}

// ---- cp.async helpers ----
__device__ __forceinline__ void cpa16(unsigned dst, const void* src) {
    asm volatile("cp.async.cg.shared.global [%0], [%1], 16;" :: "r"(dst), "l"(src));
}
__device__ __forceinline__ void cpa16z(unsigned dst, const void* src, int sz) {
    asm volatile("cp.async.cg.shared.global [%0], [%1], 16, %2;"
                 :: "r"(dst), "l"(src), "r"(sz));
}
__device__ __forceinline__ void cp_commit() {
    asm volatile("cp.async.commit_group;");
}

// ---------------- K0: zero the stats accumulators ----------------
__global__ void k_zero() {
    int i = blockIdx.x * 256 + threadIdx.x;
    if (i < En * Bn * 8 * 2) g_estats[i] = 0.f;
    if (i < Bn * 8 * 2) { g_s1[i] = 0.f; g_s2[i] = 0.f; }
}

// ---------------- W preps ----------------
__global__ void k_wprep(const float* __restrict__ w_exp) {
    int i = blockIdx.x * 256 + threadIdx.x;
    if (i >= En * 16 * 9 * 8 * 128) return;
    int co = i & 127;
    int r = i >> 7;
    int ci = r & 7; r >>= 3;
    int tap = r % 9; r /= 9;
    int cc = r & 15;
    int e = r >> 4;
    g_wt[i] = to_tf32(w_exp[((size_t)(e * 128 + co) * 128 + cc * 8 + ci) * 9 + tap]);
}
__global__ void k_w1prep(const float* __restrict__ w_pw1) {
    int i = blockIdx.x * 256 + threadIdx.x;
    if (i >= 4 * 16 * 8 * 128) return;
    int hcl = i & 127;
    int ci = (i >> 7) & 7;
    int cc = (i >> 10) & 15;
    int blk = i >> 14;
    g_w1t[i] = to_tf32(w_pw1[(size_t)(blk * 128 + hcl) * 128 + cc * 8 + ci]);
}
__global__ void k_w2prep(const float* __restrict__ w_pw2) {
    int i = blockIdx.x * 256 + threadIdx.x;
    if (i >= 64 * 8 * 128) return;
    int co = i & 127;
    int ci = (i >> 7) & 7;
    int cc = i >> 10;
    g_w2t[i] = to_tf32(w_pw2[(size_t)co * 512 + cc * 8 + ci]);
}
__global__ void k_xprep(const float* __restrict__ x) {
    int i = blockIdx.x * 256 + threadIdx.x;
    g_xt[i] = to_tf32(x[i]);
}

// ---------------- K1: expert 3x3 conv, 3-buffer single-sync pipeline ----------------
#define WS_STRIDE 72
#define WS_BUF (72 * WS_STRIDE)
#define XR_STRIDE 76
#define XS_BUF (48 * XR_STRIDE)
__global__ __launch_bounds__(256, 2) void k_expert() {
    extern __shared__ unsigned sm[];
    const int ty0 = blockIdx.x * 4;
    const int chb = blockIdx.y;
    const int e = blockIdx.z >> 4;
    const int b = blockIdx.z & 15;

    const int tid = threadIdx.x;
    const int warp = tid >> 5;
    const int lane = tid & 31;
    const int wc = warp >> 2;
    const int wp = warp & 3;
    const int grp = lane >> 2;
    const int tig = lane & 3;

    const unsigned smbase = (unsigned)__cvta_generic_to_shared(sm);

    float acc[2][8][4];
    #pragma unroll
    for (int mt = 0; mt < 2; mt++)
        #pragma unroll
        for (int nt = 0; nt < 8; nt++)
            #pragma unroll
            for (int q = 0; q < 4; q++) acc[mt][nt][q] = 0.f;

    const unsigned* wt = g_wt + (size_t)e * 147456 + chb * 64;
    const unsigned* xt = g_xt + (size_t)b * Cn * HWn;

    // zero always-OOB halo cols for all 3 X buffers: 3 x 48 rows
    if (tid < 144) {
        int buf = tid / 48;
        int r = tid - buf * 48;
        sm[3 * WS_BUF + buf * XS_BUF + r * XR_STRIDE + 3] = 0u;
        sm[3 * WS_BUF + buf * XS_BUF + r * XR_STRIDE + 68] = 0u;
    }
    __syncthreads();

    auto stage = [&](int cc, int buf) {
        const unsigned wsoff = buf * WS_BUF;
        #pragma unroll
        for (int it = 0; it < 5; it++) {
            int idx = tid + it * 256;
            if (idx < 1152) {
                int rw = idx >> 4, q = idx & 15;
                cpa16(smbase + (wsoff + rw * WS_STRIDE + q * 4) * 4,
                      wt + (size_t)cc * 9216 + rw * 128 + q * 4);
            }
        }
        const unsigned xsoff = 3 * WS_BUF + buf * XS_BUF;
        if (lane < 16) {
            const unsigned* src = xt + (size_t)(cc * 8 + warp) * HWn + (ty0 - 1) * 64 + lane * 4;
            #pragma unroll
            for (int rr = 0; rr < 6; rr++) {
                int gy = ty0 - 1 + rr;
                bool ok = (unsigned)gy < 64u;
                cpa16z(smbase + (xsoff + (warp * 6 + rr) * XR_STRIDE + 4 + lane * 4) * 4,
                       ok ? (const void*)(src + rr * 64) : (const void*)xt, ok ? 16 : 0);
            }
        }
    };

    stage(0, 0); cp_commit();
    stage(1, 1); cp_commit();

    int buf = 0;
    for (int cc = 0; cc < 16; cc++) {
        if (cc < 15) {
            asm volatile("cp.async.wait_group 1;");
        } else {
            asm volatile("cp.async.wait_group 0;");
        }
        __syncthreads();
        if (cc + 2 < 16) {
            int nb = buf + 2; if (nb >= 3) nb -= 3;
            stage(cc + 2, nb);
            cp_commit();
        }

        const unsigned* ws = sm + buf * WS_BUF;
        const unsigned* xs = sm + 3 * WS_BUF + buf * XS_BUF;

        #pragma unroll
        for (int tap = 0; tap < 9; tap++) {
            const int kh = tap / 3, kw = tap % 3;
            unsigned a0[2], a1[2], a2[2], a3[2];
            #pragma unroll
            for (int mt = 0; mt < 2; mt++) {
                int co_r = wc * 32 + mt * 16 + grp;
                a0[mt] = ws[(tap * 8 + tig) * WS_STRIDE + co_r];
                a1[mt] = ws[(tap * 8 + tig) * WS_STRIDE + co_r + 8];
                a2[mt] = ws[(tap * 8 + tig + 4) * WS_STRIDE + co_r];
                a3[mt] = ws[(tap * 8 + tig + 4) * WS_STRIDE + co_r + 8];
            }
            #pragma unroll
            for (int nt = 0; nt < 8; nt++) {
                int col = 3 + nt * 8 + grp + kw;
                unsigned b0 = xs[(tig * 6 + wp + kh) * XR_STRIDE + col];
                unsigned b1 = xs[((tig + 4) * 6 + wp + kh) * XR_STRIDE + col];
                mma_tf32(acc[0][nt][0], acc[0][nt][1], acc[0][nt][2], acc[0][nt][3],
                         a0[0], a1[0], a2[0], a3[0], b0, b1);
                mma_tf32(acc[1][nt][0], acc[1][nt][1], acc[1][nt][2], acc[1][nt][3],
                         a0[1], a1[1], a2[1], a3[1], b0, b1);
            }
        }
        buf++; if (buf >= 3) buf = 0;
    }

    size_t ybase = (size_t)(e * Bn + b) * Cn * HWn;
    const int row = ty0 + wp;
    float ls[2] = {0.f, 0.f}, lq[2] = {0.f, 0.f};
    #pragma unroll
    for (int mt = 0; mt < 2; mt++) {
        int co = chb * 64 + wc * 32 + mt * 16 + grp;
        #pragma unroll
        for (int nt = 0; nt < 8; nt++) {
            int colx = nt * 8 + 2 * tig;
            float2 v0 = make_float2(acc[mt][nt][0], acc[mt][nt][1]);
            float2 v1 = make_float2(acc[mt][nt][2], acc[mt][nt][3]);
            *(float2*)(g_y + ybase + (size_t)co * HWn + row * 64 + colx) = v0;
            *(float2*)(g_y + ybase + (size_t)(co + 8) * HWn + row * 64 + colx) = v1;
            ls[mt] += v0.x + v0.y + v1.x + v1.y;
            lq[mt] += v0.x * v0.x + v0.y * v0.y + v1.x * v1.x + v1.y * v1.y;
        }
    }
    #pragma unroll
    for (int mt = 0; mt < 2; mt++) {
        float s = ls[mt], q = lq[mt];
        #pragma unroll
        for (int off = 16; off > 0; off >>= 1) {
            s += __shfl_xor_sync(0xFFFFFFFFu, s, off);
            q += __shfl_xor_sync(0xFFFFFFFFu, q, off);
        }
        if (lane == 0) {
            int g = chb * 4 + wc * 2 + mt;
            atomicAdd(&g_estats[((e * Bn + b) * 8 + g) * 2], s);
            atomicAdd(&g_estats[((e * Bn + b) * 8 + g) * 2 + 1], q);
        }
    }
}

// ---------------- K2: finalize expert GN coefs + router softmax ----------------
__global__ void k_router_fin(const float* __restrict__ gns, const float* __restrict__ gnb,
                             const float* __restrict__ w1, const float* __restrict__ b1,
                             const float* __restrict__ w2, const float* __restrict__ b2) {
    int tid = threadIdx.x;
    for (int i = tid; i < En * Bn * Cn; i += 256) {
        int e = i >> 11, b = (i >> 7) & 15, c = i & 127, g = c >> 4;
        float s = g_estats[((e * Bn + b) * 8 + g) * 2];
        float sq = g_estats[((e * Bn + b) * 8 + g) * 2 + 1];
        float mean = s * (1.f / 65536.f);
        float var = sq * (1.f / 65536.f) - mean * mean;
        float rstd = rsqrtf(var + 1e-5f);
        float a = rstd * gns[e * Cn + c];
        g_eca[i] = a;
        g_ecb[i] = gnb[e * Cn + c] - mean * a;
    }
    if (tid < 16) {
        int py = tid >> 2, px = tid & 3;
        float fe[32];
        float cy = (py + 0.5f) * 0.25f, cx = (px + 0.5f) * 0.25f;
        #pragma unroll
        for (int k = 0; k < 8; k++) {
            float fr = (float)(1 << k) * 3.14159265358979323846f;
            fe[k] = sinf(cy * fr);
            fe[8 + k] = cosf(cy * fr);
            fe[16 + k] = sinf(cx * fr);
            fe[24 + k] = cosf(cx * fr);
        }
        float hb[64];
        for (int j = 0; j < 64; j++) {
            float s = b1[j];
            for (int k = 0; k < 32; k++) s = fmaf(fe[k], w1[k * 64 + j], s);
            hb[j] = s / (1.f + expf(-s));
        }
        float lo[8];
        float mx = -1e30f;
        for (int ee = 0; ee < 8; ee++) {
            float s = b2[ee];
            for (int j = 0; j < 64; j++) s = fmaf(hb[j], w2[j * 8 + ee], s);
            lo[ee] = s;
            mx = fmaxf(mx, s);
        }
        float den = 0.f;
        for (int ee = 0; ee < 8; ee++) { lo[ee] = expf(lo[ee] - mx); den += lo[ee]; }
        float inv = 1.f / den;
        for (int ee = 0; ee < 8; ee++) g_wts[tid][ee] = lo[ee] * inv;
    }
}

// ---------------- K3: combine experts -> tf32 bits ----------------
__global__ void k_combine(const float* __restrict__ x) {
    size_t t = (size_t)blockIdx.x * 256 + threadIdx.x;
    size_t i = t * 4;
    int b = (int)(i >> 19);
    int c = (int)(i >> 12) & 127;
    int p = (int)(i & 4095);
    int patch = ((p >> 6) >> 4) * 4 + ((p & 63) >> 4);
    float4 outv = *(const float4*)(x + i);
    #pragma unroll
    for (int e = 0; e < 8; e++) {
        int ebc = (e * Bn + b) * Cn + c;
        float a = g_eca[ebc], bb = g_ecb[ebc];
        float wt = g_wts[patch][e];
        float4 y = *(const float4*)(g_y + (size_t)ebc * HWn + p);
        outv.x += wt * silu_f(fmaf(y.x, a, bb));
        outv.y += wt * silu_f(fmaf(y.y, a, bb));
        outv.z += wt * silu_f(fmaf(y.z, a, bb));
        outv.w += wt * silu_f(fmaf(y.w, a, bb));
    }
    uint4 o;
    o.x = to_tf32(outv.x);
    o.y = to_tf32(outv.y);
    o.z = to_tf32(outv.z);
    o.w = to_tf32(outv.w);
    *(uint4*)(g_combt + i) = o;
}

// ---------------- K4: pw1 1x1 via tf32 mma, 4-buffer single-sync + gn1 stats ----------------
__global__ __launch_bounds__(256) void k_pw1m() {
    __shared__ unsigned As[4][8 * 136];
    __shared__ unsigned Bs[4][8 * 136];
    const int pxb = blockIdx.x * 128;
    const int hcb = blockIdx.y * 128;
    const int b = blockIdx.z;
    const int tid = threadIdx.x;
    const int lane = tid & 31;
    const int warp = tid >> 5;
    const int wc = warp >> 1;
    const int wpx = warp & 1;
    const int grp = lane >> 2;
    const int tig = lane & 3;

    const unsigned sa = (unsigned)__cvta_generic_to_shared(&As[0][0]);
    const unsigned sb = (unsigned)__cvta_generic_to_shared(&Bs[0][0]);

    float acc[2][8][4];
    #pragma unroll
    for (int mt = 0; mt < 2; mt++)
        #pragma unroll
        for (int nt = 0; nt < 8; nt++)
            #pragma unroll
            for (int q = 0; q < 4; q++) acc[mt][nt][q] = 0.f;

    auto stage = [&](int cc, int buf) {
        cpa16(sa + (buf * 1088 + warp * 136 + lane * 4) * 4,
              g_w1t + (size_t)((blockIdx.y * 16 + cc) * 8) * 128 + warp * 128 + lane * 4);
        cpa16(sb + (buf * 1088 + warp * 136 + lane * 4) * 4,
              g_combt + (size_t)(b * Cn + cc * 8 + warp) * HWn + pxb + lane * 4);
    };

    stage(0, 0); cp_commit();
    stage(1, 1); cp_commit();
    stage(2, 2); cp_commit();

    for (int cc = 0; cc < 16; cc++) {
        int wg = 15 - cc; if (wg > 2) wg = 2;
        if (wg == 2) asm volatile("cp.async.wait_group 2;");
        else if (wg == 1) asm volatile("cp.async.wait_group 1;");
        else asm volatile("cp.async.wait_group 0;");
        __syncthreads();
        if (cc + 3 < 16) {
            stage(cc + 3, (cc + 3) & 3);
            cp_commit();
        }

        const unsigned* Ab = &As[cc & 3][0];
        const unsigned* Bb = &Bs[cc & 3][0];

        unsigned a0[2], a1[2], a2[2], a3[2];
        #pragma unroll
        for (int mt = 0; mt < 2; mt++) {
            int hc_r = wc * 32 + mt * 16 + grp;
            a0[mt] = Ab[tig * 136 + hc_r];
            a1[mt] = Ab[tig * 136 + hc_r + 8];
            a2[mt] = Ab[(tig + 4) * 136 + hc_r];
            a3[mt] = Ab[(tig + 4) * 136 + hc_r + 8];
        }
        #pragma unroll
        for (int nt = 0; nt < 8; nt++) {
            int col = wpx * 64 + nt * 8 + grp;
            unsigned b0 = Bb[tig * 136 + col];
            unsigned b1 = Bb[(tig + 4) * 136 + col];
            mma_tf32(acc[0][nt][0], acc[0][nt][1], acc[0][nt][2], acc[0][nt][3],
                     a0[0], a1[0], a2[0], a3[0], b0, b1);
            mma_tf32(acc[1][nt][0], acc[1][nt][1], acc[1][nt][2], acc[1][nt][3],
                     a0[1], a1[1], a2[1], a3[1], b0, b1);
        }
    }

    #pragma unroll
    for (int mt = 0; mt < 2; mt++) {
        int hc0 = hcb + wc * 32 + mt * 16 + grp;
        float ls = 0.f, lq = 0.f;
        #pragma unroll
        for (int nt = 0; nt < 8; nt++) {
            int px = pxb + wpx * 64 + nt * 8 + 2 * tig;
            float2 v0 = make_float2(acc[mt][nt][0], acc[mt][nt][1]);
            float2 v1 = make_float2(acc[mt][nt][2], acc[mt][nt][3]);
            *(float2*)(g_h1 + (size_t)(b * HCn + hc0) * HWn + px) = v0;
            *(float2*)(g_h1 + (size_t)(b * HCn + hc0 + 8) * HWn + px) = v1;
            ls += v0.x + v0.y + v1.x + v1.y;
            lq += v0.x * v0.x + v0.y * v0.y + v1.x * v1.x + v1.y * v1.y;
        }
        #pragma unroll
        for (int off = 16; off > 0; off >>= 1) {
            ls += __shfl_xor_sync(0xFFFFFFFFu, ls, off);
            lq += __shfl_xor_sync(0xFFFFFFFFu, lq, off);
        }
        if (lane == 0) {
            int g = (hcb >> 6) + (wc >> 1);
            atomicAdd(&g_s1[(b * 8 + g) * 2], ls);
            atomicAdd(&g_s1[(b * 8 + g) * 2 + 1], lq);
        }
    }
}

// ---------------- K5: depthwise 3x3, one block per (hc,b), halo loaded once ----------------
__global__ __launch_bounds__(256) void k_dw(const float* __restrict__ w_dw,
                                            const float* __restrict__ gn1s,
                                            const float* __restrict__ gn1b) {
    const int hc = blockIdx.x;
    const int b = blockIdx.y;
    __shared__ float xs[66][68];
    __shared__ float sred[2];
    const int tid = threadIdx.x;
    int g1 = hc >> 6;
    float su = g_s1[(b * 8 + g1) * 2], sq = g_s1[(b * 8 + g1) * 2 + 1];
    float mean = su * (1.f / 262144.f);
    float var = sq * (1.f / 262144.f) - mean * mean;
    float rstd = rsqrtf(var + 1e-5f);
    float a = rstd * gn1s[hc];
    float bb = gn1b[hc] - mean * a;

    const float* src = g_h1 + (size_t)(b * HCn + hc) * HWn;
    for (int idx = tid; idx < 66 * 66; idx += 256) {
        int rr = idx / 66, cx = idx - rr * 66;
        int gy = rr - 1, gx = cx - 1;
        float v = 0.f;
        if ((unsigned)gy < 64u && (unsigned)gx < 64u)
            v = silu_f(fmaf(src[gy * 64 + gx], a, bb));
        xs[rr][cx] = v;
    }
    float wd[9];
    #pragma unroll
    for (int t9 = 0; t9 < 9; t9++) wd[t9] = __ldg(&w_dw[hc * 9 + t9]);
    __syncthreads();

    float lsum = 0.f, lsq = 0.f;
    float* dst = g_h2s + (size_t)(b * HCn + hc) * OHWn;
    #pragma unroll
    for (int k16 = 0; k16 < 16; k16++) {
        int idx = tid + k16 * 256;
        int row = idx >> 6, col = idx & 63;
        float sum = 0.f;
        #pragma unroll
        for (int kh = 0; kh < 3; kh++)
            #pragma unroll
            for (int kw = 0; kw < 3; kw++)
                sum = fmaf(wd[kh * 3 + kw], xs[row + kh][col + kw], sum);
        if (((row & 1) | (col & 1)) == 0)
            dst[(row >> 1) * 32 + (col >> 1)] = sum;
        lsum += sum;
        lsq += sum * sum;
    }
    #pragma unroll
    for (int off = 16; off > 0; off >>= 1) {
        lsum += __shfl_xor_sync(0xFFFFFFFFu, lsum, off);
        lsq += __shfl_xor_sync(0xFFFFFFFFu, lsq, off);
    }
    if (tid < 2) sred[tid] = 0.f;
    __syncthreads();
    if ((tid & 31) == 0) {
        atomicAdd(&sred[0], lsum);
        atomicAdd(&sred[1], lsq);
    }
    __syncthreads();
    if (tid == 0) {
        int g = hc >> 6;
        atomicAdd(&g_s2[(b * 8 + g) * 2], sred[0]);
        atomicAdd(&g_s2[(b * 8 + g) * 2 + 1], sred[1]);
    }
}

// ---------------- K6: pw2 via tf32 mma, K-split x2, gn2 inline (reg prefetch B) ----------------
__global__ __launch_bounds__(256) void k_pw2m(const float* __restrict__ gn2s,
                                              const float* __restrict__ gn2b) {
    __shared__ unsigned As[2][8 * 136];
    __shared__ unsigned Bs[2][8 * 136];
    const int pxb = blockIdx.x * 128;
    const int ky = blockIdx.y;
    const int b = blockIdx.z;
    const int tid = threadIdx.x;
    const int lane = tid & 31;
    const int warp = tid >> 5;
    const int wc = warp >> 1;
    const int wpx = warp & 1;
    const int grp = lane >> 2;
    const int tig = lane & 3;
    const int r = warp;
    const unsigned sa = (unsigned)__cvta_generic_to_shared(&As[0][0]);

    float acc[2][8][4];
    #pragma unroll
    for (int mt = 0; mt < 2; mt++)
        #pragma unroll
        for (int nt = 0; nt < 8; nt++)
            #pragma unroll
            for (int q = 0; q < 4; q++) acc[mt][nt][q] = 0.f;

    auto loadB = [&](int cc, float* breg) {
        int ch = (ky * 32 + cc) * 8 + r;
        float4 v = *(const float4*)(g_h2s + (size_t)(b * HCn + ch) * OHWn + pxb + lane * 4);
        breg[0] = v.x; breg[1] = v.y; breg[2] = v.z; breg[3] = v.w;
    };
    auto coefs = [&](int cc, float& a, float& bb) {
        int ch = (ky * 32 + cc) * 8 + r;
        int g2 = ch >> 6;
        float su = g_s2[(b * 8 + g2) * 2], sq = g_s2[(b * 8 + g2) * 2 + 1];
        float mean = su * (1.f / 262144.f);
        float var = sq * (1.f / 262144.f) - mean * mean;
        float rstd = rsqrtf(var + 1e-5f);
        a = rstd * gn2s[ch];
        bb = gn2b[ch] - mean * a;
    };
    auto stsB = [&](int buf, const float* breg, float a, float bb) {
        uint4 v;
        v.x = to_tf32(silu_f(fmaf(breg[0], a, bb)));
        v.y = to_tf32(silu_f(fmaf(breg[1], a, bb)));
        v.z = to_tf32(silu_f(fmaf(breg[2], a, bb)));
        v.w = to_tf32(silu_f(fmaf(breg[3], a, bb)));
        *(uint4*)(&Bs[buf][r * 136 + lane * 4]) = v;
    };
    auto stageA = [&](int cc, int buf) {
        cpa16(sa + (buf * 1088 + warp * 136 + lane * 4) * 4,
              g_w2t + (size_t)(ky * 32 + cc) * 1024 + warp * 128 + lane * 4);
    };

    float breg[4], brega, bregb;
    loadB(0, breg);
    coefs(0, brega, bregb);
    stageA(0, 0);
    cp_commit();
    stsB(0, breg, brega, bregb);

    for (int cc = 0; cc < 32; cc++) {
        float nreg[4], na, nb2;
        if (cc < 31) {
            loadB(cc + 1, nreg);
            coefs(cc + 1, na, nb2);
            stageA(cc + 1, (cc + 1) & 1);
            cp_commit();
            asm volatile("cp.async.wait_group 1;");
        } else {
            asm volatile("cp.async.wait_group 0;");
        }
        __syncthreads();

        const unsigned* Ab = &As[cc & 1][0];
        const unsigned* Bb = &Bs[cc & 1][0];

        unsigned a0[2], a1[2], a2[2], a3[2];
        #pragma unroll
        for (int mt = 0; mt < 2; mt++) {
            int co_r = wc * 32 + mt * 16 + grp;
            a0[mt] = Ab[tig * 136 + co_r];
            a1[mt] = Ab[tig * 136 + co_r + 8];
            a2[mt] = Ab[(tig + 4) * 136 + co_r];
            a3[mt] = Ab[(tig + 4) * 136 + co_r + 8];
        }
        #pragma unroll
        for (int nt = 0; nt < 8; nt++) {
            int col = wpx * 64 + nt * 8 + grp;
            unsigned b0 = Bb[tig * 136 + col];
            unsigned b1 = Bb[(tig + 4) * 136 + col];
            mma_tf32(acc[0][nt][0], acc[0][nt][1], acc[0][nt][2], acc[0][nt][3],
                     a0[0], a1[0], a2[0], a3[0], b0, b1);
            mma_tf32(acc[1][nt][0], acc[1][nt][1], acc[1][nt][2], acc[1][nt][3],
                     a0[1], a1[1], a2[1], a3[1], b0, b1);
        }
        __syncthreads();
        if (cc < 31) stsB((cc + 1) & 1, nreg, na, nb2);
    }

    float* po = g_po + (size_t)ky * (Bn * Cn * OHWn);
    #pragma unroll
    for (int mt = 0; mt < 2; mt++) {
        int co0 = wc * 32 + mt * 16 + grp;
        #pragma unroll
        for (int nt = 0; nt < 8; nt++) {
            int px = pxb + wpx * 64 + nt * 8 + 2 * tig;
            *(float2*)(po + (size_t)(b * Cn + co0) * OHWn + px) =
                make_float2(acc[mt][nt][0], acc[mt][nt][1]);
            *(float2*)(po + (size_t)(b * Cn + co0 + 8) * OHWn + px) =
                make_float2(acc[mt][nt][2], acc[mt][nt][3]);
        }
    }
}

// ---------------- K7: fused gn3 stats + apply + write output ----------------
__global__ __launch_bounds__(256) void k_sout(float* __restrict__ out,
                                              const float* __restrict__ gn3s,
                                              const float* __restrict__ gn3b) {
    const int b = blockIdx.x;
    const int g = blockIdx.y;
    const int tid = threadIdx.x;
    __shared__ float rs[8], rq[8];
    __shared__ float smean, srstd;
    const size_t base = (size_t)(b * Cn + g * 16) * OHWn;
    float s = 0.f, q = 0.f;
    for (int i = tid; i < 16 * OHWn; i += 256) {
        float v = g_po[base + i] + g_po[(size_t)(Bn * Cn * OHWn) + base + i];
        s += v;
        q += v * v;
    }
    #pragma unroll
    for (int off = 16; off > 0; off >>= 1) {
        s += __shfl_xor_sync(0xFFFFFFFFu, s, off);
        q += __shfl_xor_sync(0xFFFFFFFFu, q, off);
    }
    if ((tid & 31) == 0) { rs[tid >> 5] = s; rq[tid >> 5] = q; }
    __syncthreads();
    if (tid == 0) {
        float ts = 0.f, tq = 0.f;
        #pragma unroll
        for (int w = 0; w < 8; w++) { ts += rs[w]; tq += rq[w]; }
        float mean = ts * (1.f / 16384.f);
        float var = tq * (1.f / 16384.f) - mean * mean;
        smean = mean;
        srstd = rsqrtf(var + 1e-5f);
    }
    __syncthreads();
    float mean = smean, rstd = srstd;
    for (int i = tid; i < 16 * OHWn; i += 256) {
        int c = g * 16 + (i >> 10);
        float a = rstd * gn3s[c];
        float bb = gn3b[c] - mean * a;
        float v = g_po[base + i] + g_po[(size_t)(Bn * Cn * OHWn) + base + i];
        out[base + i] = silu_f(fmaf(v, a, bb));
    }
}

// ---------------- launch ----------------
extern "C" void kernel_launch(void* const* d_in, const int* in_sizes, int n_in,
                              void* d_out, int out_size) {
    const float* x      = (const float*)d_in[0];
    const float* w_exp  = (const float*)d_in[1];
    const float* gns    = (const float*)d_in[2];
    const float* gnb    = (const float*)d_in[3];
    const float* w1     = (const float*)d_in[4];
    const float* b1     = (const float*)d_in[5];
    const float* w2     = (const float*)d_in[6];
    const float* b2     = (const float*)d_in[7];
    const float* w_pw1  = (const float*)d_in[8];
    const float* gn1s   = (const float*)d_in[9];
    const float* gn1b   = (const float*)d_in[10];
    const float* w_dw   = (const float*)d_in[11];
    const float* gn2s   = (const float*)d_in[12];
    const float* gn2b   = (const float*)d_in[13];
    const float* w_pw2  = (const float*)d_in[14];
    const float* gn3s   = (const float*)d_in[15];
    const float* gn3b   = (const float*)d_in[16];
    float* out = (float*)d_out;

    const int expert_smem = (3 * WS_BUF + 3 * XS_BUF) * 4;   // 105984 B
    cudaFuncSetAttribute(k_expert, cudaFuncAttributeMaxDynamicSharedMemorySize,
                         expert_smem);

    // k_expert stays at slot 4 for the ncu window
    k_zero<<<8, 256>>>();
    k_wprep<<<(En * 16 * 9 * 8 * 128 + 255) / 256, 256>>>(w_exp);
    k_xprep<<<(Bn * Cn * HWn) / 256, 256>>>(x);
    {
        dim3 g(16, 2, En * Bn);
        k_expert<<<g, 256, expert_smem>>>();
    }
    k_w1prep<<<(4 * 16 * 8 * 128 + 255) / 256, 256>>>(w_pw1);
    k_w2prep<<<(64 * 8 * 128 + 255) / 256, 256>>>(w_pw2);
    k_router_fin<<<1, 256>>>(gns, gnb, w1, b1, w2, b2);
    k_combine<<<8192, 256>>>(x);
    {
        dim3 g(32, 4, Bn);
        k_pw1m<<<g, 256>>>();
    }
    {
        dim3 g(HCn, Bn);
        k_dw<<<g, 256>>>(w_dw, gn1s, gn1b);
    }
    {
        dim3 g(8, 2, Bn);
        k_pw2m<<<g, 256>>>(gn2s, gn2b);
    }
    {
        dim3 g(Bn, 8);
        k_sout<<<g, 256>>>(out, gn3s, gn3b);
    }
}